// round 1
// baseline (speedup 1.0000x reference)
#include <cuda_runtime.h>
#include <math.h>

// Problem constants
#define B_   16
#define C_   512
#define L_   1024
#define NH_  8
#define HD_  64
#define NG_  32
#define GCH_ 16          // channels per group = C/NG
#define M_QKV 1536
#define EPS_ 1e-5f

// Scratch (device globals; no runtime allocation)
__device__ float g_h  [(size_t)B_ * C_ * L_];      // groupnorm output  (B,C,L)
__device__ float g_qkv[(size_t)B_ * M_QKV * L_];   // qkv               (B,3C,L)
__device__ float g_at [(size_t)B_ * C_ * L_];      // attention output  (B,C,L)

// ---------------------------------------------------------------------------
// GroupNorm: one block per (batch, group); group = 16 ch x 1024 = 16384 elems
// ---------------------------------------------------------------------------
__global__ void gn_kernel(const float* __restrict__ x,
                          const float* __restrict__ w,
                          const float* __restrict__ bn)
{
    int gb  = blockIdx.x;           // 0..511
    int b   = gb >> 5;
    int grp = gb & 31;
    const float* xp = x + ((size_t)b * C_ + (size_t)grp * GCH_) * L_;
    float*       op = g_h + ((size_t)b * C_ + (size_t)grp * GCH_) * L_;

    int tid = threadIdx.x;
    float s = 0.f, s2 = 0.f;
    for (int i = tid; i < GCH_ * L_; i += 256) {
        float v = xp[i];
        s += v; s2 += v * v;
    }
    __shared__ float sh[512];
    sh[tid] = s; sh[256 + tid] = s2;
    __syncthreads();
    for (int off = 128; off > 0; off >>= 1) {
        if (tid < off) { sh[tid] += sh[tid + off]; sh[256 + tid] += sh[256 + tid + off]; }
        __syncthreads();
    }
    __shared__ float s_mean, s_inv;
    if (tid == 0) {
        float mean = sh[0] * (1.f / (GCH_ * L_));
        float var  = sh[256] * (1.f / (GCH_ * L_)) - mean * mean;
        s_mean = mean;
        s_inv  = rsqrtf(var + EPS_);
    }
    __syncthreads();
    float mean = s_mean, inv = s_inv;
    for (int i = tid; i < GCH_ * L_; i += 256) {
        int c = grp * GCH_ + (i >> 10);
        float v = (xp[i] - mean) * inv;
        op[i] = v * w[c] + bn[c];
    }
}

// ---------------------------------------------------------------------------
// Tiled SGEMM: C[b,o,l] = sum_c A[o,c]*Bm[b,c,l] + bias[o] (+ res) ;
// tile 64x64, BK=16, 256 threads, 4x4 microtile.
// ---------------------------------------------------------------------------
template <bool RES>
__device__ __forceinline__ void gemm_body(const float* __restrict__ A,
                                          const float* __restrict__ bias,
                                          const float* __restrict__ Bm,   // batch base (K x 1024)
                                          const float* __restrict__ res,  // batch base (M x 1024) or null
                                          float* __restrict__ Cm,         // batch base (M x 1024)
                                          int M, int K)
{
    __shared__ float As[16 * 68];
    __shared__ float Bs[16 * 68];

    int tid = threadIdx.x;
    int tx = tid & 15, ty = tid >> 4;
    int o0 = blockIdx.y * 64;
    int l0 = blockIdx.x * 64;

    float acc[4][4];
#pragma unroll
    for (int i = 0; i < 4; i++)
#pragma unroll
        for (int j = 0; j < 4; j++) acc[i][j] = 0.f;

    for (int c0 = 0; c0 < K; c0 += 16) {
#pragma unroll
        for (int r = 0; r < 4; r++) {
            int i2 = tid + r * 256;
            int oo = i2 >> 4, kk = i2 & 15;
            As[kk * 68 + oo] = A[(size_t)(o0 + oo) * K + c0 + kk];
            int kb = i2 >> 6, lb = i2 & 63;
            Bs[kb * 68 + lb] = Bm[(size_t)(c0 + kb) * L_ + l0 + lb];
        }
        __syncthreads();
#pragma unroll
        for (int kk = 0; kk < 16; kk++) {
            float a[4], bb[4];
#pragma unroll
            for (int i = 0; i < 4; i++) a[i] = As[kk * 68 + ty * 4 + i];
#pragma unroll
            for (int j = 0; j < 4; j++) bb[j] = Bs[kk * 68 + tx * 4 + j];
#pragma unroll
            for (int i = 0; i < 4; i++)
#pragma unroll
                for (int j = 0; j < 4; j++) acc[i][j] = fmaf(a[i], bb[j], acc[i][j]);
        }
        __syncthreads();
    }

#pragma unroll
    for (int i = 0; i < 4; i++) {
        int o = o0 + ty * 4 + i;
        float bv = bias[o];
        size_t row = (size_t)o * L_ + l0 + tx * 4;
#pragma unroll
        for (int j = 0; j < 4; j++) {
            float v = acc[i][j] + bv;
            if (RES) v += res[row + j];
            Cm[row + j] = v;
        }
    }
}

__global__ void qkv_gemm_kernel(const float* __restrict__ qkv_w,
                                const float* __restrict__ qkv_b)
{
    int b = blockIdx.z;
    gemm_body<false>(qkv_w, qkv_b,
                     g_h + (size_t)b * C_ * L_,
                     nullptr,
                     g_qkv + (size_t)b * M_QKV * L_,
                     M_QKV, C_);
}

__global__ void proj_gemm_kernel(const float* __restrict__ proj_w,
                                 const float* __restrict__ proj_b,
                                 const float* __restrict__ x,
                                 float* __restrict__ out)
{
    int b = blockIdx.z;
    gemm_body<true>(proj_w, proj_b,
                    g_at + (size_t)b * C_ * L_,
                    x   + (size_t)b * C_ * L_,
                    out + (size_t)b * C_ * L_,
                    C_, C_);
}

// ---------------------------------------------------------------------------
// Flash attention: 1 block = (batch*head, 64-query tile). 256 threads.
// Q/K/V stored as [d][l] slices of g_qkv. Online softmax, 16 K-tiles of 64.
// ---------------------------------------------------------------------------
#define ATT_SMEM_FLOATS (4 * 64 * 65 + 64 * 16 + 3 * 64)
#define ATT_SMEM_BYTES  (ATT_SMEM_FLOATS * 4)

__global__ void attn_kernel()
{
    int bh = blockIdx.y;
    int b = bh >> 3, h = bh & 7;
    int l0 = blockIdx.x * 64;

    const float* Qp = g_qkv + ((size_t)b * M_QKV + 0 * C_ + h * HD_) * L_;
    const float* Kp = g_qkv + ((size_t)b * M_QKV + 1 * C_ + h * HD_) * L_;
    const float* Vp = g_qkv + ((size_t)b * M_QKV + 2 * C_ + h * HD_) * L_;

    extern __shared__ float sm[];
    float* Qs  = sm;                 // [d][q]  64x65
    float* Ks  = Qs + 64 * 65;       // [d][k]  64x65
    float* Vt  = Ks + 64 * 65;       // [k][d]  64x65
    float* Ps  = Vt + 64 * 65;       // [q][k]  64x65
    float* red = Ps + 64 * 65;       // [q][16]
    float* m_s = red + 64 * 16;
    float* l_s = m_s + 64;
    float* a_s = l_s + 64;

    int tid = threadIdx.x;
    int tx = tid & 15, ty = tid >> 4;

    for (int idx = tid; idx < 4096; idx += 256) {
        int d = idx >> 6, q = idx & 63;
        Qs[d * 65 + q] = Qp[(size_t)d * L_ + l0 + q];
    }
    if (tid < 64) { m_s[tid] = -1e30f; l_s[tid] = 0.f; }

    float acc[4][4];
#pragma unroll
    for (int i = 0; i < 4; i++)
#pragma unroll
        for (int j = 0; j < 4; j++) acc[i][j] = 0.f;

    const float scale = 0.125f;   // 64^-0.5
    __syncthreads();

    for (int kt = 0; kt < 16; kt++) {
        int k0 = kt * 64;
        for (int idx = tid; idx < 4096; idx += 256) {
            int d = idx >> 6, k = idx & 63;
            Ks[d * 65 + k] = Kp[(size_t)d * L_ + k0 + k];
            Vt[k * 65 + d] = Vp[(size_t)d * L_ + k0 + k];
        }
        __syncthreads();

        // S = Q^T K (64q x 64k), microtile 4x4
        float s[4][4];
#pragma unroll
        for (int i = 0; i < 4; i++)
#pragma unroll
            for (int j = 0; j < 4; j++) s[i][j] = 0.f;
        for (int d = 0; d < 64; d++) {
            float a[4], bb[4];
#pragma unroll
            for (int i = 0; i < 4; i++) a[i] = Qs[d * 65 + ty * 4 + i];
#pragma unroll
            for (int j = 0; j < 4; j++) bb[j] = Ks[d * 65 + tx * 4 + j];
#pragma unroll
            for (int i = 0; i < 4; i++)
#pragma unroll
                for (int j = 0; j < 4; j++) s[i][j] = fmaf(a[i], bb[j], s[i][j]);
        }
#pragma unroll
        for (int i = 0; i < 4; i++) {
            float rm = -1e30f;
#pragma unroll
            for (int j = 0; j < 4; j++) { s[i][j] *= scale; rm = fmaxf(rm, s[i][j]); }
            red[(ty * 4 + i) * 16 + tx] = rm;
        }
        __syncthreads();
        if (tid < 64) {
            float mt = red[tid * 16];
#pragma unroll
            for (int t = 1; t < 16; t++) mt = fmaxf(mt, red[tid * 16 + t]);
            float mo = m_s[tid];
            float mn = fmaxf(mo, mt);
            float al = __expf(mo - mn);
            m_s[tid] = mn; a_s[tid] = al; l_s[tid] *= al;
        }
        __syncthreads();
#pragma unroll
        for (int i = 0; i < 4; i++) {
            int q = ty * 4 + i;
            float mq = m_s[q];
            float rs = 0.f;
#pragma unroll
            for (int j = 0; j < 4; j++) {
                float p = __expf(s[i][j] - mq);
                Ps[q * 65 + tx * 4 + j] = p;
                rs += p;
            }
            red[q * 16 + tx] = rs;
            float al = a_s[q];
#pragma unroll
            for (int j = 0; j < 4; j++) acc[i][j] *= al;
        }
        __syncthreads();
        if (tid < 64) {
            float t2 = 0.f;
#pragma unroll
            for (int t = 0; t < 16; t++) t2 += red[tid * 16 + t];
            l_s[tid] += t2;
        }
        // O += P V   (O[q][d], P[q][k], Vt[k][d])
        for (int k = 0; k < 64; k++) {
            float p[4], v[4];
#pragma unroll
            for (int i = 0; i < 4; i++) p[i] = Ps[(ty * 4 + i) * 65 + k];
#pragma unroll
            for (int j = 0; j < 4; j++) v[j] = Vt[k * 65 + tx * 4 + j];
#pragma unroll
            for (int i = 0; i < 4; i++)
#pragma unroll
                for (int j = 0; j < 4; j++) acc[i][j] = fmaf(p[i], v[j], acc[i][j]);
        }
        __syncthreads();
    }

    // write O[q][d] / l  ->  g_at[b][h*64+d][l0+q]
#pragma unroll
    for (int i = 0; i < 4; i++) {
        int q = ty * 4 + i;
        float li = 1.f / l_s[q];
#pragma unroll
        for (int j = 0; j < 4; j++) {
            int d = tx * 4 + j;
            g_at[((size_t)b * C_ + h * HD_ + d) * L_ + l0 + q] = acc[i][j] * li;
        }
    }
}

// ---------------------------------------------------------------------------
extern "C" void kernel_launch(void* const* d_in, const int* in_sizes, int n_in,
                              void* d_out, int out_size)
{
    const float* x      = (const float*)d_in[0];
    const float* norm_w = (const float*)d_in[1];
    const float* norm_b = (const float*)d_in[2];
    const float* qkv_w  = (const float*)d_in[3];
    const float* qkv_b  = (const float*)d_in[4];
    const float* proj_w = (const float*)d_in[5];
    const float* proj_b = (const float*)d_in[6];
    float* out = (float*)d_out;

    cudaFuncSetAttribute(attn_kernel,
                         cudaFuncAttributeMaxDynamicSharedMemorySize,
                         ATT_SMEM_BYTES);

    gn_kernel<<<B_ * NG_, 256>>>(x, norm_w, norm_b);

    {
        dim3 grid(L_ / 64, M_QKV / 64, B_);
        qkv_gemm_kernel<<<grid, 256>>>(qkv_w, qkv_b);
    }
    {
        dim3 grid(L_ / 64, B_ * NH_);
        attn_kernel<<<grid, 256, ATT_SMEM_BYTES>>>();
    }
    {
        dim3 grid(L_ / 64, C_ / 64, B_);
        proj_gemm_kernel<<<grid, 256>>>(proj_w, proj_b, x, out);
    }
}

// round 2
// speedup vs baseline: 1.3701x; 1.3701x over previous
#include <cuda_runtime.h>
#include <math.h>

#define B_   16
#define C_   512
#define L_   1024
#define NH_  8
#define HD_  64
#define NG_  32
#define GCH_ 16
#define M_QKV 1536
#define EPS_ 1e-5f

__device__ float g_h  [(size_t)B_ * C_ * L_];
__device__ float g_qkv[(size_t)B_ * M_QKV * L_];
__device__ float g_at [(size_t)B_ * C_ * L_];

// ---------------------------------------------------------------------------
// GroupNorm (float4 vectorized): one block per (batch, group)
// ---------------------------------------------------------------------------
__global__ void gn_kernel(const float* __restrict__ x,
                          const float* __restrict__ w,
                          const float* __restrict__ bn)
{
    int gb  = blockIdx.x;
    int b   = gb >> 5;
    int grp = gb & 31;
    const float4* xp = (const float4*)(x  + ((size_t)b * C_ + (size_t)grp * GCH_) * L_);
    float4*       op = (float4*)(g_h + ((size_t)b * C_ + (size_t)grp * GCH_) * L_);

    int tid = threadIdx.x;
    float s = 0.f, s2 = 0.f;
#pragma unroll 4
    for (int i = tid; i < GCH_ * L_ / 4; i += 256) {
        float4 v = xp[i];
        s  += v.x + v.y + v.z + v.w;
        s2 += v.x*v.x + v.y*v.y + v.z*v.z + v.w*v.w;
    }
    __shared__ float sh[512];
    sh[tid] = s; sh[256 + tid] = s2;
    __syncthreads();
    for (int off = 128; off > 0; off >>= 1) {
        if (tid < off) { sh[tid] += sh[tid + off]; sh[256 + tid] += sh[256 + tid + off]; }
        __syncthreads();
    }
    __shared__ float s_mean, s_inv;
    if (tid == 0) {
        float mean = sh[0] * (1.f / (GCH_ * L_));
        float var  = sh[256] * (1.f / (GCH_ * L_)) - mean * mean;
        s_mean = mean;
        s_inv  = rsqrtf(var + EPS_);
    }
    __syncthreads();
    float mean = s_mean, inv = s_inv;
#pragma unroll 4
    for (int i = tid; i < GCH_ * L_ / 4; i += 256) {
        int c = grp * GCH_ + (i >> 8);          // i*4 >> 10
        float wc = w[c], bc = bn[c];
        float4 v = xp[i];
        v.x = (v.x - mean) * inv * wc + bc;
        v.y = (v.y - mean) * inv * wc + bc;
        v.z = (v.z - mean) * inv * wc + bc;
        v.w = (v.w - mean) * inv * wc + bc;
        op[i] = v;
    }
}

// ---------------------------------------------------------------------------
// SGEMM 128x128 tile, BK=16, 256 threads, 8x8 microtile (2x2 blocks of 4x4)
// C[o][l] = sum_c A[o][c] * B[c][l] + bias[o] (+ res)
// ---------------------------------------------------------------------------
template <bool RES>
__device__ __forceinline__ void gemm128(const float* __restrict__ A,
                                        const float* __restrict__ bias,
                                        const float* __restrict__ Bm,
                                        const float* __restrict__ res,
                                        float* __restrict__ Cm,
                                        int K)
{
    __shared__ float As[16][132];
    __shared__ float Bs[16][132];

    int tid = threadIdx.x;
    int tx = tid & 15, ty = tid >> 4;
    int o0 = blockIdx.y * 128;
    int l0 = blockIdx.x * 128;

    float acc[2][4][2][4];
#pragma unroll
    for (int a = 0; a < 2; a++)
#pragma unroll
        for (int i = 0; i < 4; i++)
#pragma unroll
            for (int bq = 0; bq < 2; bq++)
#pragma unroll
                for (int j = 0; j < 4; j++) acc[a][i][bq][j] = 0.f;

    for (int c0 = 0; c0 < K; c0 += 16) {
#pragma unroll
        for (int r = 0; r < 2; r++) {
            int idx = tid + r * 256;                 // 0..511
            int row = idx >> 2, u = idx & 3;
            float4 av = *(const float4*)&A[(size_t)(o0 + row) * K + c0 + 4 * u];
            As[4*u+0][row] = av.x; As[4*u+1][row] = av.y;
            As[4*u+2][row] = av.z; As[4*u+3][row] = av.w;
            int kb = idx >> 5, lb = idx & 31;
            *(float4*)&Bs[kb][lb*4] =
                *(const float4*)&Bm[(size_t)(c0 + kb) * L_ + l0 + lb*4];
        }
        __syncthreads();
#pragma unroll
        for (int kk = 0; kk < 16; kk++) {
            float a[2][4], b[2][4];
            *(float4*)a[0] = *(const float4*)&As[kk][ty*4];
            *(float4*)a[1] = *(const float4*)&As[kk][64 + ty*4];
            *(float4*)b[0] = *(const float4*)&Bs[kk][tx*4];
            *(float4*)b[1] = *(const float4*)&Bs[kk][64 + tx*4];
#pragma unroll
            for (int ah = 0; ah < 2; ah++)
#pragma unroll
                for (int i = 0; i < 4; i++)
#pragma unroll
                    for (int bh = 0; bh < 2; bh++)
#pragma unroll
                        for (int j = 0; j < 4; j++)
                            acc[ah][i][bh][j] = fmaf(a[ah][i], b[bh][j], acc[ah][i][bh][j]);
        }
        __syncthreads();
    }

#pragma unroll
    for (int ah = 0; ah < 2; ah++)
#pragma unroll
        for (int i = 0; i < 4; i++) {
            int o = o0 + ah*64 + ty*4 + i;
            float bv = bias[o];
#pragma unroll
            for (int bh = 0; bh < 2; bh++) {
                size_t addr = (size_t)o * L_ + l0 + bh*64 + tx*4;
                float4 v;
                v.x = acc[ah][i][bh][0] + bv;
                v.y = acc[ah][i][bh][1] + bv;
                v.z = acc[ah][i][bh][2] + bv;
                v.w = acc[ah][i][bh][3] + bv;
                if (RES) {
                    float4 r4 = *(const float4*)&res[addr];
                    v.x += r4.x; v.y += r4.y; v.z += r4.z; v.w += r4.w;
                }
                *(float4*)&Cm[addr] = v;
            }
        }
}

__global__ __launch_bounds__(256, 2)
void qkv_gemm_kernel(const float* __restrict__ qkv_w,
                     const float* __restrict__ qkv_b)
{
    int b = blockIdx.z;
    gemm128<false>(qkv_w, qkv_b,
                   g_h + (size_t)b * C_ * L_,
                   nullptr,
                   g_qkv + (size_t)b * M_QKV * L_,
                   C_);
}

__global__ __launch_bounds__(256, 2)
void proj_gemm_kernel(const float* __restrict__ proj_w,
                      const float* __restrict__ proj_b,
                      const float* __restrict__ x,
                      float* __restrict__ out)
{
    int b = blockIdx.z;
    gemm128<true>(proj_w, proj_b,
                  g_at + (size_t)b * C_ * L_,
                  x   + (size_t)b * C_ * L_,
                  out + (size_t)b * C_ * L_,
                  C_);
}

// ---------------------------------------------------------------------------
// Flash attention: 128-query tile per block, 256 threads, 8x4 microtiles.
// Q/K/V are [d][l] slices. 16 K-tiles of 64.
// ---------------------------------------------------------------------------
#define QS_OFF  0
#define KS_OFF  (64*132)
#define VT_OFF  (KS_OFF + 64*68)
#define PS_OFF  (VT_OFF + 64*68)
#define RED_OFF (PS_OFF + 128*68)
#define MS_OFF  (RED_OFF + 128*17)
#define LS_OFF  (MS_OFF + 128)
#define AS_OFF  (LS_OFF + 128)
#define ATT_SMEM_FLOATS (AS_OFF + 128)
#define ATT_SMEM_BYTES  (ATT_SMEM_FLOATS * 4)

__global__ __launch_bounds__(256, 1)
void attn_kernel()
{
    int bh = blockIdx.y;
    int b = bh >> 3, h = bh & 7;
    int l0 = blockIdx.x * 128;

    const float* Qp = g_qkv + ((size_t)b * M_QKV + 0 * C_ + h * HD_) * L_;
    const float* Kp = g_qkv + ((size_t)b * M_QKV + 1 * C_ + h * HD_) * L_;
    const float* Vp = g_qkv + ((size_t)b * M_QKV + 2 * C_ + h * HD_) * L_;

    extern __shared__ float sm[];
    float* Qs  = sm + QS_OFF;    // [d][q] 64 x 132
    float* Ks  = sm + KS_OFF;    // [d][k] 64 x 68
    float* Vt  = sm + VT_OFF;    // [k][d] 64 x 68
    float* Ps  = sm + PS_OFF;    // [q][k] 128 x 68
    float* red = sm + RED_OFF;   // [q][16] pitch 17
    float* m_s = sm + MS_OFF;
    float* l_s = sm + LS_OFF;
    float* a_s = sm + AS_OFF;

    int tid = threadIdx.x;
    int tx = tid & 15, ty = tid >> 4;

    // load Q tile [64d][128q]
#pragma unroll
    for (int r = 0; r < 8; r++) {
        int idx = tid + r * 256;          // 0..2047 float4s
        int d = idx >> 5, qq = idx & 31;
        *(float4*)&Qs[d * 132 + qq * 4] =
            *(const float4*)&Qp[(size_t)d * L_ + l0 + qq * 4];
    }
    if (tid < 128) { m_s[tid] = -1e30f; l_s[tid] = 0.f; }

    float acc[2][4][4];
#pragma unroll
    for (int hq = 0; hq < 2; hq++)
#pragma unroll
        for (int i = 0; i < 4; i++)
#pragma unroll
            for (int j = 0; j < 4; j++) acc[hq][i][j] = 0.f;

    const float scale = 0.125f;
    __syncthreads();

    for (int kt = 0; kt < 16; kt++) {
        int k0 = kt * 64;
        // load K [d][k], V transposed -> Vt[k][d]
#pragma unroll
        for (int r = 0; r < 4; r++) {
            int idx = tid + r * 256;      // 0..1023 float4s
            int d = idx >> 4, kq = idx & 15;
            *(float4*)&Ks[d * 68 + kq * 4] =
                *(const float4*)&Kp[(size_t)d * L_ + k0 + kq * 4];
            float4 vv = *(const float4*)&Vp[(size_t)d * L_ + k0 + kq * 4];
            Vt[(kq*4+0) * 68 + d] = vv.x;
            Vt[(kq*4+1) * 68 + d] = vv.y;
            Vt[(kq*4+2) * 68 + d] = vv.z;
            Vt[(kq*4+3) * 68 + d] = vv.w;
        }
        __syncthreads();

        // S = Q^T K : [128q x 64k], thread: 8q (two halves) x 4k
        float s[2][4][4];
#pragma unroll
        for (int hq = 0; hq < 2; hq++)
#pragma unroll
            for (int i = 0; i < 4; i++)
#pragma unroll
                for (int j = 0; j < 4; j++) s[hq][i][j] = 0.f;
#pragma unroll 16
        for (int d = 0; d < 64; d++) {
            float a0[4], a1[4], bb[4];
            *(float4*)a0 = *(const float4*)&Qs[d * 132 + ty*4];
            *(float4*)a1 = *(const float4*)&Qs[d * 132 + 64 + ty*4];
            *(float4*)bb = *(const float4*)&Ks[d * 68 + tx*4];
#pragma unroll
            for (int i = 0; i < 4; i++)
#pragma unroll
                for (int j = 0; j < 4; j++) {
                    s[0][i][j] = fmaf(a0[i], bb[j], s[0][i][j]);
                    s[1][i][j] = fmaf(a1[i], bb[j], s[1][i][j]);
                }
        }
        // row max partials
#pragma unroll
        for (int hq = 0; hq < 2; hq++)
#pragma unroll
            for (int i = 0; i < 4; i++) {
                float rm = -1e30f;
#pragma unroll
                for (int j = 0; j < 4; j++) { s[hq][i][j] *= scale; rm = fmaxf(rm, s[hq][i][j]); }
                red[(hq*64 + ty*4 + i) * 17 + tx] = rm;
            }
        __syncthreads();
        if (tid < 128) {
            float mt = red[tid * 17];
#pragma unroll
            for (int t = 1; t < 16; t++) mt = fmaxf(mt, red[tid * 17 + t]);
            float mo = m_s[tid];
            float mn = fmaxf(mo, mt);
            float al = __expf(mo - mn);
            m_s[tid] = mn; a_s[tid] = al; l_s[tid] *= al;
        }
        __syncthreads();
        // P = exp(S - m), store Ps, row-sum partials, rescale acc
#pragma unroll
        for (int hq = 0; hq < 2; hq++)
#pragma unroll
            for (int i = 0; i < 4; i++) {
                int q = hq*64 + ty*4 + i;
                float mq = m_s[q], al = a_s[q];
                float4 pv;
                pv.x = __expf(s[hq][i][0] - mq);
                pv.y = __expf(s[hq][i][1] - mq);
                pv.z = __expf(s[hq][i][2] - mq);
                pv.w = __expf(s[hq][i][3] - mq);
                *(float4*)&Ps[q * 68 + tx*4] = pv;
                red[q * 17 + tx] = pv.x + pv.y + pv.z + pv.w;
#pragma unroll
                for (int j = 0; j < 4; j++) acc[hq][i][j] *= al;
            }
        __syncthreads();
        if (tid < 128) {
            float t2 = 0.f;
#pragma unroll
            for (int t = 0; t < 16; t++) t2 += red[tid * 17 + t];
            l_s[tid] += t2;
        }
        // O += P V : thread 8q x 4d
#pragma unroll 16
        for (int k = 0; k < 64; k++) {
            float p0[4], p1[4], v[4];
            *(float4*)v = *(const float4*)&Vt[k * 68 + tx*4];
#pragma unroll
            for (int i = 0; i < 4; i++) {
                p0[i] = Ps[(ty*4 + i) * 68 + k];
                p1[i] = Ps[(64 + ty*4 + i) * 68 + k];
            }
#pragma unroll
            for (int i = 0; i < 4; i++)
#pragma unroll
                for (int j = 0; j < 4; j++) {
                    acc[0][i][j] = fmaf(p0[i], v[j], acc[0][i][j]);
                    acc[1][i][j] = fmaf(p1[i], v[j], acc[1][i][j]);
                }
        }
        __syncthreads();
    }

    // epilogue: O[q][d]/l -> g_at[b][h*64+d][l0+q]  (write transposed, q contig)
    float invl[2][4];
#pragma unroll
    for (int hq = 0; hq < 2; hq++)
#pragma unroll
        for (int i = 0; i < 4; i++)
            invl[hq][i] = 1.f / l_s[hq*64 + ty*4 + i];

#pragma unroll
    for (int hq = 0; hq < 2; hq++)
#pragma unroll
        for (int j = 0; j < 4; j++) {
            int d = tx*4 + j;
            float4 v;
            v.x = acc[hq][0][j] * invl[hq][0];
            v.y = acc[hq][1][j] * invl[hq][1];
            v.z = acc[hq][2][j] * invl[hq][2];
            v.w = acc[hq][3][j] * invl[hq][3];
            *(float4*)&g_at[((size_t)b * C_ + h * HD_ + d) * L_ + l0 + hq*64 + ty*4] = v;
        }
}

// ---------------------------------------------------------------------------
extern "C" void kernel_launch(void* const* d_in, const int* in_sizes, int n_in,
                              void* d_out, int out_size)
{
    const float* x      = (const float*)d_in[0];
    const float* norm_w = (const float*)d_in[1];
    const float* norm_b = (const float*)d_in[2];
    const float* qkv_w  = (const float*)d_in[3];
    const float* qkv_b  = (const float*)d_in[4];
    const float* proj_w = (const float*)d_in[5];
    const float* proj_b = (const float*)d_in[6];
    float* out = (float*)d_out;

    cudaFuncSetAttribute(attn_kernel,
                         cudaFuncAttributeMaxDynamicSharedMemorySize,
                         ATT_SMEM_BYTES);

    gn_kernel<<<B_ * NG_, 256>>>(x, norm_w, norm_b);

    {
        dim3 grid(L_ / 128, M_QKV / 128, B_);
        qkv_gemm_kernel<<<grid, 256>>>(qkv_w, qkv_b);
    }
    {
        dim3 grid(L_ / 128, B_ * NH_);
        attn_kernel<<<grid, 256, ATT_SMEM_BYTES>>>();
    }
    {
        dim3 grid(L_ / 128, C_ / 128, B_);
        proj_gemm_kernel<<<grid, 256>>>(proj_w, proj_b, x, out);
    }
}

// round 4
// speedup vs baseline: 1.9658x; 1.4348x over previous
#include <cuda_runtime.h>
#include <math.h>
#include <stdint.h>

#define B_   16
#define C_   512
#define L_   1024
#define NH_  8
#define HD_  64
#define NG_  32
#define GCH_ 16
#define M_QKV 1536
#define EPS_ 1e-5f

// Scratch (device globals)
__device__ float g_h  [(size_t)B_ * L_ * C_];    // groupnorm out [B][L][C]
__device__ float g_qkv[(size_t)B_ * M_QKV * L_]; // qkv           [B][3C][L]
__device__ float g_at [(size_t)B_ * L_ * C_];    // attention out [B][L][C]

__device__ __forceinline__ uint32_t f2tf(float f){
    uint32_t r; asm("cvt.rna.tf32.f32 %0, %1;" : "=r"(r) : "f"(f)); return r;
}

__device__ __forceinline__ void mma_tf32(float* d, const uint32_t* a, const uint32_t* b){
    asm volatile(
        "mma.sync.aligned.m16n8k8.row.col.f32.tf32.tf32.f32 "
        "{%0,%1,%2,%3}, {%4,%5,%6,%7}, {%8,%9}, {%0,%1,%2,%3};"
        : "+f"(d[0]), "+f"(d[1]), "+f"(d[2]), "+f"(d[3])
        : "r"(a[0]), "r"(a[1]), "r"(a[2]), "r"(a[3]), "r"(b[0]), "r"(b[1]));
}

// ---------------------------------------------------------------------------
// GroupNorm: [B][C][L] in -> [B][L][C] out (smem transpose)
// ---------------------------------------------------------------------------
__global__ void gn_kernel(const float* __restrict__ x,
                          const float* __restrict__ w,
                          const float* __restrict__ bn)
{
    int gb  = blockIdx.x;
    int b   = gb >> 5;
    int grp = gb & 31;
    const float4* xp4 = (const float4*)(x + ((size_t)b * C_ + (size_t)grp * GCH_) * L_);

    int tid = threadIdx.x;
    float s = 0.f, s2 = 0.f;
#pragma unroll 4
    for (int i = tid; i < 4096; i += 256) {
        float4 v = xp4[i];
        s  += v.x + v.y + v.z + v.w;
        s2 += v.x*v.x + v.y*v.y + v.z*v.z + v.w*v.w;
    }
    __shared__ float sh[512];
    sh[tid] = s; sh[256 + tid] = s2;
    __syncthreads();
    for (int off = 128; off > 0; off >>= 1) {
        if (tid < off) { sh[tid] += sh[tid + off]; sh[256 + tid] += sh[256 + tid + off]; }
        __syncthreads();
    }
    __shared__ float s_mean, s_inv;
    if (tid == 0) {
        float mean = sh[0] * (1.f / (GCH_ * L_));
        float var  = sh[256] * (1.f / (GCH_ * L_)) - mean * mean;
        s_mean = mean;
        s_inv  = rsqrtf(var + EPS_);
    }
    __syncthreads();
    float mean = s_mean, inv = s_inv;

    __shared__ float tile[16][257];
    for (int ch = 0; ch < 4; ch++) {
        int lb = ch * 256;
#pragma unroll
        for (int t = 0; t < 4; t++) {
            int idx = tid + t * 256;         // [16c][64 l4]
            int c = idx >> 6, l4 = idx & 63;
            float4 v = xp4[c * 256 + (lb >> 2) + l4];
            float wc = w[grp * GCH_ + c], bc = bn[grp * GCH_ + c];
            tile[c][l4*4+0] = (v.x - mean) * inv * wc + bc;
            tile[c][l4*4+1] = (v.y - mean) * inv * wc + bc;
            tile[c][l4*4+2] = (v.z - mean) * inv * wc + bc;
            tile[c][l4*4+3] = (v.w - mean) * inv * wc + bc;
        }
        __syncthreads();
#pragma unroll
        for (int t = 0; t < 4; t++) {
            int idx = tid + t * 256;         // [256 l][4 cq]
            int l = idx >> 2, cq = idx & 3;
            float4 o;
            o.x = tile[cq*4+0][l]; o.y = tile[cq*4+1][l];
            o.z = tile[cq*4+2][l]; o.w = tile[cq*4+3][l];
            *(float4*)&g_h[((size_t)b * L_ + lb + l) * C_ + grp * GCH_ + cq * 4] = o;
        }
        __syncthreads();
    }
}

// ---------------------------------------------------------------------------
// tf32 mma.sync GEMM: D[o0+m][l0+n] = sum_c A[o0+m][c] * Bm[l0+n][c]
// Tile 128x128, BK=32, 256 threads = 8 warps (2 m x 4 n), 64x32 per warp.
// Smem pitch 36 floats; double-buffered; register-staged global prefetch.
// ---------------------------------------------------------------------------
#define GPITCH 36
#define GSTAGE (128 * GPITCH)            // floats per matrix per stage
#define GSMEM_BYTES (2 * 2 * GSTAGE * 4) // 2 stages x (A+B)

__device__ __forceinline__ void g_load(float4* aR, float4* bR,
                                       const float* __restrict__ A,
                                       const float* __restrict__ Bm,
                                       int o0, int l0, int c0, int tid)
{
#pragma unroll
    for (int t = 0; t < 4; t++) {
        int idx = tid + t * 256;          // 0..1023
        int row = idx >> 3, u = idx & 7;
        aR[t] = *(const float4*)&A [(size_t)(o0 + row) * C_ + c0 + u * 4];
        bR[t] = *(const float4*)&Bm[(size_t)(l0 + row) * C_ + c0 + u * 4];
    }
}

__device__ __forceinline__ void s_store(float* As, float* Bs,
                                        const float4* aR, const float4* bR, int tid)
{
#pragma unroll
    for (int t = 0; t < 4; t++) {
        int idx = tid + t * 256;
        int row = idx >> 3, u = idx & 7;
        uint4 aw, bw;
        aw.x = f2tf(aR[t].x); aw.y = f2tf(aR[t].y); aw.z = f2tf(aR[t].z); aw.w = f2tf(aR[t].w);
        bw.x = f2tf(bR[t].x); bw.y = f2tf(bR[t].y); bw.z = f2tf(bR[t].z); bw.w = f2tf(bR[t].w);
        *(uint4*)&As[row * GPITCH + u * 4] = aw;
        *(uint4*)&Bs[row * GPITCH + u * 4] = bw;
    }
}

template <bool RES>
__device__ __forceinline__ void gemm_mma(const float* __restrict__ A,
                                         const float* __restrict__ bias,
                                         const float* __restrict__ Bm,
                                         const float* __restrict__ res,
                                         float* __restrict__ Cm)
{
    extern __shared__ float sm[];
    int tid  = threadIdx.x;
    int wid  = tid >> 5, lane = tid & 31;
    int g    = lane >> 2, t4 = lane & 3;
    int wm   = wid & 1;          // 2 warps along M
    int wn   = wid >> 1;         // 4 warps along N
    int o0   = blockIdx.y * 128;
    int l0   = blockIdx.x * 128;
    int mb   = wm * 64;
    int nb   = wn * 32;

    float acc[4][4][4];
#pragma unroll
    for (int mt = 0; mt < 4; mt++)
#pragma unroll
        for (int nt = 0; nt < 4; nt++)
#pragma unroll
            for (int r = 0; r < 4; r++) acc[mt][nt][r] = 0.f;

    float4 aR[4], bR[4];
    g_load(aR, bR, A, Bm, o0, l0, 0, tid);

    for (int it = 0; it < 16; ++it) {
        float* As = sm + (it & 1) * (2 * GSTAGE);
        float* Bs = As + GSTAGE;
        s_store(As, Bs, aR, bR, tid);
        __syncthreads();
        if (it < 15) g_load(aR, bR, A, Bm, o0, l0, (it + 1) * 32, tid);

        const uint32_t* Au = (const uint32_t*)As;
        const uint32_t* Bu = (const uint32_t*)Bs;
#pragma unroll
        for (int ks = 0; ks < 4; ks++) {
            int kk = ks * 8;
            uint32_t afr[4][4], bfr[4][2];
#pragma unroll
            for (int mt = 0; mt < 4; mt++) {
                int r = mb + mt * 16 + g;
                afr[mt][0] = Au[(size_t)r * GPITCH + kk + t4];
                afr[mt][1] = Au[(size_t)(r + 8) * GPITCH + kk + t4];
                afr[mt][2] = Au[(size_t)r * GPITCH + kk + t4 + 4];
                afr[mt][3] = Au[(size_t)(r + 8) * GPITCH + kk + t4 + 4];
            }
#pragma unroll
            for (int nt = 0; nt < 4; nt++) {
                int n = nb + nt * 8 + g;
                bfr[nt][0] = Bu[(size_t)n * GPITCH + kk + t4];
                bfr[nt][1] = Bu[(size_t)n * GPITCH + kk + t4 + 4];
            }
#pragma unroll
            for (int mt = 0; mt < 4; mt++)
#pragma unroll
                for (int nt = 0; nt < 4; nt++)
                    mma_tf32(acc[mt][nt], afr[mt], bfr[nt]);
        }
        __syncthreads();
    }

    // Epilogue: c0,c1 -> row g, cols 2t4,2t4+1 ; c2,c3 -> row g+8
#pragma unroll
    for (int mt = 0; mt < 4; mt++) {
        int r0 = o0 + mb + mt * 16 + g;
        int r1 = r0 + 8;
        float bv0 = bias[r0], bv1 = bias[r1];
#pragma unroll
        for (int nt = 0; nt < 4; nt++) {
            int col = l0 + nb + nt * 8 + 2 * t4;
            size_t a0 = (size_t)r0 * L_ + col;
            size_t a1 = (size_t)r1 * L_ + col;
            float2 v0, v1;
            v0.x = acc[mt][nt][0] + bv0; v0.y = acc[mt][nt][1] + bv0;
            v1.x = acc[mt][nt][2] + bv1; v1.y = acc[mt][nt][3] + bv1;
            if (RES) {
                float2 q0 = *(const float2*)&res[a0];
                float2 q1 = *(const float2*)&res[a1];
                v0.x += q0.x; v0.y += q0.y;
                v1.x += q1.x; v1.y += q1.y;
            }
            *(float2*)&Cm[a0] = v0;
            *(float2*)&Cm[a1] = v1;
        }
    }
}

__global__ __launch_bounds__(256)
void qkv_gemm_kernel(const float* __restrict__ qkv_w,
                     const float* __restrict__ qkv_b)
{
    int b = blockIdx.z;
    gemm_mma<false>(qkv_w, qkv_b,
                    g_h + (size_t)b * L_ * C_,
                    nullptr,
                    g_qkv + (size_t)b * M_QKV * L_);
}

__global__ __launch_bounds__(256)
void proj_gemm_kernel(const float* __restrict__ proj_w,
                      const float* __restrict__ proj_b,
                      const float* __restrict__ x,
                      float* __restrict__ out)
{
    int b = blockIdx.z;
    gemm_mma<true>(proj_w, proj_b,
                   g_at + (size_t)b * L_ * C_,
                   x   + (size_t)b * C_ * L_,
                   out + (size_t)b * C_ * L_);
}

// ---------------------------------------------------------------------------
// Flash attention: 128-query tile, 256 threads, 8x4 microtiles (fp32 FFMA).
// Reads g_qkv [3C][L] slices; writes g_at [L][C].
// ---------------------------------------------------------------------------
#define QS_OFF  0
#define KS_OFF  (64*132)
#define VT_OFF  (KS_OFF + 64*68)
#define PS_OFF  (VT_OFF + 64*68)
#define RED_OFF (PS_OFF + 128*68)
#define MS_OFF  (RED_OFF + 128*17)
#define LS_OFF  (MS_OFF + 128)
#define AS_OFF  (LS_OFF + 128)
#define ATT_SMEM_FLOATS (AS_OFF + 128)
#define ATT_SMEM_BYTES  (ATT_SMEM_FLOATS * 4)

__global__ __launch_bounds__(256, 1)
void attn_kernel()
{
    int bh = blockIdx.y;
    int b = bh >> 3, h = bh & 7;
    int l0 = blockIdx.x * 128;

    const float* Qp = g_qkv + ((size_t)b * M_QKV + 0 * C_ + h * HD_) * L_;
    const float* Kp = g_qkv + ((size_t)b * M_QKV + 1 * C_ + h * HD_) * L_;
    const float* Vp = g_qkv + ((size_t)b * M_QKV + 2 * C_ + h * HD_) * L_;

    extern __shared__ float smf[];
    float* Qs  = smf + QS_OFF;
    float* Ks  = smf + KS_OFF;
    float* Vt  = smf + VT_OFF;
    float* Ps  = smf + PS_OFF;
    float* red = smf + RED_OFF;
    float* m_s = smf + MS_OFF;
    float* l_s = smf + LS_OFF;
    float* a_s = smf + AS_OFF;

    int tid = threadIdx.x;
    int tx = tid & 15, ty = tid >> 4;

#pragma unroll
    for (int r = 0; r < 8; r++) {
        int idx = tid + r * 256;
        int d = idx >> 5, qq = idx & 31;
        *(float4*)&Qs[d * 132 + qq * 4] =
            *(const float4*)&Qp[(size_t)d * L_ + l0 + qq * 4];
    }
    if (tid < 128) { m_s[tid] = -1e30f; l_s[tid] = 0.f; }

    float acc[2][4][4];
#pragma unroll
    for (int hq = 0; hq < 2; hq++)
#pragma unroll
        for (int i = 0; i < 4; i++)
#pragma unroll
            for (int j = 0; j < 4; j++) acc[hq][i][j] = 0.f;

    const float scale = 0.125f;
    __syncthreads();

    for (int kt = 0; kt < 16; kt++) {
        int k0 = kt * 64;
#pragma unroll
        for (int r = 0; r < 4; r++) {
            int idx = tid + r * 256;
            int d = idx >> 4, kq = idx & 15;
            *(float4*)&Ks[d * 68 + kq * 4] =
                *(const float4*)&Kp[(size_t)d * L_ + k0 + kq * 4];
            float4 vv = *(const float4*)&Vp[(size_t)d * L_ + k0 + kq * 4];
            Vt[(kq*4+0) * 68 + d] = vv.x;
            Vt[(kq*4+1) * 68 + d] = vv.y;
            Vt[(kq*4+2) * 68 + d] = vv.z;
            Vt[(kq*4+3) * 68 + d] = vv.w;
        }
        __syncthreads();

        float s[2][4][4];
#pragma unroll
        for (int hq = 0; hq < 2; hq++)
#pragma unroll
            for (int i = 0; i < 4; i++)
#pragma unroll
                for (int j = 0; j < 4; j++) s[hq][i][j] = 0.f;
#pragma unroll 16
        for (int d = 0; d < 64; d++) {
            float a0[4], a1[4], bb[4];
            *(float4*)a0 = *(const float4*)&Qs[d * 132 + ty*4];
            *(float4*)a1 = *(const float4*)&Qs[d * 132 + 64 + ty*4];
            *(float4*)bb = *(const float4*)&Ks[d * 68 + tx*4];
#pragma unroll
            for (int i = 0; i < 4; i++)
#pragma unroll
                for (int j = 0; j < 4; j++) {
                    s[0][i][j] = fmaf(a0[i], bb[j], s[0][i][j]);
                    s[1][i][j] = fmaf(a1[i], bb[j], s[1][i][j]);
                }
        }
#pragma unroll
        for (int hq = 0; hq < 2; hq++)
#pragma unroll
            for (int i = 0; i < 4; i++) {
                float rm = -1e30f;
#pragma unroll
                for (int j = 0; j < 4; j++) { s[hq][i][j] *= scale; rm = fmaxf(rm, s[hq][i][j]); }
                red[(hq*64 + ty*4 + i) * 17 + tx] = rm;
            }
        __syncthreads();
        if (tid < 128) {
            float mt = red[tid * 17];
#pragma unroll
            for (int t = 1; t < 16; t++) mt = fmaxf(mt, red[tid * 17 + t]);
            float mo = m_s[tid];
            float mn = fmaxf(mo, mt);
            float al = __expf(mo - mn);
            m_s[tid] = mn; a_s[tid] = al; l_s[tid] *= al;
        }
        __syncthreads();
#pragma unroll
        for (int hq = 0; hq < 2; hq++)
#pragma unroll
            for (int i = 0; i < 4; i++) {
                int q = hq*64 + ty*4 + i;
                float mq = m_s[q], al = a_s[q];
                float4 pv;
                pv.x = __expf(s[hq][i][0] - mq);
                pv.y = __expf(s[hq][i][1] - mq);
                pv.z = __expf(s[hq][i][2] - mq);
                pv.w = __expf(s[hq][i][3] - mq);
                *(float4*)&Ps[q * 68 + tx*4] = pv;
                red[q * 17 + tx] = pv.x + pv.y + pv.z + pv.w;
#pragma unroll
                for (int j = 0; j < 4; j++) acc[hq][i][j] *= al;
            }
        __syncthreads();
        if (tid < 128) {
            float t2 = 0.f;
#pragma unroll
            for (int t = 0; t < 16; t++) t2 += red[tid * 17 + t];
            l_s[tid] += t2;
        }
#pragma unroll 16
        for (int k = 0; k < 64; k++) {
            float p0[4], p1[4], v[4];
            *(float4*)v = *(const float4*)&Vt[k * 68 + tx*4];
#pragma unroll
            for (int i = 0; i < 4; i++) {
                p0[i] = Ps[(ty*4 + i) * 68 + k];
                p1[i] = Ps[(64 + ty*4 + i) * 68 + k];
            }
#pragma unroll
            for (int i = 0; i < 4; i++)
#pragma unroll
                for (int j = 0; j < 4; j++) {
                    acc[0][i][j] = fmaf(p0[i], v[j], acc[0][i][j]);
                    acc[1][i][j] = fmaf(p1[i], v[j], acc[1][i][j]);
                }
        }
        __syncthreads();
    }

    // epilogue: O[q][d]/l -> g_at[b][l0+q][h*64+d]  (d contiguous, float4)
    float invl[2][4];
#pragma unroll
    for (int hq = 0; hq < 2; hq++)
#pragma unroll
        for (int i = 0; i < 4; i++)
            invl[hq][i] = 1.f / l_s[hq*64 + ty*4 + i];

#pragma unroll
    for (int hq = 0; hq < 2; hq++)
#pragma unroll
        for (int i = 0; i < 4; i++) {
            int q = hq*64 + ty*4 + i;
            float li = invl[hq][i];
            float4 v;
            v.x = acc[hq][i][0] * li;
            v.y = acc[hq][i][1] * li;
            v.z = acc[hq][i][2] * li;
            v.w = acc[hq][i][3] * li;
            *(float4*)&g_at[((size_t)b * L_ + l0 + q) * C_ + h * HD_ + tx * 4] = v;
        }
}

// ---------------------------------------------------------------------------
extern "C" void kernel_launch(void* const* d_in, const int* in_sizes, int n_in,
                              void* d_out, int out_size)
{
    const float* x      = (const float*)d_in[0];
    const float* norm_w = (const float*)d_in[1];
    const float* norm_b = (const float*)d_in[2];
    const float* qkv_w  = (const float*)d_in[3];
    const float* qkv_b  = (const float*)d_in[4];
    const float* proj_w = (const float*)d_in[5];
    const float* proj_b = (const float*)d_in[6];
    float* out = (float*)d_out;

    cudaFuncSetAttribute(attn_kernel,
                         cudaFuncAttributeMaxDynamicSharedMemorySize, ATT_SMEM_BYTES);
    cudaFuncSetAttribute(qkv_gemm_kernel,
                         cudaFuncAttributeMaxDynamicSharedMemorySize, GSMEM_BYTES);
    cudaFuncSetAttribute(proj_gemm_kernel,
                         cudaFuncAttributeMaxDynamicSharedMemorySize, GSMEM_BYTES);

    gn_kernel<<<B_ * NG_, 256>>>(x, norm_w, norm_b);

    {
        dim3 grid(L_ / 128, M_QKV / 128, B_);
        qkv_gemm_kernel<<<grid, 256, GSMEM_BYTES>>>(qkv_w, qkv_b);
    }
    {
        dim3 grid(L_ / 128, B_ * NH_);
        attn_kernel<<<grid, 256, ATT_SMEM_BYTES>>>();
    }
    {
        dim3 grid(L_ / 128, C_ / 128, B_);
        proj_gemm_kernel<<<grid, 256, GSMEM_BYTES>>>(proj_w, proj_b, x, out);
    }
}

// round 5
// speedup vs baseline: 3.7315x; 1.8982x over previous
#include <cuda_runtime.h>
#include <math.h>
#include <stdint.h>

#define B_   16
#define C_   512
#define L_   1024
#define NH_  8
#define HD_  64
#define NG_  32
#define GCH_ 16
#define M_QKV 1536
#define EPS_ 1e-5f

// Scratch (device globals)
__device__ float g_h  [(size_t)B_ * L_ * C_];    // groupnorm out [B][L][C]
__device__ float g_qkv[(size_t)B_ * M_QKV * L_]; // qkv           [B][3C][L]
__device__ float g_at [(size_t)B_ * L_ * C_];    // attention out [B][L][C]

__device__ __forceinline__ uint32_t f2tf(float f){
    uint32_t r; asm("cvt.rna.tf32.f32 %0, %1;" : "=r"(r) : "f"(f)); return r;
}
__device__ __forceinline__ float ex2f(float x){
    float r; asm("ex2.approx.ftz.f32 %0, %1;" : "=f"(r) : "f"(x)); return r;
}

__device__ __forceinline__ void mma_tf32(float* d, const uint32_t* a, const uint32_t* b){
    asm volatile(
        "mma.sync.aligned.m16n8k8.row.col.f32.tf32.tf32.f32 "
        "{%0,%1,%2,%3}, {%4,%5,%6,%7}, {%8,%9}, {%0,%1,%2,%3};"
        : "+f"(d[0]), "+f"(d[1]), "+f"(d[2]), "+f"(d[3])
        : "r"(a[0]), "r"(a[1]), "r"(a[2]), "r"(a[3]), "r"(b[0]), "r"(b[1]));
}

// ---------------------------------------------------------------------------
// GroupNorm: [B][C][L] in -> [B][L][C] out (smem transpose)
// ---------------------------------------------------------------------------
__global__ void gn_kernel(const float* __restrict__ x,
                          const float* __restrict__ w,
                          const float* __restrict__ bn)
{
    int gb  = blockIdx.x;
    int b   = gb >> 5;
    int grp = gb & 31;
    const float4* xp4 = (const float4*)(x + ((size_t)b * C_ + (size_t)grp * GCH_) * L_);

    int tid = threadIdx.x;
    float s = 0.f, s2 = 0.f;
#pragma unroll 4
    for (int i = tid; i < 4096; i += 256) {
        float4 v = xp4[i];
        s  += v.x + v.y + v.z + v.w;
        s2 += v.x*v.x + v.y*v.y + v.z*v.z + v.w*v.w;
    }
    __shared__ float sh[512];
    sh[tid] = s; sh[256 + tid] = s2;
    __syncthreads();
    for (int off = 128; off > 0; off >>= 1) {
        if (tid < off) { sh[tid] += sh[tid + off]; sh[256 + tid] += sh[256 + tid + off]; }
        __syncthreads();
    }
    __shared__ float s_mean, s_inv;
    if (tid == 0) {
        float mean = sh[0] * (1.f / (GCH_ * L_));
        float var  = sh[256] * (1.f / (GCH_ * L_)) - mean * mean;
        s_mean = mean;
        s_inv  = rsqrtf(var + EPS_);
    }
    __syncthreads();
    float mean = s_mean, inv = s_inv;

    __shared__ float tile[16][257];
    for (int ch = 0; ch < 4; ch++) {
        int lb = ch * 256;
#pragma unroll
        for (int t = 0; t < 4; t++) {
            int idx = tid + t * 256;
            int c = idx >> 6, l4 = idx & 63;
            float4 v = xp4[c * 256 + (lb >> 2) + l4];
            float wc = w[grp * GCH_ + c], bc = bn[grp * GCH_ + c];
            tile[c][l4*4+0] = (v.x - mean) * inv * wc + bc;
            tile[c][l4*4+1] = (v.y - mean) * inv * wc + bc;
            tile[c][l4*4+2] = (v.z - mean) * inv * wc + bc;
            tile[c][l4*4+3] = (v.w - mean) * inv * wc + bc;
        }
        __syncthreads();
#pragma unroll
        for (int t = 0; t < 4; t++) {
            int idx = tid + t * 256;
            int l = idx >> 2, cq = idx & 3;
            float4 o;
            o.x = tile[cq*4+0][l]; o.y = tile[cq*4+1][l];
            o.z = tile[cq*4+2][l]; o.w = tile[cq*4+3][l];
            *(float4*)&g_h[((size_t)b * L_ + lb + l) * C_ + grp * GCH_ + cq * 4] = o;
        }
        __syncthreads();
    }
}

// ---------------------------------------------------------------------------
// tf32 mma.sync GEMM: D[o0+m][l0+n] = sum_c A[o0+m][c] * Bm[l0+n][c]
// ---------------------------------------------------------------------------
#define GPITCH 36
#define GSTAGE (128 * GPITCH)
#define GSMEM_BYTES (2 * 2 * GSTAGE * 4)

__device__ __forceinline__ void g_load(float4* aR, float4* bR,
                                       const float* __restrict__ A,
                                       const float* __restrict__ Bm,
                                       int o0, int l0, int c0, int tid)
{
#pragma unroll
    for (int t = 0; t < 4; t++) {
        int idx = tid + t * 256;
        int row = idx >> 3, u = idx & 7;
        aR[t] = *(const float4*)&A [(size_t)(o0 + row) * C_ + c0 + u * 4];
        bR[t] = *(const float4*)&Bm[(size_t)(l0 + row) * C_ + c0 + u * 4];
    }
}

__device__ __forceinline__ void s_store(float* As, float* Bs,
                                        const float4* aR, const float4* bR, int tid)
{
#pragma unroll
    for (int t = 0; t < 4; t++) {
        int idx = tid + t * 256;
        int row = idx >> 3, u = idx & 7;
        uint4 aw, bw;
        aw.x = f2tf(aR[t].x); aw.y = f2tf(aR[t].y); aw.z = f2tf(aR[t].z); aw.w = f2tf(aR[t].w);
        bw.x = f2tf(bR[t].x); bw.y = f2tf(bR[t].y); bw.z = f2tf(bR[t].z); bw.w = f2tf(bR[t].w);
        *(uint4*)&As[row * GPITCH + u * 4] = aw;
        *(uint4*)&Bs[row * GPITCH + u * 4] = bw;
    }
}

template <bool RES>
__device__ __forceinline__ void gemm_mma(const float* __restrict__ A,
                                         const float* __restrict__ bias,
                                         const float* __restrict__ Bm,
                                         const float* __restrict__ res,
                                         float* __restrict__ Cm)
{
    extern __shared__ float sm[];
    int tid  = threadIdx.x;
    int wid  = tid >> 5, lane = tid & 31;
    int g    = lane >> 2, t4 = lane & 3;
    int wm   = wid & 1;
    int wn   = wid >> 1;
    int o0   = blockIdx.y * 128;
    int l0   = blockIdx.x * 128;
    int mb   = wm * 64;
    int nb   = wn * 32;

    float acc[4][4][4];
#pragma unroll
    for (int mt = 0; mt < 4; mt++)
#pragma unroll
        for (int nt = 0; nt < 4; nt++)
#pragma unroll
            for (int r = 0; r < 4; r++) acc[mt][nt][r] = 0.f;

    float4 aR[4], bR[4];
    g_load(aR, bR, A, Bm, o0, l0, 0, tid);

    for (int it = 0; it < 16; ++it) {
        float* As = sm + (it & 1) * (2 * GSTAGE);
        float* Bs = As + GSTAGE;
        s_store(As, Bs, aR, bR, tid);
        __syncthreads();
        if (it < 15) g_load(aR, bR, A, Bm, o0, l0, (it + 1) * 32, tid);

        const uint32_t* Au = (const uint32_t*)As;
        const uint32_t* Bu = (const uint32_t*)Bs;
#pragma unroll
        for (int ks = 0; ks < 4; ks++) {
            int kk = ks * 8;
            uint32_t afr[4][4], bfr[4][2];
#pragma unroll
            for (int mt = 0; mt < 4; mt++) {
                int r = mb + mt * 16 + g;
                afr[mt][0] = Au[(size_t)r * GPITCH + kk + t4];
                afr[mt][1] = Au[(size_t)(r + 8) * GPITCH + kk + t4];
                afr[mt][2] = Au[(size_t)r * GPITCH + kk + t4 + 4];
                afr[mt][3] = Au[(size_t)(r + 8) * GPITCH + kk + t4 + 4];
            }
#pragma unroll
            for (int nt = 0; nt < 4; nt++) {
                int n = nb + nt * 8 + g;
                bfr[nt][0] = Bu[(size_t)n * GPITCH + kk + t4];
                bfr[nt][1] = Bu[(size_t)n * GPITCH + kk + t4 + 4];
            }
#pragma unroll
            for (int mt = 0; mt < 4; mt++)
#pragma unroll
                for (int nt = 0; nt < 4; nt++)
                    mma_tf32(acc[mt][nt], afr[mt], bfr[nt]);
        }
        __syncthreads();
    }

#pragma unroll
    for (int mt = 0; mt < 4; mt++) {
        int r0 = o0 + mb + mt * 16 + g;
        int r1 = r0 + 8;
        float bv0 = bias[r0], bv1 = bias[r1];
#pragma unroll
        for (int nt = 0; nt < 4; nt++) {
            int col = l0 + nb + nt * 8 + 2 * t4;
            size_t a0 = (size_t)r0 * L_ + col;
            size_t a1 = (size_t)r1 * L_ + col;
            float2 v0, v1;
            v0.x = acc[mt][nt][0] + bv0; v0.y = acc[mt][nt][1] + bv0;
            v1.x = acc[mt][nt][2] + bv1; v1.y = acc[mt][nt][3] + bv1;
            if (RES) {
                float2 q0 = *(const float2*)&res[a0];
                float2 q1 = *(const float2*)&res[a1];
                v0.x += q0.x; v0.y += q0.y;
                v1.x += q1.x; v1.y += q1.y;
            }
            *(float2*)&Cm[a0] = v0;
            *(float2*)&Cm[a1] = v1;
        }
    }
}

__global__ __launch_bounds__(256)
void qkv_gemm_kernel(const float* __restrict__ qkv_w,
                     const float* __restrict__ qkv_b)
{
    int b = blockIdx.z;
    gemm_mma<false>(qkv_w, qkv_b,
                    g_h + (size_t)b * L_ * C_,
                    nullptr,
                    g_qkv + (size_t)b * M_QKV * L_);
}

__global__ __launch_bounds__(256)
void proj_gemm_kernel(const float* __restrict__ proj_w,
                      const float* __restrict__ proj_b,
                      const float* __restrict__ x,
                      float* __restrict__ out)
{
    int b = blockIdx.z;
    gemm_mma<true>(proj_w, proj_b,
                   g_at + (size_t)b * L_ * C_,
                   x   + (size_t)b * C_ * L_,
                   out + (size_t)b * C_ * L_);
}

// ---------------------------------------------------------------------------
// Tensor-core flash attention (no-max single-pass softmax).
// Block = (b, h, 128-q tile). 256 threads = 8 warps; warp w owns q rows
// [w*16, w*16+16). K-tiles of 64. All mma.sync.m16n8k8 tf32.
// Smem: Qs[128][68] (q,d; pre-scaled by 0.125*log2e), Ks[64][68] (k,d),
//       Vs[64][68] (d,k), Ps[128][68] (q,k; warp-private strips).
// ---------------------------------------------------------------------------
#define AP 68
#define AQS 0
#define AKS (AQS + 128*AP)
#define AVS (AKS + 64*AP)
#define APS (AVS + 64*AP)
#define ATT2_FLOATS (APS + 128*AP)
#define ATT2_BYTES  (ATT2_FLOATS * 4)

__global__ __launch_bounds__(256, 2)
void attn_kernel()
{
    int bh = blockIdx.y;
    int b = bh >> 3, h = bh & 7;
    int l0 = blockIdx.x * 128;

    const float* Qp = g_qkv + ((size_t)b * M_QKV + 0 * C_ + h * HD_) * L_;
    const float* Kp = g_qkv + ((size_t)b * M_QKV + 1 * C_ + h * HD_) * L_;
    const float* Vp = g_qkv + ((size_t)b * M_QKV + 2 * C_ + h * HD_) * L_;

    extern __shared__ float smf[];
    uint32_t* Qu = (uint32_t*)(smf + AQS);
    uint32_t* Ku = (uint32_t*)(smf + AKS);
    uint32_t* Vu = (uint32_t*)(smf + AVS);
    uint32_t* Pu = (uint32_t*)(smf + APS);

    int tid  = threadIdx.x;
    int lane = tid & 31, wp = tid >> 5;
    int g = lane >> 2, t4 = lane & 3;
    int qb = wp * 16;

    const float SC = 0.125f * 1.44269504088896340736f;  // scale * log2(e)

    // ---- load Q (strided along d, coalesced along l), scaled, transposed ----
    {
        int qq = lane + 32 * (wp & 3);        // 0..127
        int d0 = (wp >> 2) * 4;               // 0 or 4
#pragma unroll
        for (int r = 0; r < 8; r++) {
            int d = d0 + 8 * r;
            uint4 wv;
            wv.x = f2tf(Qp[(size_t)(d+0) * L_ + l0 + qq] * SC);
            wv.y = f2tf(Qp[(size_t)(d+1) * L_ + l0 + qq] * SC);
            wv.z = f2tf(Qp[(size_t)(d+2) * L_ + l0 + qq] * SC);
            wv.w = f2tf(Qp[(size_t)(d+3) * L_ + l0 + qq] * SC);
            *(uint4*)&Qu[qq * AP + d] = wv;
        }
    }

    float oacc[8][4];
#pragma unroll
    for (int nt = 0; nt < 8; nt++)
#pragma unroll
        for (int r = 0; r < 4; r++) oacc[nt][r] = 0.f;
    float rsum0 = 0.f, rsum1 = 0.f;

    for (int kt = 0; kt < 16; kt++) {
        int k0 = kt * 64;
        // ---- K tile transposed: Ks[k][d] ----
        {
            int kk2 = lane + 32 * (wp & 1);   // 0..63
            int d0 = (wp >> 1) * 4;           // 0,4,8,12
#pragma unroll
            for (int r = 0; r < 4; r++) {
                int d = d0 + 16 * r;
                uint4 wv;
                wv.x = f2tf(Kp[(size_t)(d+0) * L_ + k0 + kk2]);
                wv.y = f2tf(Kp[(size_t)(d+1) * L_ + k0 + kk2]);
                wv.z = f2tf(Kp[(size_t)(d+2) * L_ + k0 + kk2]);
                wv.w = f2tf(Kp[(size_t)(d+3) * L_ + k0 + kk2]);
                *(uint4*)&Ku[kk2 * AP + d] = wv;
            }
        }
        // ---- V tile direct: Vs[d][k] ----
#pragma unroll
        for (int r = 0; r < 4; r++) {
            int idx = tid + r * 256;          // 0..1023
            int d = idx >> 4, k4 = idx & 15;
            float4 vv = *(const float4*)&Vp[(size_t)d * L_ + k0 + k4 * 4];
            uint4 wv;
            wv.x = f2tf(vv.x); wv.y = f2tf(vv.y); wv.z = f2tf(vv.z); wv.w = f2tf(vv.w);
            *(uint4*)&Vu[d * AP + k4 * 4] = wv;
        }
        __syncthreads();

        // ---- S = Q K^T : 16q x 64k per warp ----
        float sacc[8][4];
#pragma unroll
        for (int nt = 0; nt < 8; nt++)
#pragma unroll
            for (int r = 0; r < 4; r++) sacc[nt][r] = 0.f;
#pragma unroll
        for (int kc = 0; kc < 8; kc++) {
            uint32_t af[4];
            af[0] = Qu[(qb + g)     * AP + kc*8 + t4];
            af[1] = Qu[(qb + g + 8) * AP + kc*8 + t4];
            af[2] = Qu[(qb + g)     * AP + kc*8 + t4 + 4];
            af[3] = Qu[(qb + g + 8) * AP + kc*8 + t4 + 4];
#pragma unroll
            for (int nt = 0; nt < 8; nt++) {
                uint32_t bf[2];
                bf[0] = Ku[(nt*8 + g) * AP + kc*8 + t4];
                bf[1] = Ku[(nt*8 + g) * AP + kc*8 + t4 + 4];
                mma_tf32(sacc[nt], af, bf);
            }
        }

        // ---- P = exp2(S'), row sums, store P (warp-private strip) ----
#pragma unroll
        for (int nt = 0; nt < 8; nt++) {
            float p0 = ex2f(sacc[nt][0]);
            float p1 = ex2f(sacc[nt][1]);
            float p2 = ex2f(sacc[nt][2]);
            float p3 = ex2f(sacc[nt][3]);
            rsum0 += p0 + p1;
            rsum1 += p2 + p3;
            uint2 w0, w1;
            w0.x = f2tf(p0); w0.y = f2tf(p1);
            w1.x = f2tf(p2); w1.y = f2tf(p3);
            *(uint2*)&Pu[(qb + g)     * AP + nt*8 + 2*t4] = w0;
            *(uint2*)&Pu[(qb + g + 8) * AP + nt*8 + 2*t4] = w1;
        }
        __syncwarp();

        // ---- O += P V : 16q x 64d per warp ----
#pragma unroll
        for (int kc = 0; kc < 8; kc++) {
            uint32_t af[4];
            af[0] = Pu[(qb + g)     * AP + kc*8 + t4];
            af[1] = Pu[(qb + g + 8) * AP + kc*8 + t4];
            af[2] = Pu[(qb + g)     * AP + kc*8 + t4 + 4];
            af[3] = Pu[(qb + g + 8) * AP + kc*8 + t4 + 4];
#pragma unroll
            for (int nt = 0; nt < 8; nt++) {
                uint32_t bf[2];
                bf[0] = Vu[(nt*8 + g) * AP + kc*8 + t4];
                bf[1] = Vu[(nt*8 + g) * AP + kc*8 + t4 + 4];
                mma_tf32(oacc[nt], af, bf);
            }
        }
        __syncthreads();
    }

    // ---- finalize: quad-reduce row sums, normalize, write [L][C] ----
    rsum0 += __shfl_xor_sync(0xFFFFFFFFu, rsum0, 1);
    rsum0 += __shfl_xor_sync(0xFFFFFFFFu, rsum0, 2);
    rsum1 += __shfl_xor_sync(0xFFFFFFFFu, rsum1, 1);
    rsum1 += __shfl_xor_sync(0xFFFFFFFFu, rsum1, 2);
    float inv0 = 1.f / rsum0;
    float inv1 = 1.f / rsum1;

    size_t row0 = ((size_t)b * L_ + l0 + qb + g)     * C_ + h * HD_;
    size_t row1 = ((size_t)b * L_ + l0 + qb + g + 8) * C_ + h * HD_;
#pragma unroll
    for (int nt = 0; nt < 8; nt++) {
        int c = nt * 8 + 2 * t4;
        float2 v0, v1;
        v0.x = oacc[nt][0] * inv0; v0.y = oacc[nt][1] * inv0;
        v1.x = oacc[nt][2] * inv1; v1.y = oacc[nt][3] * inv1;
        *(float2*)&g_at[row0 + c] = v0;
        *(float2*)&g_at[row1 + c] = v1;
    }
}

// ---------------------------------------------------------------------------
extern "C" void kernel_launch(void* const* d_in, const int* in_sizes, int n_in,
                              void* d_out, int out_size)
{
    const float* x      = (const float*)d_in[0];
    const float* norm_w = (const float*)d_in[1];
    const float* norm_b = (const float*)d_in[2];
    const float* qkv_w  = (const float*)d_in[3];
    const float* qkv_b  = (const float*)d_in[4];
    const float* proj_w = (const float*)d_in[5];
    const float* proj_b = (const float*)d_in[6];
    float* out = (float*)d_out;

    cudaFuncSetAttribute(attn_kernel,
                         cudaFuncAttributeMaxDynamicSharedMemorySize, ATT2_BYTES);
    cudaFuncSetAttribute(qkv_gemm_kernel,
                         cudaFuncAttributeMaxDynamicSharedMemorySize, GSMEM_BYTES);
    cudaFuncSetAttribute(proj_gemm_kernel,
                         cudaFuncAttributeMaxDynamicSharedMemorySize, GSMEM_BYTES);

    gn_kernel<<<B_ * NG_, 256>>>(x, norm_w, norm_b);

    {
        dim3 grid(L_ / 128, M_QKV / 128, B_);
        qkv_gemm_kernel<<<grid, 256, GSMEM_BYTES>>>(qkv_w, qkv_b);
    }
    {
        dim3 grid(L_ / 128, B_ * NH_);
        attn_kernel<<<grid, 256, ATT2_BYTES>>>();
    }
    {
        dim3 grid(L_ / 128, C_ / 128, B_);
        proj_gemm_kernel<<<grid, 256, GSMEM_BYTES>>>(proj_w, proj_b, x, out);
    }
}

// round 6
// speedup vs baseline: 5.5629x; 1.4908x over previous
#include <cuda_runtime.h>
#include <math.h>
#include <stdint.h>

#define B_   16
#define C_   512
#define L_   1024
#define NH_  8
#define HD_  64
#define NG_  32
#define GCH_ 16
#define M_QKV 1536
#define EPS_ 1e-5f

// Scratch (device globals)
__device__ uint16_t g_h  [(size_t)B_ * L_ * C_];    // groupnorm out, bf16 [B][L][C]
__device__ float    g_qkv[(size_t)B_ * M_QKV * L_]; // qkv fp32 [B][3C][L]
__device__ uint16_t g_at [(size_t)B_ * L_ * C_];    // attention out, bf16 [B][L][C]

__device__ __forceinline__ uint32_t smem_u32(const void* p){
    uint32_t a;
    asm("{ .reg .u64 t; cvta.to.shared.u64 t, %1; cvt.u32.u64 %0, t; }" : "=r"(a) : "l"(p));
    return a;
}
// pack two floats -> bf16x2 (lo = first arg)
__device__ __forceinline__ uint32_t f2bf2(float lo, float hi){
    uint32_t r; asm("cvt.rn.bf16x2.f32 %0, %1, %2;" : "=r"(r) : "f"(hi), "f"(lo)); return r;
}
__device__ __forceinline__ float ex2f(float x){
    float r; asm("ex2.approx.ftz.f32 %0, %1;" : "=f"(r) : "f"(x)); return r;
}
__device__ __forceinline__ void ldsm_x4(uint32_t* r, uint32_t addr){
    asm volatile("ldmatrix.sync.aligned.m8n8.x4.shared.b16 {%0,%1,%2,%3}, [%4];"
        : "=r"(r[0]), "=r"(r[1]), "=r"(r[2]), "=r"(r[3]) : "r"(addr));
}
__device__ __forceinline__ void mma_bf16(float* d, const uint32_t* a,
                                         uint32_t b0, uint32_t b1){
    asm volatile(
        "mma.sync.aligned.m16n8k16.row.col.f32.bf16.bf16.f32 "
        "{%0,%1,%2,%3}, {%4,%5,%6,%7}, {%8,%9}, {%0,%1,%2,%3};"
        : "+f"(d[0]), "+f"(d[1]), "+f"(d[2]), "+f"(d[3])
        : "r"(a[0]), "r"(a[1]), "r"(a[2]), "r"(a[3]), "r"(b0), "r"(b1));
}

// ---------------------------------------------------------------------------
// GroupNorm: fp32 [B][C][L] -> bf16 [B][L][C]
// ---------------------------------------------------------------------------
__global__ void gn_kernel(const float* __restrict__ x,
                          const float* __restrict__ w,
                          const float* __restrict__ bn)
{
    int gb  = blockIdx.x;
    int b   = gb >> 5;
    int grp = gb & 31;
    const float4* xp4 = (const float4*)(x + ((size_t)b * C_ + (size_t)grp * GCH_) * L_);

    int tid = threadIdx.x;
    float s = 0.f, s2 = 0.f;
#pragma unroll 4
    for (int i = tid; i < 4096; i += 256) {
        float4 v = xp4[i];
        s  += v.x + v.y + v.z + v.w;
        s2 += v.x*v.x + v.y*v.y + v.z*v.z + v.w*v.w;
    }
    __shared__ float sh[512];
    sh[tid] = s; sh[256 + tid] = s2;
    __syncthreads();
    for (int off = 128; off > 0; off >>= 1) {
        if (tid < off) { sh[tid] += sh[tid + off]; sh[256 + tid] += sh[256 + tid + off]; }
        __syncthreads();
    }
    __shared__ float s_mean, s_inv;
    if (tid == 0) {
        float mean = sh[0] * (1.f / (GCH_ * L_));
        float var  = sh[256] * (1.f / (GCH_ * L_)) - mean * mean;
        s_mean = mean;
        s_inv  = rsqrtf(var + EPS_);
    }
    __syncthreads();
    float mean = s_mean, inv = s_inv;

    __shared__ float tile[16][257];
    for (int ch = 0; ch < 4; ch++) {
        int lb = ch * 256;
#pragma unroll
        for (int t = 0; t < 4; t++) {
            int idx = tid + t * 256;
            int c = idx >> 6, l4 = idx & 63;
            float4 v = xp4[c * 256 + (lb >> 2) + l4];
            float wc = w[grp * GCH_ + c], bc = bn[grp * GCH_ + c];
            tile[c][l4*4+0] = (v.x - mean) * inv * wc + bc;
            tile[c][l4*4+1] = (v.y - mean) * inv * wc + bc;
            tile[c][l4*4+2] = (v.z - mean) * inv * wc + bc;
            tile[c][l4*4+3] = (v.w - mean) * inv * wc + bc;
        }
        __syncthreads();
#pragma unroll
        for (int t = 0; t < 4; t++) {
            int idx = tid + t * 256;
            int l = idx >> 2, cq = idx & 3;
            uint2 o;
            o.x = f2bf2(tile[cq*4+0][l], tile[cq*4+1][l]);
            o.y = f2bf2(tile[cq*4+2][l], tile[cq*4+3][l]);
            *(uint2*)&g_h[((size_t)b * L_ + lb + l) * C_ + grp * GCH_ + cq * 4] = o;
        }
        __syncthreads();
    }
}

// ---------------------------------------------------------------------------
// bf16 mma GEMM: D[o0+m][l0+n] = sum_c A[o0+m][c] * Bg[l0+n][c]
// Tile 128x128, BK=32, 8 warps (2m x 4n), ldmatrix + m16n8k16, double-buffered.
// A fp32 global (converted on store); B bf16 global (direct copy).
// ---------------------------------------------------------------------------
#define GP 40                         // smem pitch in bf16
#define GSTG (128 * GP)               // bf16 per matrix per stage
#define GSMEM_BYTES (2 * 2 * GSTG * 2)

template <bool RES>
__device__ __forceinline__ void gemm_mma(const float* __restrict__ A,
                                         const float* __restrict__ bias,
                                         const uint16_t* __restrict__ Bg,
                                         const float* __restrict__ res,
                                         float* __restrict__ Cm)
{
    extern __shared__ uint16_t smh[];
    uint32_t smb = smem_u32(smh);
    int tid  = threadIdx.x;
    int wid  = tid >> 5, lane = tid & 31;
    int g    = lane >> 2, t4 = lane & 3;
    int wm   = wid & 1;
    int wn   = wid >> 1;
    int o0   = blockIdx.y * 128;
    int l0   = blockIdx.x * 128;
    int mb   = wm * 64;
    int nb   = wn * 32;
    int l15  = lane & 15;
    int khal = (lane >> 4) * 16;      // byte offset for k-half

    float acc[4][4][4];
#pragma unroll
    for (int mt = 0; mt < 4; mt++)
#pragma unroll
        for (int nt = 0; nt < 4; nt++)
#pragma unroll
            for (int r = 0; r < 4; r++) acc[mt][nt][r] = 0.f;

    // prefetch registers
    float4 aR[2][2];  uint4 bR[2];
    {
        int arow = tid >> 1, ah = tid & 1;          // A: row, 16-float half
#pragma unroll
        for (int u = 0; u < 2; u++)
            aR[u][0] = *(const float4*)&A[(size_t)(o0 + arow) * C_ + ah * 16 + u * 8],
            aR[u][1] = *(const float4*)&A[(size_t)(o0 + arow) * C_ + ah * 16 + u * 8 + 4];
        int brow = tid >> 1, bh = tid & 1;          // B: row, 16-bf16 half
#pragma unroll
        for (int u = 0; u < 2; u++)
            bR[u] = *(const uint4*)&Bg[(size_t)(l0 + brow) * C_ + bh * 16 + u * 8];
    }

    for (int it = 0; it < 16; ++it) {
        uint16_t* As = smh + (it & 1) * (2 * GSTG);
        uint16_t* Bs = As + GSTG;
        uint32_t AsB = smb + (it & 1) * (2 * GSTG * 2);
        uint32_t BsB = AsB + GSTG * 2;
        {
            int row = tid >> 1, hh = tid & 1;
#pragma unroll
            for (int u = 0; u < 2; u++) {
                uint2 aw;
                aw.x = f2bf2(aR[u][0].x, aR[u][0].y);
                aw.y = f2bf2(aR[u][0].z, aR[u][0].w);
                uint2 aw2;
                aw2.x = f2bf2(aR[u][1].x, aR[u][1].y);
                aw2.y = f2bf2(aR[u][1].z, aR[u][1].w);
                *(uint2*)&As[row * GP + hh * 16 + u * 8]     = aw;
                *(uint2*)&As[row * GP + hh * 16 + u * 8 + 4] = aw2;
                *(uint4*)&Bs[row * GP + hh * 16 + u * 8]     = bR[u];
            }
        }
        __syncthreads();
        if (it < 15) {
            int c0 = (it + 1) * 32;
            int row = tid >> 1, hh = tid & 1;
#pragma unroll
            for (int u = 0; u < 2; u++) {
                aR[u][0] = *(const float4*)&A[(size_t)(o0 + row) * C_ + c0 + hh * 16 + u * 8];
                aR[u][1] = *(const float4*)&A[(size_t)(o0 + row) * C_ + c0 + hh * 16 + u * 8 + 4];
                bR[u]    = *(const uint4*)&Bg[(size_t)(l0 + row) * C_ + c0 + hh * 16 + u * 8];
            }
        }

#pragma unroll
        for (int ks = 0; ks < 2; ks++) {
            int kb = ks * 32 + khal;              // byte col offset
            uint32_t af[4][4];
#pragma unroll
            for (int mt = 0; mt < 4; mt++)
                ldsm_x4(af[mt], AsB + (mb + mt * 16 + l15) * (GP * 2) + kb);
            uint32_t bf[4][2];
#pragma unroll
            for (int ng = 0; ng < 2; ng++) {
                uint32_t rr[4];
                ldsm_x4(rr, BsB + (nb + ng * 16 + l15) * (GP * 2) + kb);
                bf[2*ng][0]   = rr[0]; bf[2*ng][1]   = rr[2];
                bf[2*ng+1][0] = rr[1]; bf[2*ng+1][1] = rr[3];
            }
#pragma unroll
            for (int mt = 0; mt < 4; mt++)
#pragma unroll
                for (int nt = 0; nt < 4; nt++)
                    mma_bf16(acc[mt][nt], af[mt], bf[nt][0], bf[nt][1]);
        }
        __syncthreads();
    }

#pragma unroll
    for (int mt = 0; mt < 4; mt++) {
        int r0 = o0 + mb + mt * 16 + g;
        int r1 = r0 + 8;
        float bv0 = bias[r0], bv1 = bias[r1];
#pragma unroll
        for (int nt = 0; nt < 4; nt++) {
            int col = l0 + nb + nt * 8 + 2 * t4;
            size_t a0 = (size_t)r0 * L_ + col;
            size_t a1 = (size_t)r1 * L_ + col;
            float2 v0, v1;
            v0.x = acc[mt][nt][0] + bv0; v0.y = acc[mt][nt][1] + bv0;
            v1.x = acc[mt][nt][2] + bv1; v1.y = acc[mt][nt][3] + bv1;
            if (RES) {
                float2 q0 = *(const float2*)&res[a0];
                float2 q1 = *(const float2*)&res[a1];
                v0.x += q0.x; v0.y += q0.y;
                v1.x += q1.x; v1.y += q1.y;
            }
            *(float2*)&Cm[a0] = v0;
            *(float2*)&Cm[a1] = v1;
        }
    }
}

__global__ __launch_bounds__(256)
void qkv_gemm_kernel(const float* __restrict__ qkv_w,
                     const float* __restrict__ qkv_b)
{
    int b = blockIdx.z;
    gemm_mma<false>(qkv_w, qkv_b,
                    g_h + (size_t)b * L_ * C_,
                    nullptr,
                    g_qkv + (size_t)b * M_QKV * L_);
}

__global__ __launch_bounds__(256)
void proj_gemm_kernel(const float* __restrict__ proj_w,
                      const float* __restrict__ proj_b,
                      const float* __restrict__ x,
                      float* __restrict__ out)
{
    int b = blockIdx.z;
    gemm_mma<true>(proj_w, proj_b,
                   g_at + (size_t)b * L_ * C_,
                   x   + (size_t)b * C_ * L_,
                   out + (size_t)b * C_ * L_);
}

// ---------------------------------------------------------------------------
// bf16 tensor-core flash attention (no-max single-pass softmax).
// Block = (b,h,128q). 8 warps, warp w owns q rows [16w,16w+16). K-tiles of 64.
// Smem (bf16, pitch 72): Qs[128][.] (q,d; prescaled), Ks[64][.] (k,d),
// Vs[64][.] (d,k), Ps[128][.] (q,k warp-private).
// ---------------------------------------------------------------------------
#define APt 72
#define AQo 0
#define AKo (128 * APt)
#define AVo (AKo + 64 * APt)
#define APo (AVo + 64 * APt)
#define ATT_BF16 (APo + 128 * APt)
#define ATT_BYTES (ATT_BF16 * 2)

__global__ __launch_bounds__(256, 2)
void attn_kernel()
{
    int bh = blockIdx.y;
    int b = bh >> 3, h = bh & 7;
    int l0 = blockIdx.x * 128;

    const float* Qp = g_qkv + ((size_t)b * M_QKV + 0 * C_ + h * HD_) * L_;
    const float* Kp = g_qkv + ((size_t)b * M_QKV + 1 * C_ + h * HD_) * L_;
    const float* Vp = g_qkv + ((size_t)b * M_QKV + 2 * C_ + h * HD_) * L_;

    extern __shared__ uint16_t smh[];
    uint32_t smb = smem_u32(smh);
    uint16_t* Qs = smh + AQo;
    uint16_t* Ks = smh + AKo;
    uint16_t* Vs = smh + AVo;
    uint16_t* Ps = smh + APo;
    uint32_t QsB = smb + AQo * 2, KsB = smb + AKo * 2;
    uint32_t VsB = smb + AVo * 2, PsB = smb + APo * 2;

    int tid  = threadIdx.x;
    int lane = tid & 31, wp = tid >> 5;
    int g = lane >> 2, t4 = lane & 3;
    int qb = wp * 16;
    int l15 = lane & 15;
    int khal = (lane >> 4) * 16;

    const float SC = 0.125f * 1.44269504088896340736f;

    // ---- load Q, scaled, [q][d] ----
    {
        int qq = lane + 32 * (wp & 3);
        int d0 = (wp >> 2) * 4;
#pragma unroll
        for (int r = 0; r < 8; r++) {
            int d = d0 + 8 * r;
            uint2 wv;
            wv.x = f2bf2(Qp[(size_t)(d+0) * L_ + l0 + qq] * SC,
                         Qp[(size_t)(d+1) * L_ + l0 + qq] * SC);
            wv.y = f2bf2(Qp[(size_t)(d+2) * L_ + l0 + qq] * SC,
                         Qp[(size_t)(d+3) * L_ + l0 + qq] * SC);
            *(uint2*)&Qs[qq * APt + d] = wv;
        }
    }

    float oacc[8][4];
#pragma unroll
    for (int nt = 0; nt < 8; nt++)
#pragma unroll
        for (int r = 0; r < 4; r++) oacc[nt][r] = 0.f;
    float rsum0 = 0.f, rsum1 = 0.f;

    for (int kt = 0; kt < 16; kt++) {
        int k0 = kt * 64;
        // K [k][d]
        {
            int kk2 = lane + 32 * (wp & 1);
            int d0 = (wp >> 1) * 4;
#pragma unroll
            for (int r = 0; r < 4; r++) {
                int d = d0 + 16 * r;
                uint2 wv;
                wv.x = f2bf2(Kp[(size_t)(d+0) * L_ + k0 + kk2],
                             Kp[(size_t)(d+1) * L_ + k0 + kk2]);
                wv.y = f2bf2(Kp[(size_t)(d+2) * L_ + k0 + kk2],
                             Kp[(size_t)(d+3) * L_ + k0 + kk2]);
                *(uint2*)&Ks[kk2 * APt + d] = wv;
            }
        }
        // V [d][k]
#pragma unroll
        for (int r = 0; r < 4; r++) {
            int idx = tid + r * 256;
            int d = idx >> 4, k4 = idx & 15;
            float4 vv = *(const float4*)&Vp[(size_t)d * L_ + k0 + k4 * 4];
            uint2 wv;
            wv.x = f2bf2(vv.x, vv.y);
            wv.y = f2bf2(vv.z, vv.w);
            *(uint2*)&Vs[d * APt + k4 * 4] = wv;
        }
        __syncthreads();

        // S = Q K^T
        float sacc[8][4];
#pragma unroll
        for (int nt = 0; nt < 8; nt++)
#pragma unroll
            for (int r = 0; r < 4; r++) sacc[nt][r] = 0.f;
#pragma unroll
        for (int kc = 0; kc < 4; kc++) {
            int kb = kc * 32 + khal;
            uint32_t af[4];
            ldsm_x4(af, QsB + (qb + l15) * (APt * 2) + kb);
#pragma unroll
            for (int ng = 0; ng < 4; ng++) {
                uint32_t rr[4];
                ldsm_x4(rr, KsB + (ng * 16 + l15) * (APt * 2) + kb);
                mma_bf16(sacc[2*ng],   af, rr[0], rr[2]);
                mma_bf16(sacc[2*ng+1], af, rr[1], rr[3]);
            }
        }

        // P = exp2(S), row sums, store bf16
#pragma unroll
        for (int nt = 0; nt < 8; nt++) {
            float p0 = ex2f(sacc[nt][0]);
            float p1 = ex2f(sacc[nt][1]);
            float p2 = ex2f(sacc[nt][2]);
            float p3 = ex2f(sacc[nt][3]);
            rsum0 += p0 + p1;
            rsum1 += p2 + p3;
            *(uint32_t*)&Ps[(qb + g)     * APt + nt*8 + 2*t4] = f2bf2(p0, p1);
            *(uint32_t*)&Ps[(qb + g + 8) * APt + nt*8 + 2*t4] = f2bf2(p2, p3);
        }
        __syncwarp();

        // O += P V
#pragma unroll
        for (int kc = 0; kc < 4; kc++) {
            int kb = kc * 32 + khal;
            uint32_t af[4];
            ldsm_x4(af, PsB + (qb + l15) * (APt * 2) + kb);
#pragma unroll
            for (int ng = 0; ng < 4; ng++) {
                uint32_t rr[4];
                ldsm_x4(rr, VsB + (ng * 16 + l15) * (APt * 2) + kb);
                mma_bf16(oacc[2*ng],   af, rr[0], rr[2]);
                mma_bf16(oacc[2*ng+1], af, rr[1], rr[3]);
            }
        }
        __syncthreads();
    }

    // finalize
    rsum0 += __shfl_xor_sync(0xFFFFFFFFu, rsum0, 1);
    rsum0 += __shfl_xor_sync(0xFFFFFFFFu, rsum0, 2);
    rsum1 += __shfl_xor_sync(0xFFFFFFFFu, rsum1, 1);
    rsum1 += __shfl_xor_sync(0xFFFFFFFFu, rsum1, 2);
    float inv0 = 1.f / rsum0;
    float inv1 = 1.f / rsum1;

    size_t row0 = ((size_t)b * L_ + l0 + qb + g)     * C_ + h * HD_;
    size_t row1 = ((size_t)b * L_ + l0 + qb + g + 8) * C_ + h * HD_;
#pragma unroll
    for (int nt = 0; nt < 8; nt++) {
        int c = nt * 8 + 2 * t4;
        *(uint32_t*)&g_at[row0 + c] = f2bf2(oacc[nt][0] * inv0, oacc[nt][1] * inv0);
        *(uint32_t*)&g_at[row1 + c] = f2bf2(oacc[nt][2] * inv1, oacc[nt][3] * inv1);
    }
}

// ---------------------------------------------------------------------------
extern "C" void kernel_launch(void* const* d_in, const int* in_sizes, int n_in,
                              void* d_out, int out_size)
{
    const float* x      = (const float*)d_in[0];
    const float* norm_w = (const float*)d_in[1];
    const float* norm_b = (const float*)d_in[2];
    const float* qkv_w  = (const float*)d_in[3];
    const float* qkv_b  = (const float*)d_in[4];
    const float* proj_w = (const float*)d_in[5];
    const float* proj_b = (const float*)d_in[6];
    float* out = (float*)d_out;

    cudaFuncSetAttribute(attn_kernel,
                         cudaFuncAttributeMaxDynamicSharedMemorySize, ATT_BYTES);
    cudaFuncSetAttribute(qkv_gemm_kernel,
                         cudaFuncAttributeMaxDynamicSharedMemorySize, GSMEM_BYTES);
    cudaFuncSetAttribute(proj_gemm_kernel,
                         cudaFuncAttributeMaxDynamicSharedMemorySize, GSMEM_BYTES);

    gn_kernel<<<B_ * NG_, 256>>>(x, norm_w, norm_b);

    {
        dim3 grid(L_ / 128, M_QKV / 128, B_);
        qkv_gemm_kernel<<<grid, 256, GSMEM_BYTES>>>(qkv_w, qkv_b);
    }
    {
        dim3 grid(L_ / 128, B_ * NH_);
        attn_kernel<<<grid, 256, ATT_BYTES>>>();
    }
    {
        dim3 grid(L_ / 128, C_ / 128, B_);
        proj_gemm_kernel<<<grid, 256, GSMEM_BYTES>>>(proj_w, proj_b, x, out);
    }
}

// round 7
// speedup vs baseline: 6.3695x; 1.1450x over previous
#include <cuda_runtime.h>
#include <math.h>
#include <stdint.h>

#define B_   16
#define C_   512
#define L_   1024
#define NH_  8
#define HD_  64
#define NG_  32
#define GCH_ 16
#define M_QKV 1536
#define EPS_ 1e-5f

// Scratch (device globals)
__device__ uint16_t g_h   [(size_t)B_ * L_ * C_];     // groupnorm out bf16 [B][L][C]
__device__ uint16_t g_qkvh[(size_t)B_ * M_QKV * L_];  // qkv bf16 [B][3C][L]
__device__ uint16_t g_at  [(size_t)B_ * L_ * C_];     // attention out bf16 [B][L][C]
__device__ uint16_t g_wq  [(size_t)M_QKV * C_];       // qkv_w bf16
__device__ uint16_t g_wp  [(size_t)C_ * C_];          // proj_w bf16

__device__ __forceinline__ uint32_t smem_u32(const void* p){
    uint32_t a;
    asm("{ .reg .u64 t; cvta.to.shared.u64 t, %1; cvt.u32.u64 %0, t; }" : "=r"(a) : "l"(p));
    return a;
}
__device__ __forceinline__ uint32_t f2bf2(float lo, float hi){
    uint32_t r; asm("cvt.rn.bf16x2.f32 %0, %1, %2;" : "=r"(r) : "f"(hi), "f"(lo)); return r;
}
__device__ __forceinline__ float ex2f(float x){
    float r; asm("ex2.approx.ftz.f32 %0, %1;" : "=f"(r) : "f"(x)); return r;
}
__device__ __forceinline__ void ldsm_x4(uint32_t* r, uint32_t addr){
    asm volatile("ldmatrix.sync.aligned.m8n8.x4.shared.b16 {%0,%1,%2,%3}, [%4];"
        : "=r"(r[0]), "=r"(r[1]), "=r"(r[2]), "=r"(r[3]) : "r"(addr));
}
__device__ __forceinline__ void mma_bf16(float* d, const uint32_t* a,
                                         uint32_t b0, uint32_t b1){
    asm volatile(
        "mma.sync.aligned.m16n8k16.row.col.f32.bf16.bf16.f32 "
        "{%0,%1,%2,%3}, {%4,%5,%6,%7}, {%8,%9}, {%0,%1,%2,%3};"
        : "+f"(d[0]), "+f"(d[1]), "+f"(d[2]), "+f"(d[3])
        : "r"(a[0]), "r"(a[1]), "r"(a[2]), "r"(a[3]), "r"(b0), "r"(b1));
}
#define CP16(dst, src) \
    asm volatile("cp.async.cg.shared.global [%0], [%1], 16;" :: "r"(dst), "l"(src))
#define CP_COMMIT() asm volatile("cp.async.commit_group;" ::: "memory")
#define CP_WAIT1()  asm volatile("cp.async.wait_group 1;" ::: "memory")
#define CP_WAIT0()  asm volatile("cp.async.wait_group 0;" ::: "memory")

// ---------------------------------------------------------------------------
// fp32 -> bf16 weight conversion (once per launch; deterministic)
// ---------------------------------------------------------------------------
__global__ void w2bf_kernel(const float* __restrict__ src,
                            uint16_t* __restrict__ dst, int n4)
{
    int i = blockIdx.x * blockDim.x + threadIdx.x;
    if (i < n4) {
        float4 v = ((const float4*)src)[i];
        uint2 o;
        o.x = f2bf2(v.x, v.y);
        o.y = f2bf2(v.z, v.w);
        ((uint2*)dst)[i] = o;
    }
}

// ---------------------------------------------------------------------------
// GroupNorm: fp32 [B][C][L] -> bf16 [B][L][C]
// ---------------------------------------------------------------------------
__global__ void gn_kernel(const float* __restrict__ x,
                          const float* __restrict__ w,
                          const float* __restrict__ bn)
{
    int gb  = blockIdx.x;
    int b   = gb >> 5;
    int grp = gb & 31;
    const float4* xp4 = (const float4*)(x + ((size_t)b * C_ + (size_t)grp * GCH_) * L_);

    int tid = threadIdx.x;
    float s = 0.f, s2 = 0.f;
#pragma unroll 4
    for (int i = tid; i < 4096; i += 256) {
        float4 v = xp4[i];
        s  += v.x + v.y + v.z + v.w;
        s2 += v.x*v.x + v.y*v.y + v.z*v.z + v.w*v.w;
    }
    __shared__ float sh[512];
    sh[tid] = s; sh[256 + tid] = s2;
    __syncthreads();
    for (int off = 128; off > 0; off >>= 1) {
        if (tid < off) { sh[tid] += sh[tid + off]; sh[256 + tid] += sh[256 + tid + off]; }
        __syncthreads();
    }
    __shared__ float s_mean, s_inv;
    if (tid == 0) {
        float mean = sh[0] * (1.f / (GCH_ * L_));
        float var  = sh[256] * (1.f / (GCH_ * L_)) - mean * mean;
        s_mean = mean;
        s_inv  = rsqrtf(var + EPS_);
    }
    __syncthreads();
    float mean = s_mean, inv = s_inv;

    __shared__ float tile[16][257];
    for (int ch = 0; ch < 4; ch++) {
        int lb = ch * 256;
#pragma unroll
        for (int t = 0; t < 4; t++) {
            int idx = tid + t * 256;
            int c = idx >> 6, l4 = idx & 63;
            float4 v = xp4[c * 256 + (lb >> 2) + l4];
            float wc = w[grp * GCH_ + c], bc = bn[grp * GCH_ + c];
            tile[c][l4*4+0] = (v.x - mean) * inv * wc + bc;
            tile[c][l4*4+1] = (v.y - mean) * inv * wc + bc;
            tile[c][l4*4+2] = (v.z - mean) * inv * wc + bc;
            tile[c][l4*4+3] = (v.w - mean) * inv * wc + bc;
        }
        __syncthreads();
#pragma unroll
        for (int t = 0; t < 4; t++) {
            int idx = tid + t * 256;
            int l = idx >> 2, cq = idx & 3;
            uint2 o;
            o.x = f2bf2(tile[cq*4+0][l], tile[cq*4+1][l]);
            o.y = f2bf2(tile[cq*4+2][l], tile[cq*4+3][l]);
            *(uint2*)&g_h[((size_t)b * L_ + lb + l) * C_ + grp * GCH_ + cq * 4] = o;
        }
        __syncthreads();
    }
}

// ---------------------------------------------------------------------------
// bf16 GEMM, cp.async 3-stage: D[o0+m][l0+n] = sum_c A[o][c] * Bg[l][c]
// Tile 128x128, BK=32, 8 warps (2m x 4n), ldmatrix + m16n8k16.
// MODE 0: store bf16 (qkv). MODE 1: fp32 + residual (proj).
// ---------------------------------------------------------------------------
#define GP 40
#define GSTG (128 * GP)              // bf16 per matrix per stage
#define STAGE_B (2 * GSTG * 2)       // bytes per stage (A+B)
#define GSMEM_BYTES (3 * STAGE_B)

template <int MODE>
__device__ __forceinline__ void gemm_mma(const uint16_t* __restrict__ Aw,
                                         const float* __restrict__ bias,
                                         const uint16_t* __restrict__ Bg,
                                         const float* __restrict__ res,
                                         float* __restrict__ Cf,
                                         uint16_t* __restrict__ Ch)
{
    extern __shared__ uint16_t smh[];
    uint32_t smb = smem_u32(smh);
    int tid  = threadIdx.x;
    int wid  = tid >> 5, lane = tid & 31;
    int g    = lane >> 2, t4 = lane & 3;
    int wm   = wid & 1;
    int wn   = wid >> 1;
    int o0   = blockIdx.y * 128;
    int l0   = blockIdx.x * 128;
    int mb   = wm * 64;
    int nb   = wn * 32;
    int l15  = lane & 15;
    int khal = (lane >> 4) * 16;

    int ldrow = tid >> 2, ldc = tid & 3;   // 4 chunks of 16B per 32-bf16 row... (2 per thread)

    float acc[4][4][4];
#pragma unroll
    for (int mt = 0; mt < 4; mt++)
#pragma unroll
        for (int nt = 0; nt < 4; nt++)
#pragma unroll
            for (int r = 0; r < 4; r++) acc[mt][nt][r] = 0.f;

    // stage issue: A tile 128x32 bf16 (4 chunks/row), same for B
    auto issue = [&](int st, int c0) {
        uint32_t base = smb + st * STAGE_B;
#pragma unroll
        for (int t = 0; t < 2; t++) {
            int idx = tid + t * 256;             // 0..511
            int row = idx >> 2, c = idx & 3;
            CP16(base + row * 80 + c * 16,
                 &Aw[(size_t)(o0 + row) * C_ + c0 + c * 8]);
            CP16(base + GSTG * 2 + row * 80 + c * 16,
                 &Bg[(size_t)(l0 + row) * C_ + c0 + c * 8]);
        }
    };

    issue(0, 0);  CP_COMMIT();
    issue(1, 32); CP_COMMIT();

    for (int it = 0; it < 16; ++it) {
        if (it < 14) CP_WAIT1(); else CP_WAIT0();
        __syncthreads();
        if (it + 2 < 16) {
            int st = (it + 2) % 3;
            issue(st, (it + 2) * 32);
            CP_COMMIT();
        }
        uint32_t AsB = smb + (it % 3) * STAGE_B;
        uint32_t BsB = AsB + GSTG * 2;
#pragma unroll
        for (int ks = 0; ks < 2; ks++) {
            int kb = ks * 32 + khal;
            uint32_t af[4][4];
#pragma unroll
            for (int mt = 0; mt < 4; mt++)
                ldsm_x4(af[mt], AsB + (mb + mt * 16 + l15) * 80 + kb);
            uint32_t bf[4][2];
#pragma unroll
            for (int ng = 0; ng < 2; ng++) {
                uint32_t rr[4];
                ldsm_x4(rr, BsB + (nb + ng * 16 + l15) * 80 + kb);
                bf[2*ng][0]   = rr[0]; bf[2*ng][1]   = rr[2];
                bf[2*ng+1][0] = rr[1]; bf[2*ng+1][1] = rr[3];
            }
#pragma unroll
            for (int mt = 0; mt < 4; mt++)
#pragma unroll
                for (int nt = 0; nt < 4; nt++)
                    mma_bf16(acc[mt][nt], af[mt], bf[nt][0], bf[nt][1]);
        }
        __syncthreads();
    }

#pragma unroll
    for (int mt = 0; mt < 4; mt++) {
        int r0 = o0 + mb + mt * 16 + g;
        int r1 = r0 + 8;
        float bv0 = bias[r0], bv1 = bias[r1];
#pragma unroll
        for (int nt = 0; nt < 4; nt++) {
            int col = l0 + nb + nt * 8 + 2 * t4;
            size_t a0 = (size_t)r0 * L_ + col;
            size_t a1 = (size_t)r1 * L_ + col;
            float v00 = acc[mt][nt][0] + bv0, v01 = acc[mt][nt][1] + bv0;
            float v10 = acc[mt][nt][2] + bv1, v11 = acc[mt][nt][3] + bv1;
            if (MODE == 0) {
                *(uint32_t*)&Ch[a0] = f2bf2(v00, v01);
                *(uint32_t*)&Ch[a1] = f2bf2(v10, v11);
            } else {
                float2 q0 = *(const float2*)&res[a0];
                float2 q1 = *(const float2*)&res[a1];
                float2 w0, w1;
                w0.x = v00 + q0.x; w0.y = v01 + q0.y;
                w1.x = v10 + q1.x; w1.y = v11 + q1.y;
                *(float2*)&Cf[a0] = w0;
                *(float2*)&Cf[a1] = w1;
            }
        }
    }
}

__global__ __launch_bounds__(256)
void qkv_gemm_kernel(const float* __restrict__ qkv_b)
{
    int b = blockIdx.z;
    gemm_mma<0>(g_wq, qkv_b,
                g_h + (size_t)b * L_ * C_,
                nullptr, nullptr,
                g_qkvh + (size_t)b * M_QKV * L_);
}

__global__ __launch_bounds__(256)
void proj_gemm_kernel(const float* __restrict__ proj_b,
                      const float* __restrict__ x,
                      float* __restrict__ out)
{
    int b = blockIdx.z;
    gemm_mma<1>(g_wp, proj_b,
                g_at + (size_t)b * L_ * C_,
                x   + (size_t)b * C_ * L_,
                out + (size_t)b * C_ * L_,
                nullptr);
}

// ---------------------------------------------------------------------------
// bf16 tensor-core flash attention (no-max softmax; scale folded post-MMA).
// All QKV inputs bf16 [3C][L]. Smem pitch 72 bf16.
// ---------------------------------------------------------------------------
#define APt 72
#define AQo 0
#define AKo (128 * APt)
#define AVo (AKo + 64 * APt)
#define APo (AVo + 64 * APt)
#define ATT_BF16 (APo + 128 * APt)
#define ATT_BYTES (ATT_BF16 * 2)

__global__ __launch_bounds__(256, 2)
void attn_kernel()
{
    int bh = blockIdx.y;
    int b = bh >> 3, h = bh & 7;
    int l0 = blockIdx.x * 128;

    const uint16_t* Qp = g_qkvh + ((size_t)b * M_QKV + 0 * C_ + h * HD_) * L_;
    const uint16_t* Kp = g_qkvh + ((size_t)b * M_QKV + 1 * C_ + h * HD_) * L_;
    const uint16_t* Vp = g_qkvh + ((size_t)b * M_QKV + 2 * C_ + h * HD_) * L_;

    extern __shared__ uint16_t smh[];
    uint32_t smb = smem_u32(smh);
    uint16_t* Qs = smh + AQo;
    uint16_t* Ks = smh + AKo;
    uint16_t* Vs = smh + AVo;
    uint16_t* Ps = smh + APo;
    uint32_t QsB = smb + AQo * 2, KsB = smb + AKo * 2;
    uint32_t VsB = smb + AVo * 2, PsB = smb + APo * 2;

    int tid  = threadIdx.x;
    int lane = tid & 31, wp = tid >> 5;
    int g = lane >> 2, t4 = lane & 3;
    int qb = wp * 16;
    int l15 = lane & 15;
    int khal = (lane >> 4) * 16;

    const float SC = 0.125f * 1.44269504088896340736f;

    // ---- load Q [q][d] (transposed copy, raw bf16) ----
    {
        int qq = lane + 32 * (wp & 3);
        int d0 = (wp >> 2) * 4;
#pragma unroll
        for (int r = 0; r < 8; r++) {
            int d = d0 + 8 * r;
            uint16_t q0 = Qp[(size_t)(d+0) * L_ + l0 + qq];
            uint16_t q1 = Qp[(size_t)(d+1) * L_ + l0 + qq];
            uint16_t q2 = Qp[(size_t)(d+2) * L_ + l0 + qq];
            uint16_t q3 = Qp[(size_t)(d+3) * L_ + l0 + qq];
            uint2 wv;
            wv.x = (uint32_t)q0 | ((uint32_t)q1 << 16);
            wv.y = (uint32_t)q2 | ((uint32_t)q3 << 16);
            *(uint2*)&Qs[qq * APt + d] = wv;
        }
    }

    float oacc[8][4];
#pragma unroll
    for (int nt = 0; nt < 8; nt++)
#pragma unroll
        for (int r = 0; r < 4; r++) oacc[nt][r] = 0.f;
    float rsum0 = 0.f, rsum1 = 0.f;

    for (int kt = 0; kt < 16; kt++) {
        int k0 = kt * 64;
        // K [k][d] transposed copy
        {
            int kk2 = lane + 32 * (wp & 1);
            int d0 = (wp >> 1) * 4;
#pragma unroll
            for (int r = 0; r < 4; r++) {
                int d = d0 + 16 * r;
                uint16_t q0 = Kp[(size_t)(d+0) * L_ + k0 + kk2];
                uint16_t q1 = Kp[(size_t)(d+1) * L_ + k0 + kk2];
                uint16_t q2 = Kp[(size_t)(d+2) * L_ + k0 + kk2];
                uint16_t q3 = Kp[(size_t)(d+3) * L_ + k0 + kk2];
                uint2 wv;
                wv.x = (uint32_t)q0 | ((uint32_t)q1 << 16);
                wv.y = (uint32_t)q2 | ((uint32_t)q3 << 16);
                *(uint2*)&Ks[kk2 * APt + d] = wv;
            }
        }
        // V [d][k] direct 16B copies
#pragma unroll
        for (int r = 0; r < 2; r++) {
            int idx = tid + r * 256;          // 0..511
            int d = idx >> 3, k8 = idx & 7;
            *(uint4*)&Vs[d * APt + k8 * 8] =
                *(const uint4*)&Vp[(size_t)d * L_ + k0 + k8 * 8];
        }
        __syncthreads();

        // S = Q K^T
        float sacc[8][4];
#pragma unroll
        for (int nt = 0; nt < 8; nt++)
#pragma unroll
            for (int r = 0; r < 4; r++) sacc[nt][r] = 0.f;
#pragma unroll
        for (int kc = 0; kc < 4; kc++) {
            int kb = kc * 32 + khal;
            uint32_t af[4];
            ldsm_x4(af, QsB + (qb + l15) * (APt * 2) + kb);
#pragma unroll
            for (int ng = 0; ng < 4; ng++) {
                uint32_t rr[4];
                ldsm_x4(rr, KsB + (ng * 16 + l15) * (APt * 2) + kb);
                mma_bf16(sacc[2*ng],   af, rr[0], rr[2]);
                mma_bf16(sacc[2*ng+1], af, rr[1], rr[3]);
            }
        }

        // P = exp2(S * SC)
#pragma unroll
        for (int nt = 0; nt < 8; nt++) {
            float p0 = ex2f(sacc[nt][0] * SC);
            float p1 = ex2f(sacc[nt][1] * SC);
            float p2 = ex2f(sacc[nt][2] * SC);
            float p3 = ex2f(sacc[nt][3] * SC);
            rsum0 += p0 + p1;
            rsum1 += p2 + p3;
            *(uint32_t*)&Ps[(qb + g)     * APt + nt*8 + 2*t4] = f2bf2(p0, p1);
            *(uint32_t*)&Ps[(qb + g + 8) * APt + nt*8 + 2*t4] = f2bf2(p2, p3);
        }
        __syncwarp();

        // O += P V
#pragma unroll
        for (int kc = 0; kc < 4; kc++) {
            int kb = kc * 32 + khal;
            uint32_t af[4];
            ldsm_x4(af, PsB + (qb + l15) * (APt * 2) + kb);
#pragma unroll
            for (int ng = 0; ng < 4; ng++) {
                uint32_t rr[4];
                ldsm_x4(rr, VsB + (ng * 16 + l15) * (APt * 2) + kb);
                mma_bf16(oacc[2*ng],   af, rr[0], rr[2]);
                mma_bf16(oacc[2*ng+1], af, rr[1], rr[3]);
            }
        }
        __syncthreads();
    }

    rsum0 += __shfl_xor_sync(0xFFFFFFFFu, rsum0, 1);
    rsum0 += __shfl_xor_sync(0xFFFFFFFFu, rsum0, 2);
    rsum1 += __shfl_xor_sync(0xFFFFFFFFu, rsum1, 1);
    rsum1 += __shfl_xor_sync(0xFFFFFFFFu, rsum1, 2);
    float inv0 = 1.f / rsum0;
    float inv1 = 1.f / rsum1;

    size_t row0 = ((size_t)b * L_ + l0 + qb + g)     * C_ + h * HD_;
    size_t row1 = ((size_t)b * L_ + l0 + qb + g + 8) * C_ + h * HD_;
#pragma unroll
    for (int nt = 0; nt < 8; nt++) {
        int c = nt * 8 + 2 * t4;
        *(uint32_t*)&g_at[row0 + c] = f2bf2(oacc[nt][0] * inv0, oacc[nt][1] * inv0);
        *(uint32_t*)&g_at[row1 + c] = f2bf2(oacc[nt][2] * inv1, oacc[nt][3] * inv1);
    }
}

// ---------------------------------------------------------------------------
extern "C" void kernel_launch(void* const* d_in, const int* in_sizes, int n_in,
                              void* d_out, int out_size)
{
    const float* x      = (const float*)d_in[0];
    const float* norm_w = (const float*)d_in[1];
    const float* norm_b = (const float*)d_in[2];
    const float* qkv_w  = (const float*)d_in[3];
    const float* qkv_b  = (const float*)d_in[4];
    const float* proj_w = (const float*)d_in[5];
    const float* proj_b = (const float*)d_in[6];
    float* out = (float*)d_out;

    cudaFuncSetAttribute(attn_kernel,
                         cudaFuncAttributeMaxDynamicSharedMemorySize, ATT_BYTES);
    cudaFuncSetAttribute(qkv_gemm_kernel,
                         cudaFuncAttributeMaxDynamicSharedMemorySize, GSMEM_BYTES);
    cudaFuncSetAttribute(proj_gemm_kernel,
                         cudaFuncAttributeMaxDynamicSharedMemorySize, GSMEM_BYTES);

    // weight conversion (runs concurrently-safe, ordered on stream)
    {
        uint16_t* dq; cudaGetSymbolAddress((void**)&dq, g_wq);
        uint16_t* dp; cudaGetSymbolAddress((void**)&dp, g_wp);
        int n4q = M_QKV * C_ / 4;
        int n4p = C_ * C_ / 4;
        w2bf_kernel<<<(n4q + 255) / 256, 256>>>(qkv_w, dq, n4q);
        w2bf_kernel<<<(n4p + 255) / 256, 256>>>(proj_w, dp, n4p);
    }

    gn_kernel<<<B_ * NG_, 256>>>(x, norm_w, norm_b);

    {
        dim3 grid(L_ / 128, M_QKV / 128, B_);
        qkv_gemm_kernel<<<grid, 256, GSMEM_BYTES>>>(qkv_b);
    }
    {
        dim3 grid(L_ / 128, B_ * NH_);
        attn_kernel<<<grid, 256, ATT_BYTES>>>();
    }
    {
        dim3 grid(L_ / 128, C_ / 128, B_);
        proj_gemm_kernel<<<grid, 256, GSMEM_BYTES>>>(proj_b, x, out);
    }
}

// round 9
// speedup vs baseline: 7.0094x; 1.1005x over previous
#include <cuda_runtime.h>
#include <math.h>
#include <stdint.h>

#define B_   16
#define C_   512
#define L_   1024
#define NH_  8
#define HD_  64
#define NG_  32
#define GCH_ 16
#define M_QKV 1536
#define EPS_ 1e-5f

// Scratch (device globals)
__device__ uint16_t g_h   [(size_t)B_ * L_ * C_];     // groupnorm out bf16 [B][L][C]
__device__ uint16_t g_qkvh[(size_t)B_ * M_QKV * L_];  // qkv bf16 [B][3C][L]
__device__ uint16_t g_at  [(size_t)B_ * L_ * C_];     // attention out bf16 [B][L][C]
__device__ uint16_t g_wq  [(size_t)M_QKV * C_];       // qkv_w bf16
__device__ uint16_t g_wp  [(size_t)C_ * C_];          // proj_w bf16

__device__ __forceinline__ uint32_t smem_u32(const void* p){
    uint32_t a;
    asm("{ .reg .u64 t; cvta.to.shared.u64 t, %1; cvt.u32.u64 %0, t; }" : "=r"(a) : "l"(p));
    return a;
}
__device__ __forceinline__ uint32_t f2bf2(float lo, float hi){
    uint32_t r; asm("cvt.rn.bf16x2.f32 %0, %1, %2;" : "=r"(r) : "f"(hi), "f"(lo)); return r;
}
__device__ __forceinline__ float ex2f(float x){
    float r; asm("ex2.approx.ftz.f32 %0, %1;" : "=f"(r) : "f"(x)); return r;
}
__device__ __forceinline__ void ldsm_x4(uint32_t* r, uint32_t addr){
    asm volatile("ldmatrix.sync.aligned.m8n8.x4.shared.b16 {%0,%1,%2,%3}, [%4];"
        : "=r"(r[0]), "=r"(r[1]), "=r"(r[2]), "=r"(r[3]) : "r"(addr));
}
__device__ __forceinline__ void mma_bf16(float* d, const uint32_t* a,
                                         uint32_t b0, uint32_t b1){
    asm volatile(
        "mma.sync.aligned.m16n8k16.row.col.f32.bf16.bf16.f32 "
        "{%0,%1,%2,%3}, {%4,%5,%6,%7}, {%8,%9}, {%0,%1,%2,%3};"
        : "+f"(d[0]), "+f"(d[1]), "+f"(d[2]), "+f"(d[3])
        : "r"(a[0]), "r"(a[1]), "r"(a[2]), "r"(a[3]), "r"(b0), "r"(b1));
}
#define CP16(dst, src) \
    asm volatile("cp.async.cg.shared.global [%0], [%1], 16;" :: "r"(dst), "l"(src))
#define CP_COMMIT() asm volatile("cp.async.commit_group;" ::: "memory")
#define CP_WAIT1()  asm volatile("cp.async.wait_group 1;" ::: "memory")
#define CP_WAIT0()  asm volatile("cp.async.wait_group 0;" ::: "memory")

// ---------------------------------------------------------------------------
// Fused GroupNorm + weight conversion.
// blocks [0,512): GN fp32 [B][C][L] -> bf16 [B][L][C]
// blocks [512,1536): convert qkv_w / proj_w to bf16
// ---------------------------------------------------------------------------
#define N4Q (M_QKV * C_ / 4)
#define N4P (C_ * C_ / 4)

__global__ void gn_kernel(const float* __restrict__ x,
                          const float* __restrict__ w,
                          const float* __restrict__ bn,
                          const float* __restrict__ qkv_w,
                          const float* __restrict__ proj_w)
{
    int tid = threadIdx.x;
    if (blockIdx.x >= 512) {
        int i = (blockIdx.x - 512) * 256 + tid;     // 0 .. 262143
        const float4* src;
        uint2* dst;
        if (i < N4Q) { src = (const float4*)qkv_w + i;        dst = (uint2*)g_wq + i; }
        else         { src = (const float4*)proj_w + (i-N4Q); dst = (uint2*)g_wp + (i-N4Q); }
        float4 v = *src;
        uint2 o;
        o.x = f2bf2(v.x, v.y);
        o.y = f2bf2(v.z, v.w);
        *dst = o;
        return;
    }

    int gb  = blockIdx.x;
    int b   = gb >> 5;
    int grp = gb & 31;
    const float4* xp4 = (const float4*)(x + ((size_t)b * C_ + (size_t)grp * GCH_) * L_);

    float s = 0.f, s2 = 0.f;
#pragma unroll 4
    for (int i = tid; i < 4096; i += 256) {
        float4 v = xp4[i];
        s  += v.x + v.y + v.z + v.w;
        s2 += v.x*v.x + v.y*v.y + v.z*v.z + v.w*v.w;
    }
    __shared__ float sh[512];
    sh[tid] = s; sh[256 + tid] = s2;
    __syncthreads();
    for (int off = 128; off > 0; off >>= 1) {
        if (tid < off) { sh[tid] += sh[tid + off]; sh[256 + tid] += sh[256 + tid + off]; }
        __syncthreads();
    }
    __shared__ float s_mean, s_inv;
    if (tid == 0) {
        float mean = sh[0] * (1.f / (GCH_ * L_));
        float var  = sh[256] * (1.f / (GCH_ * L_)) - mean * mean;
        s_mean = mean;
        s_inv  = rsqrtf(var + EPS_);
    }
    __syncthreads();
    float mean = s_mean, inv = s_inv;

    __shared__ float tile[16][257];
    for (int ch = 0; ch < 4; ch++) {
        int lb = ch * 256;
#pragma unroll
        for (int t = 0; t < 4; t++) {
            int idx = tid + t * 256;
            int c = idx >> 6, l4 = idx & 63;
            float4 v = xp4[c * 256 + (lb >> 2) + l4];
            float wc = w[grp * GCH_ + c], bc = bn[grp * GCH_ + c];
            tile[c][l4*4+0] = (v.x - mean) * inv * wc + bc;
            tile[c][l4*4+1] = (v.y - mean) * inv * wc + bc;
            tile[c][l4*4+2] = (v.z - mean) * inv * wc + bc;
            tile[c][l4*4+3] = (v.w - mean) * inv * wc + bc;
        }
        __syncthreads();
#pragma unroll
        for (int t = 0; t < 4; t++) {
            int idx = tid + t * 256;
            int l = idx >> 2, cq = idx & 3;
            uint2 o;
            o.x = f2bf2(tile[cq*4+0][l], tile[cq*4+1][l]);
            o.y = f2bf2(tile[cq*4+2][l], tile[cq*4+3][l]);
            *(uint2*)&g_h[((size_t)b * L_ + lb + l) * C_ + grp * GCH_ + cq * 4] = o;
        }
        __syncthreads();
    }
}

// ---------------------------------------------------------------------------
// bf16 GEMM, BK=64, 2-stage cp.async: D[o0+m][l0+n] = sum_c A[o][c]*Bg[l][c]
// Tile 128x128, 8 warps (2m x 4n), ldmatrix + m16n8k16.
// MODE 0: store bf16 (qkv). MODE 1: fp32 + residual (proj).
// ---------------------------------------------------------------------------
#define GP 72                        // smem pitch bf16 (64 data + 8 pad)
#define GSTG (128 * GP)              // bf16 per matrix per stage
#define STAGE_B (2 * GSTG * 2)       // bytes per stage (A+B) = 36864
#define GSMEM_BYTES (2 * STAGE_B)    // 73728

template <int MODE>
__device__ __forceinline__ void gemm_mma(const uint16_t* __restrict__ Aw,
                                         const float* __restrict__ bias,
                                         const uint16_t* __restrict__ Bg,
                                         const float* __restrict__ res,
                                         float* __restrict__ Cf,
                                         uint16_t* __restrict__ Ch)
{
    extern __shared__ uint16_t smh[];
    uint32_t smb = smem_u32(smh);
    int tid  = threadIdx.x;
    int wid  = tid >> 5, lane = tid & 31;
    int g    = lane >> 2, t4 = lane & 3;
    int wm   = wid & 1;
    int wn   = wid >> 1;
    int o0   = blockIdx.y * 128;
    int l0   = blockIdx.x * 128;
    int mb   = wm * 64;
    int nb   = wn * 32;
    int l15  = lane & 15;
    int khal = (lane >> 4) * 16;

    float acc[4][4][4];
#pragma unroll
    for (int mt = 0; mt < 4; mt++)
#pragma unroll
        for (int nt = 0; nt < 4; nt++)
#pragma unroll
            for (int r = 0; r < 4; r++) acc[mt][nt][r] = 0.f;

    // stage issue: A tile 128 rows x 64 bf16 = 128 rows x 8 16B-chunks; same for B
    auto issue = [&](int st, int c0) {
        uint32_t base = smb + st * STAGE_B;
#pragma unroll
        for (int t = 0; t < 4; t++) {
            int idx = tid + t * 256;             // 0..1023
            int row = idx >> 3, c = idx & 7;
            CP16(base + row * 144 + c * 16,
                 &Aw[(size_t)(o0 + row) * C_ + c0 + c * 8]);
            CP16(base + GSTG * 2 + row * 144 + c * 16,
                 &Bg[(size_t)(l0 + row) * C_ + c0 + c * 8]);
        }
    };

    issue(0, 0);  CP_COMMIT();

    for (int it = 0; it < 8; ++it) {
        if (it < 7) { issue((it + 1) & 1, (it + 1) * 64); CP_COMMIT(); CP_WAIT1(); }
        else        { CP_WAIT0(); }
        __syncthreads();

        uint32_t AsB = smb + (it & 1) * STAGE_B;
        uint32_t BsB = AsB + GSTG * 2;
#pragma unroll
        for (int ks = 0; ks < 4; ks++) {
            int kb = ks * 32 + khal;
            uint32_t af[4][4];
#pragma unroll
            for (int mt = 0; mt < 4; mt++)
                ldsm_x4(af[mt], AsB + (mb + mt * 16 + l15) * 144 + kb);
            uint32_t bf[4][2];
#pragma unroll
            for (int ng = 0; ng < 2; ng++) {
                uint32_t rr[4];
                ldsm_x4(rr, BsB + (nb + ng * 16 + l15) * 144 + kb);
                bf[2*ng][0]   = rr[0]; bf[2*ng][1]   = rr[2];
                bf[2*ng+1][0] = rr[1]; bf[2*ng+1][1] = rr[3];
            }
#pragma unroll
            for (int mt = 0; mt < 4; mt++)
#pragma unroll
                for (int nt = 0; nt < 4; nt++)
                    mma_bf16(acc[mt][nt], af[mt], bf[nt][0], bf[nt][1]);
        }
        __syncthreads();
    }

#pragma unroll
    for (int mt = 0; mt < 4; mt++) {
        int r0 = o0 + mb + mt * 16 + g;
        int r1 = r0 + 8;
        float bv0 = bias[r0], bv1 = bias[r1];
#pragma unroll
        for (int nt = 0; nt < 4; nt++) {
            int col = l0 + nb + nt * 8 + 2 * t4;
            size_t a0 = (size_t)r0 * L_ + col;
            size_t a1 = (size_t)r1 * L_ + col;
            float v00 = acc[mt][nt][0] + bv0, v01 = acc[mt][nt][1] + bv0;
            float v10 = acc[mt][nt][2] + bv1, v11 = acc[mt][nt][3] + bv1;
            if (MODE == 0) {
                *(uint32_t*)&Ch[a0] = f2bf2(v00, v01);
                *(uint32_t*)&Ch[a1] = f2bf2(v10, v11);
            } else {
                float2 q0 = *(const float2*)&res[a0];
                float2 q1 = *(const float2*)&res[a1];
                float2 w0, w1;
                w0.x = v00 + q0.x; w0.y = v01 + q0.y;
                w1.x = v10 + q1.x; w1.y = v11 + q1.y;
                *(float2*)&Cf[a0] = w0;
                *(float2*)&Cf[a1] = w1;
            }
        }
    }
}

__global__ __launch_bounds__(256)
void qkv_gemm_kernel(const float* __restrict__ qkv_b)
{
    int b = blockIdx.z;
    gemm_mma<0>(g_wq, qkv_b,
                g_h + (size_t)b * L_ * C_,
                nullptr, nullptr,
                g_qkvh + (size_t)b * M_QKV * L_);
}

__global__ __launch_bounds__(256)
void proj_gemm_kernel(const float* __restrict__ proj_b,
                      const float* __restrict__ x,
                      float* __restrict__ out)
{
    int b = blockIdx.z;
    gemm_mma<1>(g_wp, proj_b,
                g_at + (size_t)b * L_ * C_,
                x   + (size_t)b * C_ * L_,
                out + (size_t)b * C_ * L_,
                nullptr);
}

// ---------------------------------------------------------------------------
// bf16 tensor-core flash attention (no-max softmax), double-buffered K/V,
// one __syncthreads per k-tile. Inputs bf16 [3C][L]. Smem pitch 72 bf16.
// ---------------------------------------------------------------------------
#define APt 72
#define AQo 0
#define AKo (128 * APt)               // K: 2 buffers x 64 x APt
#define AVo (AKo + 2 * 64 * APt)      // V: 2 buffers x 64 x APt
#define APo (AVo + 2 * 64 * APt)      // P: 128 x APt
#define ATT_BF16 (APo + 128 * APt)
#define ATT_BYTES (ATT_BF16 * 2)

__global__ __launch_bounds__(256, 2)
void attn_kernel()
{
    int bh = blockIdx.y;
    int b = bh >> 3, h = bh & 7;
    int l0 = blockIdx.x * 128;

    const uint16_t* Qp = g_qkvh + ((size_t)b * M_QKV + 0 * C_ + h * HD_) * L_;
    const uint16_t* Kp = g_qkvh + ((size_t)b * M_QKV + 1 * C_ + h * HD_) * L_;
    const uint16_t* Vp = g_qkvh + ((size_t)b * M_QKV + 2 * C_ + h * HD_) * L_;

    extern __shared__ uint16_t smh[];
    uint32_t smb = smem_u32(smh);
    uint16_t* Qs = smh + AQo;
    uint16_t* Ks = smh + AKo;
    uint16_t* Ps = smh + APo;
    uint32_t QsB = smb + AQo * 2, KsB = smb + AKo * 2;
    uint32_t VsB = smb + AVo * 2, PsB = smb + APo * 2;

    int tid  = threadIdx.x;
    int lane = tid & 31, wp = tid >> 5;
    int g = lane >> 2, t4 = lane & 3;
    int qb = wp * 16;
    int l15 = lane & 15;
    int khal = (lane >> 4) * 16;

    const float SC = 0.125f * 1.44269504088896340736f;

    // K transposed scalar load into buffer `buf` for tile k0
    auto load_K = [&](int k0, int buf) {
        uint16_t* Kb = Ks + buf * 64 * APt;
        int kk2 = lane + 32 * (wp & 1);
        int d0 = (wp >> 1) * 4;
#pragma unroll
        for (int r = 0; r < 4; r++) {
            int d = d0 + 16 * r;
            uint16_t q0 = Kp[(size_t)(d+0) * L_ + k0 + kk2];
            uint16_t q1 = Kp[(size_t)(d+1) * L_ + k0 + kk2];
            uint16_t q2 = Kp[(size_t)(d+2) * L_ + k0 + kk2];
            uint16_t q3 = Kp[(size_t)(d+3) * L_ + k0 + kk2];
            uint2 wv;
            wv.x = (uint32_t)q0 | ((uint32_t)q1 << 16);
            wv.y = (uint32_t)q2 | ((uint32_t)q3 << 16);
            *(uint2*)&Kb[kk2 * APt + d] = wv;
        }
    };
    // V direct cp.async into buffer `buf` (64 d-rows x 64 k = 8 chunks/row)
    auto load_V = [&](int k0, int buf) {
        uint32_t base = VsB + buf * 64 * APt * 2;
#pragma unroll
        for (int t = 0; t < 2; t++) {
            int idx = tid + t * 256;          // 0..511
            int d = idx >> 3, k8 = idx & 7;
            CP16(base + d * 144 + k8 * 16, &Vp[(size_t)d * L_ + k0 + k8 * 8]);
        }
    };

    // ---- prologue: Q + tile 0 ----
    {
        int qq = lane + 32 * (wp & 3);
        int d0 = (wp >> 2) * 4;
#pragma unroll
        for (int r = 0; r < 8; r++) {
            int d = d0 + 8 * r;
            uint16_t q0 = Qp[(size_t)(d+0) * L_ + l0 + qq];
            uint16_t q1 = Qp[(size_t)(d+1) * L_ + l0 + qq];
            uint16_t q2 = Qp[(size_t)(d+2) * L_ + l0 + qq];
            uint16_t q3 = Qp[(size_t)(d+3) * L_ + l0 + qq];
            uint2 wv;
            wv.x = (uint32_t)q0 | ((uint32_t)q1 << 16);
            wv.y = (uint32_t)q2 | ((uint32_t)q3 << 16);
            *(uint2*)&Qs[qq * APt + d] = wv;
        }
    }
    load_K(0, 0);
    load_V(0, 0);
    CP_COMMIT();
    CP_WAIT0();
    __syncthreads();

    float oacc[8][4];
#pragma unroll
    for (int nt = 0; nt < 8; nt++)
#pragma unroll
        for (int r = 0; r < 4; r++) oacc[nt][r] = 0.f;
    float rsum0 = 0.f, rsum1 = 0.f;

    for (int kt = 0; kt < 16; kt++) {
        int cur = kt & 1;
        if (kt < 15) {
            load_K((kt + 1) * 64, cur ^ 1);
            load_V((kt + 1) * 64, cur ^ 1);
            CP_COMMIT();
        }
        uint32_t KbB = KsB + cur * 64 * APt * 2;
        uint32_t VbB = VsB + cur * 64 * APt * 2;

        // S = Q K^T
        float sacc[8][4];
#pragma unroll
        for (int nt = 0; nt < 8; nt++)
#pragma unroll
            for (int r = 0; r < 4; r++) sacc[nt][r] = 0.f;
#pragma unroll
        for (int kc = 0; kc < 4; kc++) {
            int kb = kc * 32 + khal;
            uint32_t af[4];
            ldsm_x4(af, QsB + (qb + l15) * 144 + kb);
#pragma unroll
            for (int ng = 0; ng < 4; ng++) {
                uint32_t rr[4];
                ldsm_x4(rr, KbB + (ng * 16 + l15) * 144 + kb);
                mma_bf16(sacc[2*ng],   af, rr[0], rr[2]);
                mma_bf16(sacc[2*ng+1], af, rr[1], rr[3]);
            }
        }

        // P = exp2(S * SC)
#pragma unroll
        for (int nt = 0; nt < 8; nt++) {
            float p0 = ex2f(sacc[nt][0] * SC);
            float p1 = ex2f(sacc[nt][1] * SC);
            float p2 = ex2f(sacc[nt][2] * SC);
            float p3 = ex2f(sacc[nt][3] * SC);
            rsum0 += p0 + p1;
            rsum1 += p2 + p3;
            *(uint32_t*)&Ps[(qb + g)     * APt + nt*8 + 2*t4] = f2bf2(p0, p1);
            *(uint32_t*)&Ps[(qb + g + 8) * APt + nt*8 + 2*t4] = f2bf2(p2, p3);
        }
        __syncwarp();

        // O += P V
#pragma unroll
        for (int kc = 0; kc < 4; kc++) {
            int kb = kc * 32 + khal;
            uint32_t af[4];
            ldsm_x4(af, PsB + (qb + l15) * 144 + kb);
#pragma unroll
            for (int ng = 0; ng < 4; ng++) {
                uint32_t rr[4];
                ldsm_x4(rr, VbB + (ng * 16 + l15) * 144 + kb);
                mma_bf16(oacc[2*ng],   af, rr[0], rr[2]);
                mma_bf16(oacc[2*ng+1], af, rr[1], rr[3]);
            }
        }
        CP_WAIT0();
        __syncthreads();
    }

    rsum0 += __shfl_xor_sync(0xFFFFFFFFu, rsum0, 1);
    rsum0 += __shfl_xor_sync(0xFFFFFFFFu, rsum0, 2);
    rsum1 += __shfl_xor_sync(0xFFFFFFFFu, rsum1, 1);
    rsum1 += __shfl_xor_sync(0xFFFFFFFFu, rsum1, 2);
    float inv0 = 1.f / rsum0;
    float inv1 = 1.f / rsum1;

    size_t row0 = ((size_t)b * L_ + l0 + qb + g)     * C_ + h * HD_;
    size_t row1 = ((size_t)b * L_ + l0 + qb + g + 8) * C_ + h * HD_;
#pragma unroll
    for (int nt = 0; nt < 8; nt++) {
        int c = nt * 8 + 2 * t4;
        *(uint32_t*)&g_at[row0 + c] = f2bf2(oacc[nt][0] * inv0, oacc[nt][1] * inv0);
        *(uint32_t*)&g_at[row1 + c] = f2bf2(oacc[nt][2] * inv1, oacc[nt][3] * inv1);
    }
}

// ---------------------------------------------------------------------------
extern "C" void kernel_launch(void* const* d_in, const int* in_sizes, int n_in,
                              void* d_out, int out_size)
{
    const float* x      = (const float*)d_in[0];
    const float* norm_w = (const float*)d_in[1];
    const float* norm_b = (const float*)d_in[2];
    const float* qkv_w  = (const float*)d_in[3];
    const float* qkv_b  = (const float*)d_in[4];
    const float* proj_w = (const float*)d_in[5];
    const float* proj_b = (const float*)d_in[6];
    float* out = (float*)d_out;

    cudaFuncSetAttribute(attn_kernel,
                         cudaFuncAttributeMaxDynamicSharedMemorySize, ATT_BYTES);
    cudaFuncSetAttribute(qkv_gemm_kernel,
                         cudaFuncAttributeMaxDynamicSharedMemorySize, GSMEM_BYTES);
    cudaFuncSetAttribute(proj_gemm_kernel,
                         cudaFuncAttributeMaxDynamicSharedMemorySize, GSMEM_BYTES);

    gn_kernel<<<1536, 256>>>(x, norm_w, norm_b, qkv_w, proj_w);

    {
        dim3 grid(L_ / 128, M_QKV / 128, B_);
        qkv_gemm_kernel<<<grid, 256, GSMEM_BYTES>>>(qkv_b);
    }
    {
        dim3 grid(L_ / 128, B_ * NH_);
        attn_kernel<<<grid, 256, ATT_BYTES>>>();
    }
    {
        dim3 grid(L_ / 128, C_ / 128, B_);
        proj_gemm_kernel<<<grid, 256, GSMEM_BYTES>>>(proj_b, x, out);
    }
}

// round 10
// speedup vs baseline: 7.6861x; 1.0965x over previous
#include <cuda_runtime.h>
#include <math.h>
#include <stdint.h>

#define B_   16
#define C_   512
#define L_   1024
#define NH_  8
#define HD_  64
#define NG_  32
#define GCH_ 16
#define M_QKV 1536
#define EPS_ 1e-5f

// Scratch (device globals)
__device__ uint16_t g_h   [(size_t)B_ * L_ * C_];     // groupnorm out bf16 [B][L][C]
__device__ uint16_t g_qkvh[(size_t)B_ * M_QKV * L_];  // qkv bf16 [B][3C][L]
__device__ uint16_t g_at  [(size_t)B_ * L_ * C_];     // attention out bf16 [B][L][C]
__device__ uint16_t g_wq  [(size_t)M_QKV * C_];       // qkv_w bf16
__device__ uint16_t g_wp  [(size_t)C_ * C_];          // proj_w bf16

__device__ __forceinline__ uint32_t smem_u32(const void* p){
    uint32_t a;
    asm("{ .reg .u64 t; cvta.to.shared.u64 t, %1; cvt.u32.u64 %0, t; }" : "=r"(a) : "l"(p));
    return a;
}
__device__ __forceinline__ uint32_t f2bf2(float lo, float hi){
    uint32_t r; asm("cvt.rn.bf16x2.f32 %0, %1, %2;" : "=r"(r) : "f"(hi), "f"(lo)); return r;
}
__device__ __forceinline__ float ex2f(float x){
    float r; asm("ex2.approx.ftz.f32 %0, %1;" : "=f"(r) : "f"(x)); return r;
}
__device__ __forceinline__ void ldsm_x4(uint32_t* r, uint32_t addr){
    asm volatile("ldmatrix.sync.aligned.m8n8.x4.shared.b16 {%0,%1,%2,%3}, [%4];"
        : "=r"(r[0]), "=r"(r[1]), "=r"(r[2]), "=r"(r[3]) : "r"(addr));
}
__device__ __forceinline__ void ldsm_x4_t(uint32_t* r, uint32_t addr){
    asm volatile("ldmatrix.sync.aligned.m8n8.x4.trans.shared.b16 {%0,%1,%2,%3}, [%4];"
        : "=r"(r[0]), "=r"(r[1]), "=r"(r[2]), "=r"(r[3]) : "r"(addr));
}
__device__ __forceinline__ void mma_bf16(float* d, const uint32_t* a,
                                         uint32_t b0, uint32_t b1){
    asm volatile(
        "mma.sync.aligned.m16n8k16.row.col.f32.bf16.bf16.f32 "
        "{%0,%1,%2,%3}, {%4,%5,%6,%7}, {%8,%9}, {%0,%1,%2,%3};"
        : "+f"(d[0]), "+f"(d[1]), "+f"(d[2]), "+f"(d[3])
        : "r"(a[0]), "r"(a[1]), "r"(a[2]), "r"(a[3]), "r"(b0), "r"(b1));
}
#define CP16(dst, src) \
    asm volatile("cp.async.cg.shared.global [%0], [%1], 16;" :: "r"(dst), "l"(src))
#define CP_COMMIT() asm volatile("cp.async.commit_group;" ::: "memory")
#define CP_WAIT0()  asm volatile("cp.async.wait_group 0;" ::: "memory")

// ---------------------------------------------------------------------------
// Fused GroupNorm + weight conversion.
// blocks [0,512): GN fp32 [B][C][L] -> bf16 [B][L][C]
// blocks [512,1536): convert qkv_w / proj_w to bf16
// ---------------------------------------------------------------------------
#define N4Q (M_QKV * C_ / 4)
#define N4P (C_ * C_ / 4)

__global__ void gn_kernel(const float* __restrict__ x,
                          const float* __restrict__ w,
                          const float* __restrict__ bn,
                          const float* __restrict__ qkv_w,
                          const float* __restrict__ proj_w)
{
    int tid = threadIdx.x;
    if (blockIdx.x >= 512) {
        int i = (blockIdx.x - 512) * 256 + tid;
        const float4* src;
        uint2* dst;
        if (i < N4Q) { src = (const float4*)qkv_w + i;        dst = (uint2*)g_wq + i; }
        else         { src = (const float4*)proj_w + (i-N4Q); dst = (uint2*)g_wp + (i-N4Q); }
        float4 v = *src;
        uint2 o;
        o.x = f2bf2(v.x, v.y);
        o.y = f2bf2(v.z, v.w);
        *dst = o;
        return;
    }

    int gb  = blockIdx.x;
    int b   = gb >> 5;
    int grp = gb & 31;
    const float4* xp4 = (const float4*)(x + ((size_t)b * C_ + (size_t)grp * GCH_) * L_);

    float s = 0.f, s2 = 0.f;
#pragma unroll 4
    for (int i = tid; i < 4096; i += 256) {
        float4 v = xp4[i];
        s  += v.x + v.y + v.z + v.w;
        s2 += v.x*v.x + v.y*v.y + v.z*v.z + v.w*v.w;
    }
    __shared__ float sh[512];
    sh[tid] = s; sh[256 + tid] = s2;
    __syncthreads();
    for (int off = 128; off > 0; off >>= 1) {
        if (tid < off) { sh[tid] += sh[tid + off]; sh[256 + tid] += sh[256 + tid + off]; }
        __syncthreads();
    }
    __shared__ float s_mean, s_inv;
    if (tid == 0) {
        float mean = sh[0] * (1.f / (GCH_ * L_));
        float var  = sh[256] * (1.f / (GCH_ * L_)) - mean * mean;
        s_mean = mean;
        s_inv  = rsqrtf(var + EPS_);
    }
    __syncthreads();
    float mean = s_mean, inv = s_inv;

    __shared__ float tile[16][257];
    for (int ch = 0; ch < 4; ch++) {
        int lb = ch * 256;
#pragma unroll
        for (int t = 0; t < 4; t++) {
            int idx = tid + t * 256;
            int c = idx >> 6, l4 = idx & 63;
            float4 v = xp4[c * 256 + (lb >> 2) + l4];
            float wc = w[grp * GCH_ + c], bc = bn[grp * GCH_ + c];
            tile[c][l4*4+0] = (v.x - mean) * inv * wc + bc;
            tile[c][l4*4+1] = (v.y - mean) * inv * wc + bc;
            tile[c][l4*4+2] = (v.z - mean) * inv * wc + bc;
            tile[c][l4*4+3] = (v.w - mean) * inv * wc + bc;
        }
        __syncthreads();
#pragma unroll
        for (int t = 0; t < 4; t++) {
            int idx = tid + t * 256;
            int l = idx >> 2, cq = idx & 3;
            uint2 o;
            o.x = f2bf2(tile[cq*4+0][l], tile[cq*4+1][l]);
            o.y = f2bf2(tile[cq*4+2][l], tile[cq*4+3][l]);
            *(uint2*)&g_h[((size_t)b * L_ + lb + l) * C_ + grp * GCH_ + cq * 4] = o;
        }
        __syncthreads();
    }
}

// ---------------------------------------------------------------------------
// bf16 GEMM, BK=64, 2-stage cp.async, ONE barrier per iter.
// D[o0+m][l0+n] = sum_c A[o][c]*Bg[l][c]; tile 128x128, 8 warps (2m x 4n).
// MODE 0: store bf16 (qkv). MODE 1: fp32 + residual (proj).
// ---------------------------------------------------------------------------
#define GP 72                        // smem pitch bf16 (64 data + 8 pad)
#define GSTG (128 * GP)              // bf16 per matrix per stage
#define STAGE_B (2 * GSTG * 2)       // bytes per stage (A+B) = 36864
#define GSMEM_BYTES (2 * STAGE_B)    // 73728

template <int MODE>
__device__ __forceinline__ void gemm_mma(const uint16_t* __restrict__ Aw,
                                         const float* __restrict__ bias,
                                         const uint16_t* __restrict__ Bg,
                                         const float* __restrict__ res,
                                         float* __restrict__ Cf,
                                         uint16_t* __restrict__ Ch)
{
    extern __shared__ uint16_t smh[];
    uint32_t smb = smem_u32(smh);
    int tid  = threadIdx.x;
    int wid  = tid >> 5, lane = tid & 31;
    int g    = lane >> 2, t4 = lane & 3;
    int wm   = wid & 1;
    int wn   = wid >> 1;
    int o0   = blockIdx.y * 128;
    int l0   = blockIdx.x * 128;
    int mb   = wm * 64;
    int nb   = wn * 32;
    int l15  = lane & 15;
    int khal = (lane >> 4) * 16;

    float acc[4][4][4];
#pragma unroll
    for (int mt = 0; mt < 4; mt++)
#pragma unroll
        for (int nt = 0; nt < 4; nt++)
#pragma unroll
            for (int r = 0; r < 4; r++) acc[mt][nt][r] = 0.f;

    auto issue = [&](int st, int c0) {
        uint32_t base = smb + st * STAGE_B;
#pragma unroll
        for (int t = 0; t < 4; t++) {
            int idx = tid + t * 256;             // 0..1023
            int row = idx >> 3, c = idx & 7;
            CP16(base + row * 144 + c * 16,
                 &Aw[(size_t)(o0 + row) * C_ + c0 + c * 8]);
            CP16(base + GSTG * 2 + row * 144 + c * 16,
                 &Bg[(size_t)(l0 + row) * C_ + c0 + c * 8]);
        }
    };

    issue(0, 0);  CP_COMMIT();

    for (int it = 0; it < 8; ++it) {
        CP_WAIT0();
        __syncthreads();
        if (it < 7) { issue((it + 1) & 1, (it + 1) * 64); CP_COMMIT(); }

        uint32_t AsB = smb + (it & 1) * STAGE_B;
        uint32_t BsB = AsB + GSTG * 2;
#pragma unroll
        for (int ks = 0; ks < 4; ks++) {
            int kb = ks * 32 + khal;
            uint32_t af[4][4];
#pragma unroll
            for (int mt = 0; mt < 4; mt++)
                ldsm_x4(af[mt], AsB + (mb + mt * 16 + l15) * 144 + kb);
            uint32_t bf[4][2];
#pragma unroll
            for (int ng = 0; ng < 2; ng++) {
                uint32_t rr[4];
                ldsm_x4(rr, BsB + (nb + ng * 16 + l15) * 144 + kb);
                bf[2*ng][0]   = rr[0]; bf[2*ng][1]   = rr[2];
                bf[2*ng+1][0] = rr[1]; bf[2*ng+1][1] = rr[3];
            }
#pragma unroll
            for (int mt = 0; mt < 4; mt++)
#pragma unroll
                for (int nt = 0; nt < 4; nt++)
                    mma_bf16(acc[mt][nt], af[mt], bf[nt][0], bf[nt][1]);
        }
    }

#pragma unroll
    for (int mt = 0; mt < 4; mt++) {
        int r0 = o0 + mb + mt * 16 + g;
        int r1 = r0 + 8;
        float bv0 = bias[r0], bv1 = bias[r1];
#pragma unroll
        for (int nt = 0; nt < 4; nt++) {
            int col = l0 + nb + nt * 8 + 2 * t4;
            size_t a0 = (size_t)r0 * L_ + col;
            size_t a1 = (size_t)r1 * L_ + col;
            float v00 = acc[mt][nt][0] + bv0, v01 = acc[mt][nt][1] + bv0;
            float v10 = acc[mt][nt][2] + bv1, v11 = acc[mt][nt][3] + bv1;
            if (MODE == 0) {
                *(uint32_t*)&Ch[a0] = f2bf2(v00, v01);
                *(uint32_t*)&Ch[a1] = f2bf2(v10, v11);
            } else {
                float2 q0 = *(const float2*)&res[a0];
                float2 q1 = *(const float2*)&res[a1];
                float2 w0, w1;
                w0.x = v00 + q0.x; w0.y = v01 + q0.y;
                w1.x = v10 + q1.x; w1.y = v11 + q1.y;
                *(float2*)&Cf[a0] = w0;
                *(float2*)&Cf[a1] = w1;
            }
        }
    }
}

__global__ __launch_bounds__(256)
void qkv_gemm_kernel(const float* __restrict__ qkv_b)
{
    int b = blockIdx.z;
    gemm_mma<0>(g_wq, qkv_b,
                g_h + (size_t)b * L_ * C_,
                nullptr, nullptr,
                g_qkvh + (size_t)b * M_QKV * L_);
}

__global__ __launch_bounds__(256)
void proj_gemm_kernel(const float* __restrict__ proj_b,
                      const float* __restrict__ x,
                      float* __restrict__ out)
{
    int b = blockIdx.z;
    gemm_mma<1>(g_wp, proj_b,
                g_at + (size_t)b * L_ * C_,
                x   + (size_t)b * C_ * L_,
                out + (size_t)b * C_ * L_,
                nullptr);
}

// ---------------------------------------------------------------------------
// bf16 tensor-core flash attention (no-max softmax).
// All tile loads are direct cp.async in native [d][l] layout;
// transposes happen in ldmatrix.trans. One barrier per k-tile.
// Smem: Qd[64][136] (d,q), Kd 2x[64][72] (d,k), Vd 2x[64][72] (d,k), P[128][72].
// ---------------------------------------------------------------------------
#define QPITCH 136                     // halves (128 q + 8 pad)
#define KVPITCH 72                     // halves (64 k + 8 pad)
#define AQo 0
#define AKo (64 * QPITCH)                          // 8704
#define AVo (AKo + 2 * 64 * KVPITCH)               // 17920
#define APo (AVo + 2 * 64 * KVPITCH)               // 27136
#define ATT_BF16 (APo + 128 * KVPITCH)             // 36352
#define ATT_BYTES (ATT_BF16 * 2)                   // 72704

__global__ __launch_bounds__(256, 2)
void attn_kernel()
{
    int bh = blockIdx.y;
    int b = bh >> 3, h = bh & 7;
    int l0 = blockIdx.x * 128;

    const uint16_t* Qp = g_qkvh + ((size_t)b * M_QKV + 0 * C_ + h * HD_) * L_;
    const uint16_t* Kp = g_qkvh + ((size_t)b * M_QKV + 1 * C_ + h * HD_) * L_;
    const uint16_t* Vp = g_qkvh + ((size_t)b * M_QKV + 2 * C_ + h * HD_) * L_;

    extern __shared__ uint16_t smh[];
    uint32_t smb = smem_u32(smh);
    uint16_t* Ps = smh + APo;
    uint32_t QsB = smb + AQo * 2, KsB = smb + AKo * 2;
    uint32_t VsB = smb + AVo * 2, PsB = smb + APo * 2;

    int tid  = threadIdx.x;
    int lane = tid & 31, wp = tid >> 5;
    int g = lane >> 2, t4 = lane & 3;
    int qb = wp * 16;
    int l15 = lane & 15;
    int khal = (lane >> 4) * 16;

    const float SC = 0.125f * 1.44269504088896340736f;

    // trans-LDSM addressing components
    int a_row = (lane & 7) + ((lane >> 4) << 3);        // A-frag: row-sel per lane
    int a_col = ((lane >> 3) & 1) * 16;                 // A-frag: col byte sel
    int b_row = (lane & 7) + (((lane >> 3) & 1) << 3);  // B-frag: row-sel per lane
    int b_col = (lane >> 4) * 16;                       // B-frag: col byte sel

    // Q [d][q] direct cp.async: 64 rows x 16 chunks
    auto load_Q = [&]() {
#pragma unroll
        for (int t = 0; t < 4; t++) {
            int idx = tid + t * 256;          // 0..1023
            int d = idx >> 4, c = idx & 15;
            CP16(QsB + d * (QPITCH*2) + c * 16, &Qp[(size_t)d * L_ + l0 + c * 8]);
        }
    };
    // K/V [d][k] direct cp.async: 64 rows x 8 chunks
    auto load_K = [&](int k0, int buf) {
        uint32_t base = KsB + buf * 64 * KVPITCH * 2;
#pragma unroll
        for (int t = 0; t < 2; t++) {
            int idx = tid + t * 256;
            int d = idx >> 3, c = idx & 7;
            CP16(base + d * (KVPITCH*2) + c * 16, &Kp[(size_t)d * L_ + k0 + c * 8]);
        }
    };
    auto load_V = [&](int k0, int buf) {
        uint32_t base = VsB + buf * 64 * KVPITCH * 2;
#pragma unroll
        for (int t = 0; t < 2; t++) {
            int idx = tid + t * 256;
            int d = idx >> 3, c = idx & 7;
            CP16(base + d * (KVPITCH*2) + c * 16, &Vp[(size_t)d * L_ + k0 + c * 8]);
        }
    };

    load_Q();
    load_K(0, 0);
    load_V(0, 0);
    CP_COMMIT();
    CP_WAIT0();
    __syncthreads();

    float oacc[8][4];
#pragma unroll
    for (int nt = 0; nt < 8; nt++)
#pragma unroll
        for (int r = 0; r < 4; r++) oacc[nt][r] = 0.f;
    float rsum0 = 0.f, rsum1 = 0.f;

    for (int kt = 0; kt < 16; kt++) {
        int cur = kt & 1;
        if (kt < 15) {
            load_K((kt + 1) * 64, cur ^ 1);
            load_V((kt + 1) * 64, cur ^ 1);
            CP_COMMIT();
        }
        uint32_t KbB = KsB + cur * 64 * KVPITCH * 2;
        uint32_t VbB = VsB + cur * 64 * KVPITCH * 2;

        // S = Q K^T : A via trans-LDSM on Qd[d][q], B via trans-LDSM on Kd[d][k]
        float sacc[8][4];
#pragma unroll
        for (int nt = 0; nt < 8; nt++)
#pragma unroll
            for (int r = 0; r < 4; r++) sacc[nt][r] = 0.f;
#pragma unroll
        for (int kc = 0; kc < 4; kc++) {
            uint32_t af[4];
            ldsm_x4_t(af, QsB + (kc * 16 + a_row) * (QPITCH*2) + qb * 2 + a_col);
#pragma unroll
            for (int ng = 0; ng < 4; ng++) {
                uint32_t rr[4];
                ldsm_x4_t(rr, KbB + (kc * 16 + b_row) * (KVPITCH*2) + ng * 32 + b_col);
                mma_bf16(sacc[2*ng],   af, rr[0], rr[1]);
                mma_bf16(sacc[2*ng+1], af, rr[2], rr[3]);
            }
        }

        // P = exp2(S * SC), row sums, store bf16 (warp-private strip)
#pragma unroll
        for (int nt = 0; nt < 8; nt++) {
            float p0 = ex2f(sacc[nt][0] * SC);
            float p1 = ex2f(sacc[nt][1] * SC);
            float p2 = ex2f(sacc[nt][2] * SC);
            float p3 = ex2f(sacc[nt][3] * SC);
            rsum0 += p0 + p1;
            rsum1 += p2 + p3;
            *(uint32_t*)&Ps[(qb + g)     * KVPITCH + nt*8 + 2*t4] = f2bf2(p0, p1);
            *(uint32_t*)&Ps[(qb + g + 8) * KVPITCH + nt*8 + 2*t4] = f2bf2(p2, p3);
        }
        __syncwarp();

        // O += P V : A non-trans on P[q][k], B non-trans on Vd[d][k]
#pragma unroll
        for (int kc = 0; kc < 4; kc++) {
            int kb = kc * 32 + khal;
            uint32_t af[4];
            ldsm_x4(af, PsB + (qb + l15) * (KVPITCH*2) + kb);
#pragma unroll
            for (int ng = 0; ng < 4; ng++) {
                uint32_t rr[4];
                ldsm_x4(rr, VbB + (ng * 16 + l15) * (KVPITCH*2) + kb);
                mma_bf16(oacc[2*ng],   af, rr[0], rr[2]);
                mma_bf16(oacc[2*ng+1], af, rr[1], rr[3]);
            }
        }
        CP_WAIT0();
        __syncthreads();
    }

    rsum0 += __shfl_xor_sync(0xFFFFFFFFu, rsum0, 1);
    rsum0 += __shfl_xor_sync(0xFFFFFFFFu, rsum0, 2);
    rsum1 += __shfl_xor_sync(0xFFFFFFFFu, rsum1, 1);
    rsum1 += __shfl_xor_sync(0xFFFFFFFFu, rsum1, 2);
    float inv0 = 1.f / rsum0;
    float inv1 = 1.f / rsum1;

    size_t row0 = ((size_t)b * L_ + l0 + qb + g)     * C_ + h * HD_;
    size_t row1 = ((size_t)b * L_ + l0 + qb + g + 8) * C_ + h * HD_;
#pragma unroll
    for (int nt = 0; nt < 8; nt++) {
        int c = nt * 8 + 2 * t4;
        *(uint32_t*)&g_at[row0 + c] = f2bf2(oacc[nt][0] * inv0, oacc[nt][1] * inv0);
        *(uint32_t*)&g_at[row1 + c] = f2bf2(oacc[nt][2] * inv1, oacc[nt][3] * inv1);
    }
}

// ---------------------------------------------------------------------------
extern "C" void kernel_launch(void* const* d_in, const int* in_sizes, int n_in,
                              void* d_out, int out_size)
{
    const float* x      = (const float*)d_in[0];
    const float* norm_w = (const float*)d_in[1];
    const float* norm_b = (const float*)d_in[2];
    const float* qkv_w  = (const float*)d_in[3];
    const float* qkv_b  = (const float*)d_in[4];
    const float* proj_w = (const float*)d_in[5];
    const float* proj_b = (const float*)d_in[6];
    float* out = (float*)d_out;

    cudaFuncSetAttribute(attn_kernel,
                         cudaFuncAttributeMaxDynamicSharedMemorySize, ATT_BYTES);
    cudaFuncSetAttribute(qkv_gemm_kernel,
                         cudaFuncAttributeMaxDynamicSharedMemorySize, GSMEM_BYTES);
    cudaFuncSetAttribute(proj_gemm_kernel,
                         cudaFuncAttributeMaxDynamicSharedMemorySize, GSMEM_BYTES);

    gn_kernel<<<1536, 256>>>(x, norm_w, norm_b, qkv_w, proj_w);

    {
        dim3 grid(L_ / 128, M_QKV / 128, B_);
        qkv_gemm_kernel<<<grid, 256, GSMEM_BYTES>>>(qkv_b);
    }
    {
        dim3 grid(L_ / 128, B_ * NH_);
        attn_kernel<<<grid, 256, ATT_BYTES>>>();
    }
    {
        dim3 grid(L_ / 128, C_ / 128, B_);
        proj_gemm_kernel<<<grid, 256, GSMEM_BYTES>>>(proj_b, x, out);
    }
}

// round 11
// speedup vs baseline: 8.0461x; 1.0468x over previous
#include <cuda_runtime.h>
#include <math.h>
#include <stdint.h>

#define B_   16
#define C_   512
#define L_   1024
#define NH_  8
#define HD_  64
#define NG_  32
#define GCH_ 16
#define M_QKV 1536
#define EPS_ 1e-5f

// Scratch (device globals)
__device__ uint16_t g_h   [(size_t)B_ * L_ * C_];     // groupnorm out bf16 [B][L][C]
__device__ uint16_t g_qkvh[(size_t)B_ * M_QKV * L_];  // qkv bf16 [B][3C][L]
__device__ uint16_t g_at  [(size_t)B_ * L_ * C_];     // attention out bf16 [B][L][C]
__device__ uint16_t g_wq  [(size_t)M_QKV * C_];       // qkv_w bf16
__device__ uint16_t g_wp  [(size_t)C_ * C_];          // proj_w bf16

__device__ __forceinline__ uint32_t smem_u32(const void* p){
    uint32_t a;
    asm("{ .reg .u64 t; cvta.to.shared.u64 t, %1; cvt.u32.u64 %0, t; }" : "=r"(a) : "l"(p));
    return a;
}
__device__ __forceinline__ uint32_t f2bf2(float lo, float hi){
    uint32_t r; asm("cvt.rn.bf16x2.f32 %0, %1, %2;" : "=r"(r) : "f"(hi), "f"(lo)); return r;
}
__device__ __forceinline__ float ex2f(float x){
    float r; asm("ex2.approx.ftz.f32 %0, %1;" : "=f"(r) : "f"(x)); return r;
}
__device__ __forceinline__ void ldsm_x4(uint32_t* r, uint32_t addr){
    asm volatile("ldmatrix.sync.aligned.m8n8.x4.shared.b16 {%0,%1,%2,%3}, [%4];"
        : "=r"(r[0]), "=r"(r[1]), "=r"(r[2]), "=r"(r[3]) : "r"(addr));
}
__device__ __forceinline__ void ldsm_x4_t(uint32_t* r, uint32_t addr){
    asm volatile("ldmatrix.sync.aligned.m8n8.x4.trans.shared.b16 {%0,%1,%2,%3}, [%4];"
        : "=r"(r[0]), "=r"(r[1]), "=r"(r[2]), "=r"(r[3]) : "r"(addr));
}
__device__ __forceinline__ void mma_bf16(float* d, const uint32_t* a,
                                         uint32_t b0, uint32_t b1){
    asm volatile(
        "mma.sync.aligned.m16n8k16.row.col.f32.bf16.bf16.f32 "
        "{%0,%1,%2,%3}, {%4,%5,%6,%7}, {%8,%9}, {%0,%1,%2,%3};"
        : "+f"(d[0]), "+f"(d[1]), "+f"(d[2]), "+f"(d[3])
        : "r"(a[0]), "r"(a[1]), "r"(a[2]), "r"(a[3]), "r"(b0), "r"(b1));
}
#define CP16(dst, src) \
    asm volatile("cp.async.cg.shared.global [%0], [%1], 16;" :: "r"(dst), "l"(src))
#define CP_COMMIT() asm volatile("cp.async.commit_group;" ::: "memory")
#define CP_WAIT0()  asm volatile("cp.async.wait_group 0;" ::: "memory")

// ---------------------------------------------------------------------------
// Fused GroupNorm (single global pass, smem-cached) + weight conversion.
// blocks [0,512): GN; blocks [512,1536): convert weights to bf16.
// ---------------------------------------------------------------------------
#define N4Q (M_QKV * C_ / 4)
#define N4P (C_ * C_ / 4)
#define GNP 257                       // float4 pitch per channel row (1028 floats)
#define GN_SMEM (16 * GNP * 16)       // bytes: 16 ch * 257 float4 * 16B = 65792

__global__ void gn_kernel(const float* __restrict__ x,
                          const float* __restrict__ w,
                          const float* __restrict__ bn,
                          const float* __restrict__ qkv_w,
                          const float* __restrict__ proj_w)
{
    int tid = threadIdx.x;
    if (blockIdx.x >= 512) {
        int i = (blockIdx.x - 512) * 256 + tid;
        const float4* src;
        uint2* dst;
        if (i < N4Q) { src = (const float4*)qkv_w + i;        dst = (uint2*)g_wq + i; }
        else         { src = (const float4*)proj_w + (i-N4Q); dst = (uint2*)g_wp + (i-N4Q); }
        float4 v = *src;
        uint2 o;
        o.x = f2bf2(v.x, v.y);
        o.y = f2bf2(v.z, v.w);
        *dst = o;
        return;
    }

    extern __shared__ float xs[];     // [16][1028] floats (pitch 257 float4)
    float4* xs4 = (float4*)xs;

    int gb  = blockIdx.x;
    int b   = gb >> 5;
    int grp = gb & 31;
    const float4* xp4 = (const float4*)(x + ((size_t)b * C_ + (size_t)grp * GCH_) * L_);

    float s = 0.f, s2 = 0.f;
#pragma unroll 4
    for (int i = tid; i < 4096; i += 256) {
        float4 v = xp4[i];
        xs4[(i >> 8) * GNP + (i & 255)] = v;
        s  += v.x + v.y + v.z + v.w;
        s2 += v.x*v.x + v.y*v.y + v.z*v.z + v.w*v.w;
    }
    __shared__ float sh[512];
    sh[tid] = s; sh[256 + tid] = s2;
    __syncthreads();
    for (int off = 128; off > 0; off >>= 1) {
        if (tid < off) { sh[tid] += sh[tid + off]; sh[256 + tid] += sh[256 + tid + off]; }
        __syncthreads();
    }
    __shared__ float sA[16], sB[16];
    if (tid == 0) {
        float mean = sh[0] * (1.f / (GCH_ * L_));
        float var  = sh[256] * (1.f / (GCH_ * L_)) - mean * mean;
        sh[0] = mean;
        sh[1] = rsqrtf(var + EPS_);
    }
    __syncthreads();
    if (tid < 16) {
        float mean = sh[0], inv = sh[1];
        float wc = w[grp * GCH_ + tid], bc = bn[grp * GCH_ + tid];
        sA[tid] = inv * wc;
        sB[tid] = bc - mean * inv * wc;
    }
    __syncthreads();

    // write-out: (l, cq) -> g_h[b][l][grp*16 + cq*4 .. +3], cq fastest (coalesced)
#pragma unroll
    for (int t = 0; t < 16; t++) {
        int idx = tid + t * 256;      // 0..4095
        int l = idx >> 2, cq = idx & 3;
        int c0 = cq * 4;
        float v0 = xs[(c0+0) * (GNP*4) + l] * sA[c0+0] + sB[c0+0];
        float v1 = xs[(c0+1) * (GNP*4) + l] * sA[c0+1] + sB[c0+1];
        float v2 = xs[(c0+2) * (GNP*4) + l] * sA[c0+2] + sB[c0+2];
        float v3 = xs[(c0+3) * (GNP*4) + l] * sA[c0+3] + sB[c0+3];
        uint2 o;
        o.x = f2bf2(v0, v1);
        o.y = f2bf2(v2, v3);
        *(uint2*)&g_h[((size_t)b * L_ + l) * C_ + grp * GCH_ + c0] = o;
    }
}

// ---------------------------------------------------------------------------
// bf16 GEMM, BK=64, 2-stage cp.async, 128 threads = 4 warps (2m x 2n),
// warp tile 64x64 (halved smem-fragment redundancy).
// D[o0+m][l0+n] = sum_c A[o][c]*Bg[l][c]; tile 128x128.
// MODE 0: store bf16 (qkv). MODE 1: fp32 + residual (proj).
// ---------------------------------------------------------------------------
#define GP 72                        // smem pitch bf16 (64 data + 8 pad)
#define GSTG (128 * GP)              // bf16 per matrix per stage
#define STAGE_B (2 * GSTG * 2)       // bytes per stage (A+B) = 36864
#define GSMEM_BYTES (2 * STAGE_B)    // 73728

template <int MODE>
__device__ __forceinline__ void gemm_mma(const uint16_t* __restrict__ Aw,
                                         const float* __restrict__ bias,
                                         const uint16_t* __restrict__ Bg,
                                         const float* __restrict__ res,
                                         float* __restrict__ Cf,
                                         uint16_t* __restrict__ Ch)
{
    extern __shared__ uint16_t smh[];
    uint32_t smb = smem_u32(smh);
    int tid  = threadIdx.x;          // 0..127
    int wid  = tid >> 5, lane = tid & 31;
    int g    = lane >> 2, t4 = lane & 3;
    int wm   = wid & 1;
    int wn   = wid >> 1;
    int o0   = blockIdx.y * 128;
    int l0   = blockIdx.x * 128;
    int mb   = wm * 64;
    int nb   = wn * 64;
    int l15  = lane & 15;
    int khal = (lane >> 4) * 16;

    float acc[4][8][4];
#pragma unroll
    for (int mt = 0; mt < 4; mt++)
#pragma unroll
        for (int nt = 0; nt < 8; nt++)
#pragma unroll
            for (int r = 0; r < 4; r++) acc[mt][nt][r] = 0.f;

    auto issue = [&](int st, int c0) {
        uint32_t base = smb + st * STAGE_B;
#pragma unroll
        for (int t = 0; t < 8; t++) {
            int idx = tid + t * 128;             // 0..1023
            int row = idx >> 3, c = idx & 7;
            CP16(base + row * 144 + c * 16,
                 &Aw[(size_t)(o0 + row) * C_ + c0 + c * 8]);
            CP16(base + GSTG * 2 + row * 144 + c * 16,
                 &Bg[(size_t)(l0 + row) * C_ + c0 + c * 8]);
        }
    };

    issue(0, 0);  CP_COMMIT();

    for (int it = 0; it < 8; ++it) {
        CP_WAIT0();
        __syncthreads();
        if (it < 7) { issue((it + 1) & 1, (it + 1) * 64); CP_COMMIT(); }

        uint32_t AsB = smb + (it & 1) * STAGE_B;
        uint32_t BsB = AsB + GSTG * 2;
#pragma unroll
        for (int ks = 0; ks < 4; ks++) {
            int kb = ks * 32 + khal;
            uint32_t af[4][4];
#pragma unroll
            for (int mt = 0; mt < 4; mt++)
                ldsm_x4(af[mt], AsB + (mb + mt * 16 + l15) * 144 + kb);
            uint32_t bf[8][2];
#pragma unroll
            for (int ng = 0; ng < 4; ng++) {
                uint32_t rr[4];
                ldsm_x4(rr, BsB + (nb + ng * 16 + l15) * 144 + kb);
                bf[2*ng][0]   = rr[0]; bf[2*ng][1]   = rr[2];
                bf[2*ng+1][0] = rr[1]; bf[2*ng+1][1] = rr[3];
            }
#pragma unroll
            for (int mt = 0; mt < 4; mt++)
#pragma unroll
                for (int nt = 0; nt < 8; nt++)
                    mma_bf16(acc[mt][nt], af[mt], bf[nt][0], bf[nt][1]);
        }
    }

#pragma unroll
    for (int mt = 0; mt < 4; mt++) {
        int r0 = o0 + mb + mt * 16 + g;
        int r1 = r0 + 8;
        float bv0 = bias[r0], bv1 = bias[r1];
#pragma unroll
        for (int nt = 0; nt < 8; nt++) {
            int col = l0 + nb + nt * 8 + 2 * t4;
            size_t a0 = (size_t)r0 * L_ + col;
            size_t a1 = (size_t)r1 * L_ + col;
            float v00 = acc[mt][nt][0] + bv0, v01 = acc[mt][nt][1] + bv0;
            float v10 = acc[mt][nt][2] + bv1, v11 = acc[mt][nt][3] + bv1;
            if (MODE == 0) {
                *(uint32_t*)&Ch[a0] = f2bf2(v00, v01);
                *(uint32_t*)&Ch[a1] = f2bf2(v10, v11);
            } else {
                float2 q0 = *(const float2*)&res[a0];
                float2 q1 = *(const float2*)&res[a1];
                float2 w0, w1;
                w0.x = v00 + q0.x; w0.y = v01 + q0.y;
                w1.x = v10 + q1.x; w1.y = v11 + q1.y;
                *(float2*)&Cf[a0] = w0;
                *(float2*)&Cf[a1] = w1;
            }
        }
    }
}

__global__ __launch_bounds__(128)
void qkv_gemm_kernel(const float* __restrict__ qkv_b)
{
    int b = blockIdx.z;
    gemm_mma<0>(g_wq, qkv_b,
                g_h + (size_t)b * L_ * C_,
                nullptr, nullptr,
                g_qkvh + (size_t)b * M_QKV * L_);
}

__global__ __launch_bounds__(128)
void proj_gemm_kernel(const float* __restrict__ proj_b,
                      const float* __restrict__ x,
                      float* __restrict__ out)
{
    int b = blockIdx.z;
    gemm_mma<1>(g_wp, proj_b,
                g_at + (size_t)b * L_ * C_,
                x   + (size_t)b * C_ * L_,
                out + (size_t)b * C_ * L_,
                nullptr);
}

// ---------------------------------------------------------------------------
// bf16 tensor-core flash attention (no-max softmax).
// All tile loads are direct cp.async in native [d][l] layout;
// transposes happen in ldmatrix.trans. One barrier per k-tile.
// Smem: Qd[64][136] (d,q), Kd 2x[64][72] (d,k), Vd 2x[64][72] (d,k), P[128][72].
// ---------------------------------------------------------------------------
#define QPITCH 136                     // halves (128 q + 8 pad)
#define KVPITCH 72                     // halves (64 k + 8 pad)
#define AQo 0
#define AKo (64 * QPITCH)
#define AVo (AKo + 2 * 64 * KVPITCH)
#define APo (AVo + 2 * 64 * KVPITCH)
#define ATT_BF16 (APo + 128 * KVPITCH)
#define ATT_BYTES (ATT_BF16 * 2)

__global__ __launch_bounds__(256, 2)
void attn_kernel()
{
    int bh = blockIdx.y;
    int b = bh >> 3, h = bh & 7;
    int l0 = blockIdx.x * 128;

    const uint16_t* Qp = g_qkvh + ((size_t)b * M_QKV + 0 * C_ + h * HD_) * L_;
    const uint16_t* Kp = g_qkvh + ((size_t)b * M_QKV + 1 * C_ + h * HD_) * L_;
    const uint16_t* Vp = g_qkvh + ((size_t)b * M_QKV + 2 * C_ + h * HD_) * L_;

    extern __shared__ uint16_t smh[];
    uint32_t smb = smem_u32(smh);
    uint16_t* Ps = smh + APo;
    uint32_t QsB = smb + AQo * 2, KsB = smb + AKo * 2;
    uint32_t VsB = smb + AVo * 2, PsB = smb + APo * 2;

    int tid  = threadIdx.x;
    int lane = tid & 31, wp = tid >> 5;
    int g = lane >> 2, t4 = lane & 3;
    int qb = wp * 16;
    int l15 = lane & 15;
    int khal = (lane >> 4) * 16;

    const float SC = 0.125f * 1.44269504088896340736f;

    int a_row = (lane & 7) + ((lane >> 4) << 3);
    int a_col = ((lane >> 3) & 1) * 16;
    int b_row = (lane & 7) + (((lane >> 3) & 1) << 3);
    int b_col = (lane >> 4) * 16;

    auto load_Q = [&]() {
#pragma unroll
        for (int t = 0; t < 4; t++) {
            int idx = tid + t * 256;
            int d = idx >> 4, c = idx & 15;
            CP16(QsB + d * (QPITCH*2) + c * 16, &Qp[(size_t)d * L_ + l0 + c * 8]);
        }
    };
    auto load_K = [&](int k0, int buf) {
        uint32_t base = KsB + buf * 64 * KVPITCH * 2;
#pragma unroll
        for (int t = 0; t < 2; t++) {
            int idx = tid + t * 256;
            int d = idx >> 3, c = idx & 7;
            CP16(base + d * (KVPITCH*2) + c * 16, &Kp[(size_t)d * L_ + k0 + c * 8]);
        }
    };
    auto load_V = [&](int k0, int buf) {
        uint32_t base = VsB + buf * 64 * KVPITCH * 2;
#pragma unroll
        for (int t = 0; t < 2; t++) {
            int idx = tid + t * 256;
            int d = idx >> 3, c = idx & 7;
            CP16(base + d * (KVPITCH*2) + c * 16, &Vp[(size_t)d * L_ + k0 + c * 8]);
        }
    };

    load_Q();
    load_K(0, 0);
    load_V(0, 0);
    CP_COMMIT();
    CP_WAIT0();
    __syncthreads();

    float oacc[8][4];
#pragma unroll
    for (int nt = 0; nt < 8; nt++)
#pragma unroll
        for (int r = 0; r < 4; r++) oacc[nt][r] = 0.f;
    float rsum0 = 0.f, rsum1 = 0.f;

    for (int kt = 0; kt < 16; kt++) {
        int cur = kt & 1;
        if (kt < 15) {
            load_K((kt + 1) * 64, cur ^ 1);
            load_V((kt + 1) * 64, cur ^ 1);
            CP_COMMIT();
        }
        uint32_t KbB = KsB + cur * 64 * KVPITCH * 2;
        uint32_t VbB = VsB + cur * 64 * KVPITCH * 2;

        float sacc[8][4];
#pragma unroll
        for (int nt = 0; nt < 8; nt++)
#pragma unroll
            for (int r = 0; r < 4; r++) sacc[nt][r] = 0.f;
#pragma unroll
        for (int kc = 0; kc < 4; kc++) {
            uint32_t af[4];
            ldsm_x4_t(af, QsB + (kc * 16 + a_row) * (QPITCH*2) + qb * 2 + a_col);
#pragma unroll
            for (int ng = 0; ng < 4; ng++) {
                uint32_t rr[4];
                ldsm_x4_t(rr, KbB + (kc * 16 + b_row) * (KVPITCH*2) + ng * 32 + b_col);
                mma_bf16(sacc[2*ng],   af, rr[0], rr[1]);
                mma_bf16(sacc[2*ng+1], af, rr[2], rr[3]);
            }
        }

#pragma unroll
        for (int nt = 0; nt < 8; nt++) {
            float p0 = ex2f(sacc[nt][0] * SC);
            float p1 = ex2f(sacc[nt][1] * SC);
            float p2 = ex2f(sacc[nt][2] * SC);
            float p3 = ex2f(sacc[nt][3] * SC);
            rsum0 += p0 + p1;
            rsum1 += p2 + p3;
            *(uint32_t*)&Ps[(qb + g)     * KVPITCH + nt*8 + 2*t4] = f2bf2(p0, p1);
            *(uint32_t*)&Ps[(qb + g + 8) * KVPITCH + nt*8 + 2*t4] = f2bf2(p2, p3);
        }
        __syncwarp();

#pragma unroll
        for (int kc = 0; kc < 4; kc++) {
            int kb = kc * 32 + khal;
            uint32_t af[4];
            ldsm_x4(af, PsB + (qb + l15) * (KVPITCH*2) + kb);
#pragma unroll
            for (int ng = 0; ng < 4; ng++) {
                uint32_t rr[4];
                ldsm_x4(rr, VbB + (ng * 16 + l15) * (KVPITCH*2) + kb);
                mma_bf16(oacc[2*ng],   af, rr[0], rr[2]);
                mma_bf16(oacc[2*ng+1], af, rr[1], rr[3]);
            }
        }
        CP_WAIT0();
        __syncthreads();
    }

    rsum0 += __shfl_xor_sync(0xFFFFFFFFu, rsum0, 1);
    rsum0 += __shfl_xor_sync(0xFFFFFFFFu, rsum0, 2);
    rsum1 += __shfl_xor_sync(0xFFFFFFFFu, rsum1, 1);
    rsum1 += __shfl_xor_sync(0xFFFFFFFFu, rsum1, 2);
    float inv0 = 1.f / rsum0;
    float inv1 = 1.f / rsum1;

    size_t row0 = ((size_t)b * L_ + l0 + qb + g)     * C_ + h * HD_;
    size_t row1 = ((size_t)b * L_ + l0 + qb + g + 8) * C_ + h * HD_;
#pragma unroll
    for (int nt = 0; nt < 8; nt++) {
        int c = nt * 8 + 2 * t4;
        *(uint32_t*)&g_at[row0 + c] = f2bf2(oacc[nt][0] * inv0, oacc[nt][1] * inv0);
        *(uint32_t*)&g_at[row1 + c] = f2bf2(oacc[nt][2] * inv1, oacc[nt][3] * inv1);
    }
}

// ---------------------------------------------------------------------------
extern "C" void kernel_launch(void* const* d_in, const int* in_sizes, int n_in,
                              void* d_out, int out_size)
{
    const float* x      = (const float*)d_in[0];
    const float* norm_w = (const float*)d_in[1];
    const float* norm_b = (const float*)d_in[2];
    const float* qkv_w  = (const float*)d_in[3];
    const float* qkv_b  = (const float*)d_in[4];
    const float* proj_w = (const float*)d_in[5];
    const float* proj_b = (const float*)d_in[6];
    float* out = (float*)d_out;

    cudaFuncSetAttribute(attn_kernel,
                         cudaFuncAttributeMaxDynamicSharedMemorySize, ATT_BYTES);
    cudaFuncSetAttribute(qkv_gemm_kernel,
                         cudaFuncAttributeMaxDynamicSharedMemorySize, GSMEM_BYTES);
    cudaFuncSetAttribute(proj_gemm_kernel,
                         cudaFuncAttributeMaxDynamicSharedMemorySize, GSMEM_BYTES);
    cudaFuncSetAttribute(gn_kernel,
                         cudaFuncAttributeMaxDynamicSharedMemorySize, GN_SMEM);

    gn_kernel<<<1536, 256, GN_SMEM>>>(x, norm_w, norm_b, qkv_w, proj_w);

    {
        dim3 grid(L_ / 128, M_QKV / 128, B_);
        qkv_gemm_kernel<<<grid, 128, GSMEM_BYTES>>>(qkv_b);
    }
    {
        dim3 grid(L_ / 128, B_ * NH_);
        attn_kernel<<<grid, 256, ATT_BYTES>>>();
    }
    {
        dim3 grid(L_ / 128, C_ / 128, B_);
        proj_gemm_kernel<<<grid, 128, GSMEM_BYTES>>>(proj_b, x, out);
    }
}

// round 12
// speedup vs baseline: 8.1301x; 1.0104x over previous
#include <cuda_runtime.h>
#include <math.h>
#include <stdint.h>

#define B_   16
#define C_   512
#define L_   1024
#define NH_  8
#define HD_  64
#define NG_  32
#define GCH_ 16
#define M_QKV 1536
#define EPS_ 1e-5f
#define SCQ  0.1803368801111204f   // 0.125 * log2(e)

// Scratch (device globals)
__device__ uint16_t g_h   [(size_t)B_ * L_ * C_];     // groupnorm out bf16 [B][L][C]
__device__ uint16_t g_qkvh[(size_t)B_ * M_QKV * L_];  // qkv [B][3C][L]: Q,K bf16 / V f16
__device__ uint16_t g_at  [(size_t)B_ * L_ * C_];     // attention out bf16 [B][L][C]
__device__ uint16_t g_wq  [(size_t)M_QKV * C_];       // qkv_w bf16
__device__ uint16_t g_wp  [(size_t)C_ * C_];          // proj_w bf16

__device__ __forceinline__ uint32_t smem_u32(const void* p){
    uint32_t a;
    asm("{ .reg .u64 t; cvta.to.shared.u64 t, %1; cvt.u32.u64 %0, t; }" : "=r"(a) : "l"(p));
    return a;
}
__device__ __forceinline__ uint32_t f2bf2(float lo, float hi){
    uint32_t r; asm("cvt.rn.bf16x2.f32 %0, %1, %2;" : "=r"(r) : "f"(hi), "f"(lo)); return r;
}
__device__ __forceinline__ uint32_t f2h2(float lo, float hi){
    uint32_t r; asm("cvt.rn.f16x2.f32 %0, %1, %2;" : "=r"(r) : "f"(hi), "f"(lo)); return r;
}
__device__ __forceinline__ uint32_t ex2h2(uint32_t x){
    uint32_t r; asm("ex2.approx.f16x2 %0, %1;" : "=r"(r) : "r"(x)); return r;
}
__device__ __forceinline__ void ldsm_x4(uint32_t* r, uint32_t addr){
    asm volatile("ldmatrix.sync.aligned.m8n8.x4.shared.b16 {%0,%1,%2,%3}, [%4];"
        : "=r"(r[0]), "=r"(r[1]), "=r"(r[2]), "=r"(r[3]) : "r"(addr));
}
__device__ __forceinline__ void ldsm_x4_t(uint32_t* r, uint32_t addr){
    asm volatile("ldmatrix.sync.aligned.m8n8.x4.trans.shared.b16 {%0,%1,%2,%3}, [%4];"
        : "=r"(r[0]), "=r"(r[1]), "=r"(r[2]), "=r"(r[3]) : "r"(addr));
}
__device__ __forceinline__ void mma_bf16(float* d, const uint32_t* a,
                                         uint32_t b0, uint32_t b1){
    asm volatile(
        "mma.sync.aligned.m16n8k16.row.col.f32.bf16.bf16.f32 "
        "{%0,%1,%2,%3}, {%4,%5,%6,%7}, {%8,%9}, {%0,%1,%2,%3};"
        : "+f"(d[0]), "+f"(d[1]), "+f"(d[2]), "+f"(d[3])
        : "r"(a[0]), "r"(a[1]), "r"(a[2]), "r"(a[3]), "r"(b0), "r"(b1));
}
__device__ __forceinline__ void mma_f16(float* d, const uint32_t* a,
                                        uint32_t b0, uint32_t b1){
    asm volatile(
        "mma.sync.aligned.m16n8k16.row.col.f32.f16.f16.f32 "
        "{%0,%1,%2,%3}, {%4,%5,%6,%7}, {%8,%9}, {%0,%1,%2,%3};"
        : "+f"(d[0]), "+f"(d[1]), "+f"(d[2]), "+f"(d[3])
        : "r"(a[0]), "r"(a[1]), "r"(a[2]), "r"(a[3]), "r"(b0), "r"(b1));
}
#define CP16(dst, src) \
    asm volatile("cp.async.cg.shared.global [%0], [%1], 16;" :: "r"(dst), "l"(src))
#define CP_COMMIT() asm volatile("cp.async.commit_group;" ::: "memory")
#define CP_WAIT0()  asm volatile("cp.async.wait_group 0;" ::: "memory")

// ---------------------------------------------------------------------------
// Fused GroupNorm (single global pass, smem-cached) + weight conversion.
// ---------------------------------------------------------------------------
#define N4Q (M_QKV * C_ / 4)
#define N4P (C_ * C_ / 4)
#define GNP 257
#define GN_SMEM (16 * GNP * 16)

__global__ void gn_kernel(const float* __restrict__ x,
                          const float* __restrict__ w,
                          const float* __restrict__ bn,
                          const float* __restrict__ qkv_w,
                          const float* __restrict__ proj_w)
{
    int tid = threadIdx.x;
    if (blockIdx.x >= 512) {
        int i = (blockIdx.x - 512) * 256 + tid;
        const float4* src;
        uint2* dst;
        if (i < N4Q) { src = (const float4*)qkv_w + i;        dst = (uint2*)g_wq + i; }
        else         { src = (const float4*)proj_w + (i-N4Q); dst = (uint2*)g_wp + (i-N4Q); }
        float4 v = *src;
        uint2 o;
        o.x = f2bf2(v.x, v.y);
        o.y = f2bf2(v.z, v.w);
        *dst = o;
        return;
    }

    extern __shared__ float xs[];
    float4* xs4 = (float4*)xs;

    int gb  = blockIdx.x;
    int b   = gb >> 5;
    int grp = gb & 31;
    const float4* xp4 = (const float4*)(x + ((size_t)b * C_ + (size_t)grp * GCH_) * L_);

    float s = 0.f, s2 = 0.f;
#pragma unroll 4
    for (int i = tid; i < 4096; i += 256) {
        float4 v = xp4[i];
        xs4[(i >> 8) * GNP + (i & 255)] = v;
        s  += v.x + v.y + v.z + v.w;
        s2 += v.x*v.x + v.y*v.y + v.z*v.z + v.w*v.w;
    }
    __shared__ float sh[512];
    sh[tid] = s; sh[256 + tid] = s2;
    __syncthreads();
    for (int off = 128; off > 0; off >>= 1) {
        if (tid < off) { sh[tid] += sh[tid + off]; sh[256 + tid] += sh[256 + tid + off]; }
        __syncthreads();
    }
    __shared__ float sA[16], sB[16];
    if (tid == 0) {
        float mean = sh[0] * (1.f / (GCH_ * L_));
        float var  = sh[256] * (1.f / (GCH_ * L_)) - mean * mean;
        sh[0] = mean;
        sh[1] = rsqrtf(var + EPS_);
    }
    __syncthreads();
    if (tid < 16) {
        float mean = sh[0], inv = sh[1];
        float wc = w[grp * GCH_ + tid], bc = bn[grp * GCH_ + tid];
        sA[tid] = inv * wc;
        sB[tid] = bc - mean * inv * wc;
    }
    __syncthreads();

#pragma unroll
    for (int t = 0; t < 16; t++) {
        int idx = tid + t * 256;
        int l = idx >> 2, cq = idx & 3;
        int c0 = cq * 4;
        float v0 = xs[(c0+0) * (GNP*4) + l] * sA[c0+0] + sB[c0+0];
        float v1 = xs[(c0+1) * (GNP*4) + l] * sA[c0+1] + sB[c0+1];
        float v2 = xs[(c0+2) * (GNP*4) + l] * sA[c0+2] + sB[c0+2];
        float v3 = xs[(c0+3) * (GNP*4) + l] * sA[c0+3] + sB[c0+3];
        uint2 o;
        o.x = f2bf2(v0, v1);
        o.y = f2bf2(v2, v3);
        *(uint2*)&g_h[((size_t)b * L_ + l) * C_ + grp * GCH_ + c0] = o;
    }
}

// ---------------------------------------------------------------------------
// bf16 GEMM, BK=64, 2-stage cp.async, 128 threads = 4 warps (2m x 2n), 64x64/warp.
// MODE 0 (qkv): region-dependent store — Q rows scaled by SCQ (bf16),
//               K rows bf16, V rows f16. MODE 1 (proj): fp32 + residual.
// ---------------------------------------------------------------------------
#define GP 72
#define GSTG (128 * GP)
#define STAGE_B (2 * GSTG * 2)
#define GSMEM_BYTES (2 * STAGE_B)

template <int MODE>
__device__ __forceinline__ void gemm_mma(const uint16_t* __restrict__ Aw,
                                         const float* __restrict__ bias,
                                         const uint16_t* __restrict__ Bg,
                                         const float* __restrict__ res,
                                         float* __restrict__ Cf,
                                         uint16_t* __restrict__ Ch)
{
    extern __shared__ uint16_t smh[];
    uint32_t smb = smem_u32(smh);
    int tid  = threadIdx.x;
    int wid  = tid >> 5, lane = tid & 31;
    int g    = lane >> 2, t4 = lane & 3;
    int wm   = wid & 1;
    int wn   = wid >> 1;
    int o0   = blockIdx.y * 128;
    int l0   = blockIdx.x * 128;
    int mb   = wm * 64;
    int nb   = wn * 64;
    int l15  = lane & 15;
    int khal = (lane >> 4) * 16;

    float acc[4][8][4];
#pragma unroll
    for (int mt = 0; mt < 4; mt++)
#pragma unroll
        for (int nt = 0; nt < 8; nt++)
#pragma unroll
            for (int r = 0; r < 4; r++) acc[mt][nt][r] = 0.f;

    auto issue = [&](int st, int c0) {
        uint32_t base = smb + st * STAGE_B;
#pragma unroll
        for (int t = 0; t < 8; t++) {
            int idx = tid + t * 128;
            int row = idx >> 3, c = idx & 7;
            CP16(base + row * 144 + c * 16,
                 &Aw[(size_t)(o0 + row) * C_ + c0 + c * 8]);
            CP16(base + GSTG * 2 + row * 144 + c * 16,
                 &Bg[(size_t)(l0 + row) * C_ + c0 + c * 8]);
        }
    };

    issue(0, 0);  CP_COMMIT();

    for (int it = 0; it < 8; ++it) {
        CP_WAIT0();
        __syncthreads();
        if (it < 7) { issue((it + 1) & 1, (it + 1) * 64); CP_COMMIT(); }

        uint32_t AsB = smb + (it & 1) * STAGE_B;
        uint32_t BsB = AsB + GSTG * 2;
#pragma unroll
        for (int ks = 0; ks < 4; ks++) {
            int kb = ks * 32 + khal;
            uint32_t af[4][4];
#pragma unroll
            for (int mt = 0; mt < 4; mt++)
                ldsm_x4(af[mt], AsB + (mb + mt * 16 + l15) * 144 + kb);
            uint32_t bf[8][2];
#pragma unroll
            for (int ng = 0; ng < 4; ng++) {
                uint32_t rr[4];
                ldsm_x4(rr, BsB + (nb + ng * 16 + l15) * 144 + kb);
                bf[2*ng][0]   = rr[0]; bf[2*ng][1]   = rr[2];
                bf[2*ng+1][0] = rr[1]; bf[2*ng+1][1] = rr[3];
            }
#pragma unroll
            for (int mt = 0; mt < 4; mt++)
#pragma unroll
                for (int nt = 0; nt < 8; nt++)
                    mma_bf16(acc[mt][nt], af[mt], bf[nt][0], bf[nt][1]);
        }
    }

    // region for qkv output: 0=Q (scale), 1=K (bf16), 2=V (f16)
    int region = o0 >> 9;
    float qscale = (MODE == 0 && region == 0) ? SCQ : 1.f;

#pragma unroll
    for (int mt = 0; mt < 4; mt++) {
        int r0 = o0 + mb + mt * 16 + g;
        int r1 = r0 + 8;
        float bv0 = bias[r0], bv1 = bias[r1];
#pragma unroll
        for (int nt = 0; nt < 8; nt++) {
            int col = l0 + nb + nt * 8 + 2 * t4;
            size_t a0 = (size_t)r0 * L_ + col;
            size_t a1 = (size_t)r1 * L_ + col;
            float v00 = acc[mt][nt][0] + bv0, v01 = acc[mt][nt][1] + bv0;
            float v10 = acc[mt][nt][2] + bv1, v11 = acc[mt][nt][3] + bv1;
            if (MODE == 0) {
                if (region == 2) {
                    *(uint32_t*)&Ch[a0] = f2h2(v00, v01);
                    *(uint32_t*)&Ch[a1] = f2h2(v10, v11);
                } else {
                    v00 *= qscale; v01 *= qscale; v10 *= qscale; v11 *= qscale;
                    *(uint32_t*)&Ch[a0] = f2bf2(v00, v01);
                    *(uint32_t*)&Ch[a1] = f2bf2(v10, v11);
                }
            } else {
                float2 q0 = *(const float2*)&res[a0];
                float2 q1 = *(const float2*)&res[a1];
                float2 w0, w1;
                w0.x = v00 + q0.x; w0.y = v01 + q0.y;
                w1.x = v10 + q1.x; w1.y = v11 + q1.y;
                *(float2*)&Cf[a0] = w0;
                *(float2*)&Cf[a1] = w1;
            }
        }
    }
}

__global__ __launch_bounds__(128)
void qkv_gemm_kernel(const float* __restrict__ qkv_b)
{
    int b = blockIdx.z;
    gemm_mma<0>(g_wq, qkv_b,
                g_h + (size_t)b * L_ * C_,
                nullptr, nullptr,
                g_qkvh + (size_t)b * M_QKV * L_);
}

__global__ __launch_bounds__(128)
void proj_gemm_kernel(const float* __restrict__ proj_b,
                      const float* __restrict__ x,
                      float* __restrict__ out)
{
    int b = blockIdx.z;
    gemm_mma<1>(g_wp, proj_b,
                g_at + (size_t)b * L_ * C_,
                x   + (size_t)b * C_ * L_,
                out + (size_t)b * C_ * L_,
                nullptr);
}

// ---------------------------------------------------------------------------
// Tensor-core flash attention, f16 softmax path.
// Q,K bf16 (Q pre-scaled by SCQ); S = QK^T (bf16 MMA, fp32 acc);
// P = ex2.approx.f16x2(S); PV + row-sum-via-ones in f16 MMA.
// One barrier per k-tile; all loads cp.async direct.
// ---------------------------------------------------------------------------
#define QPITCH 136
#define KVPITCH 72
#define AQo 0
#define AKo (64 * QPITCH)
#define AVo (AKo + 2 * 64 * KVPITCH)
#define APo (AVo + 2 * 64 * KVPITCH)
#define ATT_BF16 (APo + 128 * KVPITCH)
#define ATT_BYTES (ATT_BF16 * 2)

__global__ __launch_bounds__(256, 2)
void attn_kernel()
{
    int bh = blockIdx.y;
    int b = bh >> 3, h = bh & 7;
    int l0 = blockIdx.x * 128;

    const uint16_t* Qp = g_qkvh + ((size_t)b * M_QKV + 0 * C_ + h * HD_) * L_;
    const uint16_t* Kp = g_qkvh + ((size_t)b * M_QKV + 1 * C_ + h * HD_) * L_;
    const uint16_t* Vp = g_qkvh + ((size_t)b * M_QKV + 2 * C_ + h * HD_) * L_;

    extern __shared__ uint16_t smh[];
    uint32_t smb = smem_u32(smh);
    uint16_t* Ps = smh + APo;
    uint32_t QsB = smb + AQo * 2, KsB = smb + AKo * 2;
    uint32_t VsB = smb + AVo * 2, PsB = smb + APo * 2;

    int tid  = threadIdx.x;
    int lane = tid & 31, wp = tid >> 5;
    int g = lane >> 2, t4 = lane & 3;
    int qb = wp * 16;
    int l15 = lane & 15;
    int khal = (lane >> 4) * 16;

    const uint32_t ONES_H2 = 0x3C003C00u;   // f16x2 {1.0, 1.0}

    int a_row = (lane & 7) + ((lane >> 4) << 3);
    int a_col = ((lane >> 3) & 1) * 16;
    int b_row = (lane & 7) + (((lane >> 3) & 1) << 3);
    int b_col = (lane >> 4) * 16;

    auto load_Q = [&]() {
#pragma unroll
        for (int t = 0; t < 4; t++) {
            int idx = tid + t * 256;
            int d = idx >> 4, c = idx & 15;
            CP16(QsB + d * (QPITCH*2) + c * 16, &Qp[(size_t)d * L_ + l0 + c * 8]);
        }
    };
    auto load_K = [&](int k0, int buf) {
        uint32_t base = KsB + buf * 64 * KVPITCH * 2;
#pragma unroll
        for (int t = 0; t < 2; t++) {
            int idx = tid + t * 256;
            int d = idx >> 3, c = idx & 7;
            CP16(base + d * (KVPITCH*2) + c * 16, &Kp[(size_t)d * L_ + k0 + c * 8]);
        }
    };
    auto load_V = [&](int k0, int buf) {
        uint32_t base = VsB + buf * 64 * KVPITCH * 2;
#pragma unroll
        for (int t = 0; t < 2; t++) {
            int idx = tid + t * 256;
            int d = idx >> 3, c = idx & 7;
            CP16(base + d * (KVPITCH*2) + c * 16, &Vp[(size_t)d * L_ + k0 + c * 8]);
        }
    };

    load_Q();
    load_K(0, 0);
    load_V(0, 0);
    CP_COMMIT();
    CP_WAIT0();
    __syncthreads();

    float oacc[8][4];
#pragma unroll
    for (int nt = 0; nt < 8; nt++)
#pragma unroll
        for (int r = 0; r < 4; r++) oacc[nt][r] = 0.f;
    float sumacc[4] = {0.f, 0.f, 0.f, 0.f};   // rows sums via ones-MMA

    for (int kt = 0; kt < 16; kt++) {
        int cur = kt & 1;
        if (kt < 15) {
            load_K((kt + 1) * 64, cur ^ 1);
            load_V((kt + 1) * 64, cur ^ 1);
            CP_COMMIT();
        }
        uint32_t KbB = KsB + cur * 64 * KVPITCH * 2;
        uint32_t VbB = VsB + cur * 64 * KVPITCH * 2;

        // S = Q K^T  (bf16; Q pre-scaled by SCQ)
        float sacc[8][4];
#pragma unroll
        for (int nt = 0; nt < 8; nt++)
#pragma unroll
            for (int r = 0; r < 4; r++) sacc[nt][r] = 0.f;
#pragma unroll
        for (int kc = 0; kc < 4; kc++) {
            uint32_t af[4];
            ldsm_x4_t(af, QsB + (kc * 16 + a_row) * (QPITCH*2) + qb * 2 + a_col);
#pragma unroll
            for (int ng = 0; ng < 4; ng++) {
                uint32_t rr[4];
                ldsm_x4_t(rr, KbB + (kc * 16 + b_row) * (KVPITCH*2) + ng * 32 + b_col);
                mma_bf16(sacc[2*ng],   af, rr[0], rr[1]);
                mma_bf16(sacc[2*ng+1], af, rr[2], rr[3]);
            }
        }

        // P = exp2(S) in f16x2 (2 values per MUFU op)
#pragma unroll
        for (int nt = 0; nt < 8; nt++) {
            uint32_t p01 = ex2h2(f2h2(sacc[nt][0], sacc[nt][1]));
            uint32_t p23 = ex2h2(f2h2(sacc[nt][2], sacc[nt][3]));
            *(uint32_t*)&Ps[(qb + g)     * KVPITCH + nt*8 + 2*t4] = p01;
            *(uint32_t*)&Ps[(qb + g + 8) * KVPITCH + nt*8 + 2*t4] = p23;
        }
        __syncwarp();

        // O += P V  and  rsum += P * ones   (all f16 MMA)
#pragma unroll
        for (int kc = 0; kc < 4; kc++) {
            int kb = kc * 32 + khal;
            uint32_t af[4];
            ldsm_x4(af, PsB + (qb + l15) * (KVPITCH*2) + kb);
#pragma unroll
            for (int ng = 0; ng < 4; ng++) {
                uint32_t rr[4];
                ldsm_x4(rr, VbB + (ng * 16 + l15) * (KVPITCH*2) + kb);
                mma_f16(oacc[2*ng],   af, rr[0], rr[2]);
                mma_f16(oacc[2*ng+1], af, rr[1], rr[3]);
            }
            mma_f16(sumacc, af, ONES_H2, ONES_H2);
        }
        CP_WAIT0();
        __syncthreads();
    }

    float inv0 = 1.f / sumacc[0];   // row qb+g
    float inv1 = 1.f / sumacc[2];   // row qb+g+8

    size_t row0 = ((size_t)b * L_ + l0 + qb + g)     * C_ + h * HD_;
    size_t row1 = ((size_t)b * L_ + l0 + qb + g + 8) * C_ + h * HD_;
#pragma unroll
    for (int nt = 0; nt < 8; nt++) {
        int c = nt * 8 + 2 * t4;
        *(uint32_t*)&g_at[row0 + c] = f2bf2(oacc[nt][0] * inv0, oacc[nt][1] * inv0);
        *(uint32_t*)&g_at[row1 + c] = f2bf2(oacc[nt][2] * inv1, oacc[nt][3] * inv1);
    }
}

// ---------------------------------------------------------------------------
extern "C" void kernel_launch(void* const* d_in, const int* in_sizes, int n_in,
                              void* d_out, int out_size)
{
    const float* x      = (const float*)d_in[0];
    const float* norm_w = (const float*)d_in[1];
    const float* norm_b = (const float*)d_in[2];
    const float* qkv_w  = (const float*)d_in[3];
    const float* qkv_b  = (const float*)d_in[4];
    const float* proj_w = (const float*)d_in[5];
    const float* proj_b = (const float*)d_in[6];
    float* out = (float*)d_out;

    cudaFuncSetAttribute(attn_kernel,
                         cudaFuncAttributeMaxDynamicSharedMemorySize, ATT_BYTES);
    cudaFuncSetAttribute(qkv_gemm_kernel,
                         cudaFuncAttributeMaxDynamicSharedMemorySize, GSMEM_BYTES);
    cudaFuncSetAttribute(proj_gemm_kernel,
                         cudaFuncAttributeMaxDynamicSharedMemorySize, GSMEM_BYTES);
    cudaFuncSetAttribute(gn_kernel,
                         cudaFuncAttributeMaxDynamicSharedMemorySize, GN_SMEM);

    gn_kernel<<<1536, 256, GN_SMEM>>>(x, norm_w, norm_b, qkv_w, proj_w);

    {
        dim3 grid(L_ / 128, M_QKV / 128, B_);
        qkv_gemm_kernel<<<grid, 128, GSMEM_BYTES>>>(qkv_b);
    }
    {
        dim3 grid(L_ / 128, B_ * NH_);
        attn_kernel<<<grid, 256, ATT_BYTES>>>();
    }
    {
        dim3 grid(L_ / 128, C_ / 128, B_);
        proj_gemm_kernel<<<grid, 128, GSMEM_BYTES>>>(proj_b, x, out);
    }
}

// round 13
// speedup vs baseline: 8.2365x; 1.0131x over previous
#include <cuda_runtime.h>
#include <math.h>
#include <stdint.h>

#define B_   16
#define C_   512
#define L_   1024
#define NH_  8
#define HD_  64
#define NG_  32
#define GCH_ 16
#define M_QKV 1536
#define EPS_ 1e-5f
#define SCQ  0.1803368801111204f   // 0.125 * log2(e)

// Scratch (device globals)
__device__ uint16_t g_h   [(size_t)B_ * L_ * C_];     // groupnorm out bf16 [B][L][C]
__device__ uint16_t g_qkvh[(size_t)B_ * M_QKV * L_];  // qkv [B][3C][L]: Q,K bf16 / V f16
__device__ uint16_t g_at  [(size_t)B_ * L_ * C_];     // attention out bf16 [B][L][C]
__device__ uint16_t g_wq  [(size_t)M_QKV * C_];       // qkv_w bf16
__device__ uint16_t g_wp  [(size_t)C_ * C_];          // proj_w bf16

__device__ __forceinline__ uint32_t smem_u32(const void* p){
    uint32_t a;
    asm("{ .reg .u64 t; cvta.to.shared.u64 t, %1; cvt.u32.u64 %0, t; }" : "=r"(a) : "l"(p));
    return a;
}
__device__ __forceinline__ uint32_t f2bf2(float lo, float hi){
    uint32_t r; asm("cvt.rn.bf16x2.f32 %0, %1, %2;" : "=r"(r) : "f"(hi), "f"(lo)); return r;
}
__device__ __forceinline__ uint32_t f2h2(float lo, float hi){
    uint32_t r; asm("cvt.rn.f16x2.f32 %0, %1, %2;" : "=r"(r) : "f"(hi), "f"(lo)); return r;
}
__device__ __forceinline__ uint32_t ex2h2(uint32_t x){
    uint32_t r; asm("ex2.approx.f16x2 %0, %1;" : "=r"(r) : "r"(x)); return r;
}
__device__ __forceinline__ void ldsm_x4(uint32_t* r, uint32_t addr){
    asm volatile("ldmatrix.sync.aligned.m8n8.x4.shared.b16 {%0,%1,%2,%3}, [%4];"
        : "=r"(r[0]), "=r"(r[1]), "=r"(r[2]), "=r"(r[3]) : "r"(addr));
}
__device__ __forceinline__ void ldsm_x4_t(uint32_t* r, uint32_t addr){
    asm volatile("ldmatrix.sync.aligned.m8n8.x4.trans.shared.b16 {%0,%1,%2,%3}, [%4];"
        : "=r"(r[0]), "=r"(r[1]), "=r"(r[2]), "=r"(r[3]) : "r"(addr));
}
__device__ __forceinline__ void mma_bf16(float* d, const uint32_t* a,
                                         uint32_t b0, uint32_t b1){
    asm volatile(
        "mma.sync.aligned.m16n8k16.row.col.f32.bf16.bf16.f32 "
        "{%0,%1,%2,%3}, {%4,%5,%6,%7}, {%8,%9}, {%0,%1,%2,%3};"
        : "+f"(d[0]), "+f"(d[1]), "+f"(d[2]), "+f"(d[3])
        : "r"(a[0]), "r"(a[1]), "r"(a[2]), "r"(a[3]), "r"(b0), "r"(b1));
}
__device__ __forceinline__ void mma_f16(float* d, const uint32_t* a,
                                        uint32_t b0, uint32_t b1){
    asm volatile(
        "mma.sync.aligned.m16n8k16.row.col.f32.f16.f16.f32 "
        "{%0,%1,%2,%3}, {%4,%5,%6,%7}, {%8,%9}, {%0,%1,%2,%3};"
        : "+f"(d[0]), "+f"(d[1]), "+f"(d[2]), "+f"(d[3])
        : "r"(a[0]), "r"(a[1]), "r"(a[2]), "r"(a[3]), "r"(b0), "r"(b1));
}
#define CP16(dst, src) \
    asm volatile("cp.async.cg.shared.global [%0], [%1], 16;" :: "r"(dst), "l"(src))
#define CP_COMMIT() asm volatile("cp.async.commit_group;" ::: "memory")
#define CP_WAIT0()  asm volatile("cp.async.wait_group 0;" ::: "memory")

// ---------------------------------------------------------------------------
// Fused GroupNorm (single global pass, smem-cached) + weight conversion.
// ---------------------------------------------------------------------------
#define N4Q (M_QKV * C_ / 4)
#define N4P (C_ * C_ / 4)
#define GNP 257
#define GN_SMEM (16 * GNP * 16)

__global__ void gn_kernel(const float* __restrict__ x,
                          const float* __restrict__ w,
                          const float* __restrict__ bn,
                          const float* __restrict__ qkv_w,
                          const float* __restrict__ proj_w)
{
    int tid = threadIdx.x;
    if (blockIdx.x >= 512) {
        int i = (blockIdx.x - 512) * 256 + tid;
        const float4* src;
        uint2* dst;
        if (i < N4Q) { src = (const float4*)qkv_w + i;        dst = (uint2*)g_wq + i; }
        else         { src = (const float4*)proj_w + (i-N4Q); dst = (uint2*)g_wp + (i-N4Q); }
        float4 v = *src;
        uint2 o;
        o.x = f2bf2(v.x, v.y);
        o.y = f2bf2(v.z, v.w);
        *dst = o;
        return;
    }

    extern __shared__ float xs[];
    float4* xs4 = (float4*)xs;

    int gb  = blockIdx.x;
    int b   = gb >> 5;
    int grp = gb & 31;
    const float4* xp4 = (const float4*)(x + ((size_t)b * C_ + (size_t)grp * GCH_) * L_);

    float s = 0.f, s2 = 0.f;
#pragma unroll 4
    for (int i = tid; i < 4096; i += 256) {
        float4 v = xp4[i];
        xs4[(i >> 8) * GNP + (i & 255)] = v;
        s  += v.x + v.y + v.z + v.w;
        s2 += v.x*v.x + v.y*v.y + v.z*v.z + v.w*v.w;
    }
    __shared__ float sh[512];
    sh[tid] = s; sh[256 + tid] = s2;
    __syncthreads();
    for (int off = 128; off > 0; off >>= 1) {
        if (tid < off) { sh[tid] += sh[tid + off]; sh[256 + tid] += sh[256 + tid + off]; }
        __syncthreads();
    }
    __shared__ float sA[16], sB[16];
    if (tid == 0) {
        float mean = sh[0] * (1.f / (GCH_ * L_));
        float var  = sh[256] * (1.f / (GCH_ * L_)) - mean * mean;
        sh[0] = mean;
        sh[1] = rsqrtf(var + EPS_);
    }
    __syncthreads();
    if (tid < 16) {
        float mean = sh[0], inv = sh[1];
        float wc = w[grp * GCH_ + tid], bc = bn[grp * GCH_ + tid];
        sA[tid] = inv * wc;
        sB[tid] = bc - mean * inv * wc;
    }
    __syncthreads();

#pragma unroll
    for (int t = 0; t < 16; t++) {
        int idx = tid + t * 256;
        int l = idx >> 2, cq = idx & 3;
        int c0 = cq * 4;
        float v0 = xs[(c0+0) * (GNP*4) + l] * sA[c0+0] + sB[c0+0];
        float v1 = xs[(c0+1) * (GNP*4) + l] * sA[c0+1] + sB[c0+1];
        float v2 = xs[(c0+2) * (GNP*4) + l] * sA[c0+2] + sB[c0+2];
        float v3 = xs[(c0+3) * (GNP*4) + l] * sA[c0+3] + sB[c0+3];
        uint2 o;
        o.x = f2bf2(v0, v1);
        o.y = f2bf2(v2, v3);
        *(uint2*)&g_h[((size_t)b * L_ + l) * C_ + grp * GCH_ + c0] = o;
    }
}

// ---------------------------------------------------------------------------
// bf16 GEMM, BK=64, 2-stage cp.async, 256 threads = 8 warps (2m x 4n).
// MODE 0 (qkv): region stores — Q scaled bf16 / K bf16 / V f16.
// MODE 1 (proj): fp32 + residual.
// ---------------------------------------------------------------------------
#define GP 72
#define GSTG (128 * GP)
#define STAGE_B (2 * GSTG * 2)
#define GSMEM_BYTES (2 * STAGE_B)

template <int MODE>
__device__ __forceinline__ void gemm_mma(const uint16_t* __restrict__ Aw,
                                         const float* __restrict__ bias,
                                         const uint16_t* __restrict__ Bg,
                                         const float* __restrict__ res,
                                         float* __restrict__ Cf,
                                         uint16_t* __restrict__ Ch)
{
    extern __shared__ uint16_t smh[];
    uint32_t smb = smem_u32(smh);
    int tid  = threadIdx.x;
    int wid  = tid >> 5, lane = tid & 31;
    int g    = lane >> 2, t4 = lane & 3;
    int wm   = wid & 1;
    int wn   = wid >> 1;
    int o0   = blockIdx.y * 128;
    int l0   = blockIdx.x * 128;
    int mb   = wm * 64;
    int nb   = wn * 32;
    int l15  = lane & 15;
    int khal = (lane >> 4) * 16;

    float acc[4][4][4];
#pragma unroll
    for (int mt = 0; mt < 4; mt++)
#pragma unroll
        for (int nt = 0; nt < 4; nt++)
#pragma unroll
            for (int r = 0; r < 4; r++) acc[mt][nt][r] = 0.f;

    auto issue = [&](int st, int c0) {
        uint32_t base = smb + st * STAGE_B;
#pragma unroll
        for (int t = 0; t < 4; t++) {
            int idx = tid + t * 256;
            int row = idx >> 3, c = idx & 7;
            CP16(base + row * 144 + c * 16,
                 &Aw[(size_t)(o0 + row) * C_ + c0 + c * 8]);
            CP16(base + GSTG * 2 + row * 144 + c * 16,
                 &Bg[(size_t)(l0 + row) * C_ + c0 + c * 8]);
        }
    };

    issue(0, 0);  CP_COMMIT();

    for (int it = 0; it < 8; ++it) {
        CP_WAIT0();
        __syncthreads();
        if (it < 7) { issue((it + 1) & 1, (it + 1) * 64); CP_COMMIT(); }

        uint32_t AsB = smb + (it & 1) * STAGE_B;
        uint32_t BsB = AsB + GSTG * 2;
#pragma unroll
        for (int ks = 0; ks < 4; ks++) {
            int kb = ks * 32 + khal;
            uint32_t af[4][4];
#pragma unroll
            for (int mt = 0; mt < 4; mt++)
                ldsm_x4(af[mt], AsB + (mb + mt * 16 + l15) * 144 + kb);
            uint32_t bf[4][2];
#pragma unroll
            for (int ng = 0; ng < 2; ng++) {
                uint32_t rr[4];
                ldsm_x4(rr, BsB + (nb + ng * 16 + l15) * 144 + kb);
                bf[2*ng][0]   = rr[0]; bf[2*ng][1]   = rr[2];
                bf[2*ng+1][0] = rr[1]; bf[2*ng+1][1] = rr[3];
            }
#pragma unroll
            for (int mt = 0; mt < 4; mt++)
#pragma unroll
                for (int nt = 0; nt < 4; nt++)
                    mma_bf16(acc[mt][nt], af[mt], bf[nt][0], bf[nt][1]);
        }
    }

    int region = o0 >> 9;     // qkv: 0=Q, 1=K, 2=V
    float qscale = (MODE == 0 && region == 0) ? SCQ : 1.f;

#pragma unroll
    for (int mt = 0; mt < 4; mt++) {
        int r0 = o0 + mb + mt * 16 + g;
        int r1 = r0 + 8;
        float bv0 = bias[r0], bv1 = bias[r1];
#pragma unroll
        for (int nt = 0; nt < 4; nt++) {
            int col = l0 + nb + nt * 8 + 2 * t4;
            size_t a0 = (size_t)r0 * L_ + col;
            size_t a1 = (size_t)r1 * L_ + col;
            float v00 = acc[mt][nt][0] + bv0, v01 = acc[mt][nt][1] + bv0;
            float v10 = acc[mt][nt][2] + bv1, v11 = acc[mt][nt][3] + bv1;
            if (MODE == 0) {
                if (region == 2) {
                    *(uint32_t*)&Ch[a0] = f2h2(v00, v01);
                    *(uint32_t*)&Ch[a1] = f2h2(v10, v11);
                } else {
                    v00 *= qscale; v01 *= qscale; v10 *= qscale; v11 *= qscale;
                    *(uint32_t*)&Ch[a0] = f2bf2(v00, v01);
                    *(uint32_t*)&Ch[a1] = f2bf2(v10, v11);
                }
            } else {
                float2 q0 = *(const float2*)&res[a0];
                float2 q1 = *(const float2*)&res[a1];
                float2 w0, w1;
                w0.x = v00 + q0.x; w0.y = v01 + q0.y;
                w1.x = v10 + q1.x; w1.y = v11 + q1.y;
                *(float2*)&Cf[a0] = w0;
                *(float2*)&Cf[a1] = w1;
            }
        }
    }
}

__global__ __launch_bounds__(256)
void qkv_gemm_kernel(const float* __restrict__ qkv_b)
{
    int b = blockIdx.z;
    gemm_mma<0>(g_wq, qkv_b,
                g_h + (size_t)b * L_ * C_,
                nullptr, nullptr,
                g_qkvh + (size_t)b * M_QKV * L_);
}

__global__ __launch_bounds__(256)
void proj_gemm_kernel(const float* __restrict__ proj_b,
                      const float* __restrict__ x,
                      float* __restrict__ out)
{
    int b = blockIdx.z;
    gemm_mma<1>(g_wp, proj_b,
                g_at + (size_t)b * L_ * C_,
                x   + (size_t)b * C_ * L_,
                out + (size_t)b * C_ * L_,
                nullptr);
}

// ---------------------------------------------------------------------------
// Tensor-core flash attention: 128 threads = 4 warps, warp q-tile 32
// (halved K/V fragment redundancy). f16 softmax path, one barrier/tile.
// ---------------------------------------------------------------------------
#define QPITCH 136
#define KVPITCH 72
#define AQo 0
#define AKo (64 * QPITCH)
#define AVo (AKo + 2 * 64 * KVPITCH)
#define APo (AVo + 2 * 64 * KVPITCH)
#define ATT_BF16 (APo + 128 * KVPITCH)
#define ATT_BYTES (ATT_BF16 * 2)

__global__ __launch_bounds__(128, 2)
void attn_kernel()
{
    int bh = blockIdx.y;
    int b = bh >> 3, h = bh & 7;
    int l0 = blockIdx.x * 128;

    const uint16_t* Qp = g_qkvh + ((size_t)b * M_QKV + 0 * C_ + h * HD_) * L_;
    const uint16_t* Kp = g_qkvh + ((size_t)b * M_QKV + 1 * C_ + h * HD_) * L_;
    const uint16_t* Vp = g_qkvh + ((size_t)b * M_QKV + 2 * C_ + h * HD_) * L_;

    extern __shared__ uint16_t smh[];
    uint32_t smb = smem_u32(smh);
    uint16_t* Ps = smh + APo;
    uint32_t QsB = smb + AQo * 2, KsB = smb + AKo * 2;
    uint32_t VsB = smb + AVo * 2, PsB = smb + APo * 2;

    int tid  = threadIdx.x;
    int lane = tid & 31, wp = tid >> 5;   // 4 warps
    int g = lane >> 2, t4 = lane & 3;
    int qb = wp * 32;                     // warp q-tile 32
    int l15 = lane & 15;
    int khal = (lane >> 4) * 16;

    const uint32_t ONES_H2 = 0x3C003C00u;

    int a_row = (lane & 7) + ((lane >> 4) << 3);
    int a_col = ((lane >> 3) & 1) * 16;
    int b_row = (lane & 7) + (((lane >> 3) & 1) << 3);
    int b_col = (lane >> 4) * 16;

    auto load_Q = [&]() {
#pragma unroll
        for (int t = 0; t < 8; t++) {
            int idx = tid + t * 128;
            int d = idx >> 4, c = idx & 15;
            CP16(QsB + d * (QPITCH*2) + c * 16, &Qp[(size_t)d * L_ + l0 + c * 8]);
        }
    };
    auto load_K = [&](int k0, int buf) {
        uint32_t base = KsB + buf * 64 * KVPITCH * 2;
#pragma unroll
        for (int t = 0; t < 4; t++) {
            int idx = tid + t * 128;
            int d = idx >> 3, c = idx & 7;
            CP16(base + d * (KVPITCH*2) + c * 16, &Kp[(size_t)d * L_ + k0 + c * 8]);
        }
    };
    auto load_V = [&](int k0, int buf) {
        uint32_t base = VsB + buf * 64 * KVPITCH * 2;
#pragma unroll
        for (int t = 0; t < 4; t++) {
            int idx = tid + t * 128;
            int d = idx >> 3, c = idx & 7;
            CP16(base + d * (KVPITCH*2) + c * 16, &Vp[(size_t)d * L_ + k0 + c * 8]);
        }
    };

    load_Q();
    load_K(0, 0);
    load_V(0, 0);
    CP_COMMIT();
    CP_WAIT0();
    __syncthreads();

    float oacc[2][8][4];
#pragma unroll
    for (int qm = 0; qm < 2; qm++)
#pragma unroll
        for (int nt = 0; nt < 8; nt++)
#pragma unroll
            for (int r = 0; r < 4; r++) oacc[qm][nt][r] = 0.f;
    float sumacc[2][4] = {{0.f,0.f,0.f,0.f},{0.f,0.f,0.f,0.f}};

    for (int kt = 0; kt < 16; kt++) {
        int cur = kt & 1;
        if (kt < 15) {
            load_K((kt + 1) * 64, cur ^ 1);
            load_V((kt + 1) * 64, cur ^ 1);
            CP_COMMIT();
        }
        uint32_t KbB = KsB + cur * 64 * KVPITCH * 2;
        uint32_t VbB = VsB + cur * 64 * KVPITCH * 2;

        // S = Q K^T (two m16 blocks per warp)
        float sacc[2][8][4];
#pragma unroll
        for (int qm = 0; qm < 2; qm++)
#pragma unroll
            for (int nt = 0; nt < 8; nt++)
#pragma unroll
                for (int r = 0; r < 4; r++) sacc[qm][nt][r] = 0.f;
#pragma unroll
        for (int kc = 0; kc < 4; kc++) {
            uint32_t af[2][4];
#pragma unroll
            for (int qm = 0; qm < 2; qm++)
                ldsm_x4_t(af[qm], QsB + (kc * 16 + a_row) * (QPITCH*2)
                                 + (qb + qm * 16) * 2 + a_col);
#pragma unroll
            for (int ng = 0; ng < 4; ng++) {
                uint32_t rr[4];
                ldsm_x4_t(rr, KbB + (kc * 16 + b_row) * (KVPITCH*2) + ng * 32 + b_col);
#pragma unroll
                for (int qm = 0; qm < 2; qm++) {
                    mma_bf16(sacc[qm][2*ng],   af[qm], rr[0], rr[1]);
                    mma_bf16(sacc[qm][2*ng+1], af[qm], rr[2], rr[3]);
                }
            }
        }

        // P = exp2(S) in f16x2
#pragma unroll
        for (int qm = 0; qm < 2; qm++)
#pragma unroll
            for (int nt = 0; nt < 8; nt++) {
                uint32_t p01 = ex2h2(f2h2(sacc[qm][nt][0], sacc[qm][nt][1]));
                uint32_t p23 = ex2h2(f2h2(sacc[qm][nt][2], sacc[qm][nt][3]));
                *(uint32_t*)&Ps[(qb + qm*16 + g)     * KVPITCH + nt*8 + 2*t4] = p01;
                *(uint32_t*)&Ps[(qb + qm*16 + g + 8) * KVPITCH + nt*8 + 2*t4] = p23;
            }
        __syncwarp();

        // O += P V  and  rsum += P * ones
#pragma unroll
        for (int kc = 0; kc < 4; kc++) {
            int kb = kc * 32 + khal;
            uint32_t af[2][4];
#pragma unroll
            for (int qm = 0; qm < 2; qm++)
                ldsm_x4(af[qm], PsB + (qb + qm*16 + l15) * (KVPITCH*2) + kb);
#pragma unroll
            for (int ng = 0; ng < 4; ng++) {
                uint32_t rr[4];
                ldsm_x4(rr, VbB + (ng * 16 + l15) * (KVPITCH*2) + kb);
#pragma unroll
                for (int qm = 0; qm < 2; qm++) {
                    mma_f16(oacc[qm][2*ng],   af[qm], rr[0], rr[2]);
                    mma_f16(oacc[qm][2*ng+1], af[qm], rr[1], rr[3]);
                }
            }
#pragma unroll
            for (int qm = 0; qm < 2; qm++)
                mma_f16(sumacc[qm], af[qm], ONES_H2, ONES_H2);
        }
        CP_WAIT0();
        __syncthreads();
    }

#pragma unroll
    for (int qm = 0; qm < 2; qm++) {
        float inv0 = 1.f / sumacc[qm][0];
        float inv1 = 1.f / sumacc[qm][2];
        size_t row0 = ((size_t)b * L_ + l0 + qb + qm*16 + g)     * C_ + h * HD_;
        size_t row1 = ((size_t)b * L_ + l0 + qb + qm*16 + g + 8) * C_ + h * HD_;
#pragma unroll
        for (int nt = 0; nt < 8; nt++) {
            int c = nt * 8 + 2 * t4;
            *(uint32_t*)&g_at[row0 + c] = f2bf2(oacc[qm][nt][0] * inv0,
                                                oacc[qm][nt][1] * inv0);
            *(uint32_t*)&g_at[row1 + c] = f2bf2(oacc[qm][nt][2] * inv1,
                                                oacc[qm][nt][3] * inv1);
        }
    }
}

// ---------------------------------------------------------------------------
extern "C" void kernel_launch(void* const* d_in, const int* in_sizes, int n_in,
                              void* d_out, int out_size)
{
    const float* x      = (const float*)d_in[0];
    const float* norm_w = (const float*)d_in[1];
    const float* norm_b = (const float*)d_in[2];
    const float* qkv_w  = (const float*)d_in[3];
    const float* qkv_b  = (const float*)d_in[4];
    const float* proj_w = (const float*)d_in[5];
    const float* proj_b = (const float*)d_in[6];
    float* out = (float*)d_out;

    cudaFuncSetAttribute(attn_kernel,
                         cudaFuncAttributeMaxDynamicSharedMemorySize, ATT_BYTES);
    cudaFuncSetAttribute(qkv_gemm_kernel,
                         cudaFuncAttributeMaxDynamicSharedMemorySize, GSMEM_BYTES);
    cudaFuncSetAttribute(proj_gemm_kernel,
                         cudaFuncAttributeMaxDynamicSharedMemorySize, GSMEM_BYTES);
    cudaFuncSetAttribute(gn_kernel,
                         cudaFuncAttributeMaxDynamicSharedMemorySize, GN_SMEM);

    gn_kernel<<<1536, 256, GN_SMEM>>>(x, norm_w, norm_b, qkv_w, proj_w);

    {
        dim3 grid(L_ / 128, M_QKV / 128, B_);
        qkv_gemm_kernel<<<grid, 256, GSMEM_BYTES>>>(qkv_b);
    }
    {
        dim3 grid(L_ / 128, B_ * NH_);
        attn_kernel<<<grid, 128, ATT_BYTES>>>();
    }
    {
        dim3 grid(L_ / 128, C_ / 128, B_);
        proj_gemm_kernel<<<grid, 256, GSMEM_BYTES>>>(proj_b, x, out);
    }
}